// round 3
// baseline (speedup 1.0000x reference)
#include <cuda_runtime.h>
#include <math.h>

typedef unsigned long long ull;

#define NN    800000
#define NF    100000
#define NR    2000
#define FEAT  86
#define H     128
#define SA    130   // activation tile row stride (even, padded)

// ---------------- device scratch (no runtime allocation allowed) ----------------
__device__ __align__(16) float g_root_emb[NR * H];
__device__ __align__(16) float g_frag_sum[(size_t)NF * H];
__device__ __align__(16) float g_cnt[NF];
__device__ __align__(16) float g_Wa[H * H];
__device__ __align__(16) float g_Wb[H * H];

// ---------------- f32x2 packed helpers (Blackwell FFMA2 path) ----------------
__device__ __forceinline__ ull pack2(float lo, float hi) {
    ull r; asm("mov.b64 %0, {%1, %2};" : "=l"(r) : "f"(lo), "f"(hi)); return r;
}
__device__ __forceinline__ void unpack2(ull v, float& lo, float& hi) {
    asm("mov.b64 {%0, %1}, %2;" : "=f"(lo), "=f"(hi) : "l"(v));
}
__device__ __forceinline__ void fma2(ull& d, ull a, ull b) {
    asm("fma.rn.f32x2 %0, %1, %2, %3;" : "=l"(d) : "l"(a), "l"(b), "l"(d));
}

// ---------------- shared 128x128 GEMM microkernel pieces ----------------
// Thread map: tx = tid&15 (columns), ty = tid>>4 (rows).
// Thread owns rows m = ty*8+i (i<8), column pairs n = 2*tx + 32*jj (jj<4).
// acc[i][jj] is the f32x2 (col n, col n+1) accumulator for row m.

__device__ __forceinline__ void acc_bias(ull acc[8][4], const float* __restrict__ bias, int tx) {
#pragma unroll
    for (int jj = 0; jj < 4; jj++) {
        float2 b = *(const float2*)(bias + 2 * tx + 32 * jj);
        ull p = pack2(b.x, b.y);
#pragma unroll
        for (int i = 0; i < 8; i++) acc[i][jj] = p;
    }
}

__device__ __forceinline__ void gemm_acc(ull acc[8][4], const float* __restrict__ sAct,
                                         const float* __restrict__ sW, int K, int tx, int ty) {
    const int rbase = ty * 8;
    const int cbase = 2 * tx;
#pragma unroll 2
    for (int k = 0; k < K; k++) {
        ull b2[4];
#pragma unroll
        for (int jj = 0; jj < 4; jj++)
            b2[jj] = *(const ull*)(sW + k * H + cbase + 32 * jj);
        const float* pA = sAct + rbase * SA + k;
#pragma unroll
        for (int i = 0; i < 8; i++) {
            float a = pA[i * SA];
            ull pa = pack2(a, a);
#pragma unroll
            for (int jj = 0; jj < 4; jj++) fma2(acc[i][jj], pa, b2[jj]);
        }
    }
}

__device__ __forceinline__ void write_act(ull acc[8][4], float* __restrict__ sAct,
                                          bool relu, int tx, int ty) {
#pragma unroll
    for (int i = 0; i < 8; i++) {
        int m = ty * 8 + i;
#pragma unroll
        for (int jj = 0; jj < 4; jj++) {
            float lo, hi; unpack2(acc[i][jj], lo, hi);
            if (relu) { lo = fmaxf(lo, 0.f); hi = fmaxf(hi, 0.f); }
            *(float2*)(sAct + m * SA + 2 * tx + 32 * jj) = make_float2(lo, hi);
        }
    }
}

// ---------------- kernel A: root encoder (tiny) ----------------
__global__ void root_enc_kernel(const float* __restrict__ root_repr,
                                const float* __restrict__ W_root,
                                const float* __restrict__ b_root) {
    __shared__ float sX[FEAT];
    int r = blockIdx.x, n = threadIdx.x;   // 128 threads
    for (int k = n; k < FEAT; k += 128) sX[k] = root_repr[r * FEAT + k];
    __syncthreads();
    float s = b_root[n];
#pragma unroll 2
    for (int k = 0; k < FEAT; k++) s += sX[k] * W_root[k * H + n];
    g_root_emb[r * H + n] = fmaxf(s, 0.f);
}

// ---------------- kernel: fold concat structure into combined weights ----------------
// cat = [ext, ext-mean, mean, onehot] @ W_m1  ==  ext@(W1a+W1b) + mean@(W1c-W1b) + W_m1[384+bk]
__global__ void combine_w_kernel(const float* __restrict__ W_m1) {
    int i = blockIdx.x * 256 + threadIdx.x;
    if (i < H * H) {
        float wb = W_m1[H * H + i];
        g_Wa[i] = W_m1[i] + wb;
        g_Wb[i] = W_m1[2 * H * H + i] - wb;
    }
}

// ---------------- kernel B: fused node chain + segmented pooling ----------------
__global__ __launch_bounds__(256, 1) void node_chain_kernel(
    const float* __restrict__ node_h, const int* __restrict__ seg,
    const float* __restrict__ W_in, const float* __restrict__ b_in,
    const float* __restrict__ W_g1, const float* __restrict__ b_g1,
    const float* __restrict__ W_g2, const float* __restrict__ b_g2) {
    extern __shared__ float sm[];
    float* sAct = sm;            // 128 x SA
    float* sW   = sm + H * SA;   // 128 x 128
    __shared__ int sSeg[128];

    int tid = threadIdx.x;
    int base = blockIdx.x * 128;   // NN = 6250 * 128 exactly

    // load X tile (coalesced global reads)
    for (int idx = tid; idx < 128 * FEAT; idx += 256) {
        int m = idx / FEAT, k = idx - m * FEAT;
        sAct[m * SA + k] = node_h[(base + m) * FEAT + k];
    }
    if (tid < 128) sSeg[tid] = seg[base + tid];
    {   // load W_in
        const float4* s = (const float4*)W_in; float4* d = (float4*)sW;
        for (int idx = tid; idx < FEAT * (H / 4); idx += 256) d[idx] = s[idx];
    }
    __syncthreads();

    int tx = tid & 15, ty = tid >> 4;
    ull acc[8][4];

    // layer 1: x @ W_in + b_in   (no relu)
    acc_bias(acc, b_in, tx);
    gemm_acc(acc, sAct, sW, FEAT, tx, ty);
    __syncthreads();
    write_act(acc, sAct, false, tx, ty);
    {   const float4* s = (const float4*)W_g1; float4* d = (float4*)sW;
        for (int idx = tid; idx < H * (H / 4); idx += 256) d[idx] = s[idx]; }
    __syncthreads();

    // layer 2: relu(h @ W_g1 + b_g1)
    acc_bias(acc, b_g1, tx);
    gemm_acc(acc, sAct, sW, H, tx, ty);
    __syncthreads();
    write_act(acc, sAct, true, tx, ty);
    {   const float4* s = (const float4*)W_g2; float4* d = (float4*)sW;
        for (int idx = tid; idx < H * (H / 4); idx += 256) d[idx] = s[idx]; }
    __syncthreads();

    // layer 3: relu(h @ W_g2 + b_g2)
    acc_bias(acc, b_g2, tx);
    gemm_acc(acc, sAct, sW, H, tx, ty);
    __syncthreads();
    write_act(acc, sAct, true, tx, ty);
    __syncthreads();

    // segmented pooling: segment_ids are sorted -> run-length reduce in-CTA,
    // one atomic per (segment, col) run boundary (~16 frags per 128-node tile).
    if (tid < 128) {
        int n = tid;
        float r = 0.f; int cur = sSeg[0];
        for (int m = 0; m < 128; m++) {
            int s = sSeg[m];
            if (s != cur) { atomicAdd(&g_frag_sum[(size_t)cur * H + n], r); r = 0.f; cur = s; }
            r += sAct[m * SA + n];
        }
        atomicAdd(&g_frag_sum[(size_t)cur * H + n], r);
    } else if (tid == 128) {
        float c = 0.f; int cur = sSeg[0];
        for (int m = 0; m < 128; m++) {
            int s = sSeg[m];
            if (s != cur) { atomicAdd(&g_cnt[cur], c); c = 0.f; cur = s; }
            c += 1.f;
        }
        atomicAdd(&g_cnt[cur], c);
    }
}

// ---------------- kernel C: fragment MLP head ----------------
__global__ __launch_bounds__(256, 1) void frag_mlp_kernel(
    const int* __restrict__ ind_maps, const int* __restrict__ broken,
    const float* __restrict__ W_m1, const float* __restrict__ b_m1,
    const float* __restrict__ W_m2, const float* __restrict__ b_m2,
    const float* __restrict__ W_out, const float* __restrict__ b_out,
    const float* __restrict__ W_attn, const float* __restrict__ b_attn,
    float* __restrict__ out) {
    extern __shared__ float sm[];
    float* sAct = sm;
    float* sW   = sm + H * SA;
    __shared__ int sInd[128];
    __shared__ float sInv[128];
    __shared__ int sBk[128];
    __shared__ float sBo[26];

    int tid = threadIdx.x;
    int base = blockIdx.x * 128;
    int valid = NF - base; if (valid > 128) valid = 128;

    if (tid < 128) {
        int f = base + tid;
        if (f < NF) {
            sInd[tid] = ind_maps[f];
            sInv[tid] = 1.f / fmaxf(g_cnt[f], 1.f);
            int b = broken[f];
            sBk[tid] = min(max(b, 0), 12);
        } else { sInd[tid] = 0; sInv[tid] = 0.f; sBk[tid] = 0; }
    }
    if (tid < 26) sBo[tid] = (tid < 13) ? b_out[tid] : b_attn[tid - 13];
    __syncthreads();

    // stage ext-root tile + Wa
    for (int idx = tid; idx < 128 * H; idx += 256) {
        int m = idx >> 7, n = idx & 127;
        sAct[m * SA + n] = g_root_emb[sInd[m] * H + n];
    }
    {   const float4* s = (const float4*)g_Wa; float4* d = (float4*)sW;
        for (int idx = tid; idx < H * (H / 4); idx += 256) d[idx] = s[idx]; }
    __syncthreads();

    int tx = tid & 15, ty = tid >> 4;
    ull acc[8][4];

    // layer1 pass 1: ext @ Wa  (+ b_m1)
    acc_bias(acc, b_m1, tx);
    gemm_acc(acc, sAct, sW, H, tx, ty);
    __syncthreads();

    // stage mean tile + Wb
    for (int idx = tid; idx < 128 * H; idx += 256) {
        int m = idx >> 7, n = idx & 127;
        int f = base + m;
        sAct[m * SA + n] = (f < NF) ? g_frag_sum[(size_t)f * H + n] * sInv[m] : 0.f;
    }
    {   const float4* s = (const float4*)g_Wb; float4* d = (float4*)sW;
        for (int idx = tid; idx < H * (H / 4); idx += 256) d[idx] = s[idx]; }
    __syncthreads();

    // layer1 pass 2: += mean @ Wb
    gemm_acc(acc, sAct, sW, H, tx, ty);
    __syncthreads();

    // + one-hot row of W_m1, relu, write H1
#pragma unroll
    for (int i = 0; i < 8; i++) {
        int m = ty * 8 + i;
        const float* wr = W_m1 + (size_t)(384 + sBk[m]) * H;
#pragma unroll
        for (int jj = 0; jj < 4; jj++) {
            int n = 2 * tx + 32 * jj;
            float lo, hi; unpack2(acc[i][jj], lo, hi);
            lo = fmaxf(lo + wr[n], 0.f);
            hi = fmaxf(hi + wr[n + 1], 0.f);
            *(float2*)(sAct + m * SA + n) = make_float2(lo, hi);
        }
    }
    {   const float4* s = (const float4*)W_m2; float4* d = (float4*)sW;
        for (int idx = tid; idx < H * (H / 4); idx += 256) d[idx] = s[idx]; }
    __syncthreads();

    // layer2: relu(H1 @ W_m2 + b_m2)
    acc_bias(acc, b_m2, tx);
    gemm_acc(acc, sAct, sW, H, tx, ty);
    __syncthreads();
    write_act(acc, sAct, true, tx, ty);

    // build combined output weights [k][26] = [W_out | W_attn]
    for (int idx = tid; idx < H * 13; idx += 256) {
        int k = idx / 13, c = idx - 13 * k;
        sW[k * 26 + c]      = W_out[idx];
        sW[k * 26 + 13 + c] = W_attn[idx];
    }
    __syncthreads();

    // output layer: 26 columns (13 sigmoid + 13 linear)
    for (int o = tid; o < 128 * 26; o += 256) {
        int m = o / 26, c = o - 26 * m;
        if (m < valid) {
            float s = sBo[c];
            const float* h = sAct + m * SA;
#pragma unroll 4
            for (int k = 0; k < H; k++) s += h[k] * sW[k * 26 + c];
            int f = base + m;
            if (c < 13) out[f * 13 + c] = 1.f / (1.f + __expf(-s));
            else        out[(size_t)NF * 13 + f * 13 + (c - 13)] = s;
        }
    }
}

// ---------------- launcher ----------------
extern "C" void kernel_launch(void* const* d_in, const int* in_sizes, int n_in,
                              void* d_out, int out_size) {
    const float* node_h    = (const float*)d_in[0];
    const int*   seg       = (const int*)d_in[1];
    const float* root_repr = (const float*)d_in[2];
    const int*   ind_maps  = (const int*)d_in[3];
    const int*   broken    = (const int*)d_in[4];
    const float* W_root = (const float*)d_in[5];  const float* b_root = (const float*)d_in[6];
    const float* W_in   = (const float*)d_in[7];  const float* b_in   = (const float*)d_in[8];
    const float* W_g1   = (const float*)d_in[9];  const float* b_g1   = (const float*)d_in[10];
    const float* W_g2   = (const float*)d_in[11]; const float* b_g2   = (const float*)d_in[12];
    const float* W_m1   = (const float*)d_in[13]; const float* b_m1   = (const float*)d_in[14];
    const float* W_m2   = (const float*)d_in[15]; const float* b_m2   = (const float*)d_in[16];
    const float* W_out  = (const float*)d_in[17]; const float* b_out  = (const float*)d_in[18];
    const float* W_attn = (const float*)d_in[19]; const float* b_attn = (const float*)d_in[20];
    float* out = (float*)d_out;

    void* p_fs = nullptr; void* p_cnt = nullptr;
    cudaGetSymbolAddress(&p_fs, g_frag_sum);
    cudaGetSymbolAddress(&p_cnt, g_cnt);
    cudaMemsetAsync(p_fs, 0, (size_t)NF * H * sizeof(float), 0);
    cudaMemsetAsync(p_cnt, 0, (size_t)NF * sizeof(float), 0);

    int smem = (H * SA + H * H) * (int)sizeof(float);   // ~132 KB
    cudaFuncSetAttribute(node_chain_kernel, cudaFuncAttributeMaxDynamicSharedMemorySize, smem);
    cudaFuncSetAttribute(frag_mlp_kernel,   cudaFuncAttributeMaxDynamicSharedMemorySize, smem);

    root_enc_kernel<<<NR, 128>>>(root_repr, W_root, b_root);
    combine_w_kernel<<<(H * H + 255) / 256, 256>>>(W_m1);
    node_chain_kernel<<<NN / 128, 256, smem>>>(node_h, seg, W_in, b_in, W_g1, b_g1, W_g2, b_g2);
    frag_mlp_kernel<<<(NF + 127) / 128, 256, smem>>>(ind_maps, broken, W_m1, b_m1,
                                                     W_m2, b_m2, W_out, b_out,
                                                     W_attn, b_attn, out);
}

// round 5
// speedup vs baseline: 1.8451x; 1.8451x over previous
#include <cuda_runtime.h>
#include <cuda_bf16.h>

typedef unsigned int u32; typedef unsigned short u16;

#define NN   800000
#define NF   100000
#define NR   2000
#define FEAT 86
#define H    128
#define KPAD 264                 // u16 per row (stride 132 words -> conflict-free)
#define IMG16 (128 * KPAD)       // 33792 u16 per weight image
#define IMGV4 (IMG16 / 8)        // 4224 uint4 per image
#define DYN_SMEM (3 * IMG16 * 2) // A + W0 + W1 = 202752 B

// ---------------- device scratch ----------------
__device__ __align__(16) u16   g_imgs[7 * IMG16];
__device__ __align__(16) float g_root_emb[NR * H];
__device__ __align__(16) float g_frag_sum[(size_t)NF * H];
__device__ float g_cnt[NF];

// ---------------- helpers ----------------
__device__ __forceinline__ u32 smem_u32(const void* p) {
    u32 a; asm("{ .reg .u64 t; cvta.to.shared.u64 t, %1; cvt.u32.u64 %0, t; }" : "=r"(a) : "l"(p));
    return a;
}
__device__ __forceinline__ void cpa16(u32 dst, const void* src) {
    asm volatile("cp.async.ca.shared.global [%0], [%1], 16;" :: "r"(dst), "l"(src));
}
#define CPA_COMMIT() asm volatile("cp.async.commit_group;" ::: "memory")
#define CPA_WAIT(n)  asm volatile("cp.async.wait_group %0;" :: "n"(n) : "memory")

__device__ __forceinline__ u32 pack_bf2(float lo, float hi) {
    u32 r; asm("cvt.rn.bf16x2.f32 %0, %1, %2;" : "=r"(r) : "f"(hi), "f"(lo)); return r;
}
__device__ __forceinline__ void split_pair(float v0, float v1, u32& hp, u32& lp) {
    hp = pack_bf2(v0, v1);
    float r0 = v0 - __uint_as_float(hp << 16);
    float r1 = v1 - __uint_as_float(hp & 0xFFFF0000u);
    lp = pack_bf2(r0, r1);
}
__device__ __forceinline__ void mma16816(float* c, u32 a0, u32 a1, u32 a2, u32 a3, u32 b0, u32 b1) {
    asm volatile("mma.sync.aligned.m16n8k16.row.col.f32.bf16.bf16.f32 "
                 "{%0,%1,%2,%3}, {%4,%5,%6,%7}, {%8,%9}, {%0,%1,%2,%3};"
                 : "+f"(c[0]), "+f"(c[1]), "+f"(c[2]), "+f"(c[3])
                 : "r"(a0), "r"(a1), "r"(a2), "r"(a3), "r"(b0), "r"(b1));
}

// hi/lo split GEMM: 3 passes (Ahi*Whi + Ahi*Wlo + Alo*Whi). KH = hi width (mult of 16).
template<int NT>
__device__ __forceinline__ void mma_passes(float acc[NT][4], const u16* __restrict__ A,
                                           const u16* __restrict__ W, int KH, int wrow, int lane) {
    int r0 = wrow + (lane >> 2);
    int q2 = (lane & 3) * 2;
    int nk = KH >> 4;
    const int pa[3] = {0, 0, 1}, pw[3] = {0, 1, 0};
#pragma unroll
    for (int p = 0; p < 3; p++) {
        int ab = pa[p] * KH, wb = pw[p] * KH;
        for (int ks = 0; ks < nk; ks++) {
            int ak = ab + ks * 16 + q2;
            u32 a0 = *(const u32*)(A + r0 * KPAD + ak);
            u32 a1 = *(const u32*)(A + (r0 + 8) * KPAD + ak);
            u32 a2 = *(const u32*)(A + r0 * KPAD + ak + 8);
            u32 a3 = *(const u32*)(A + (r0 + 8) * KPAD + ak + 8);
            const u16* Wn = W + (lane >> 2) * KPAD + wb + ks * 16 + q2;
#pragma unroll
            for (int t = 0; t < NT; t++) {
                u32 b0 = *(const u32*)(Wn + t * 8 * KPAD);
                u32 b1 = *(const u32*)(Wn + t * 8 * KPAD + 8);
                mma16816(acc[t], a0, a1, a2, a3, b0, b1);
            }
        }
    }
}

// epilogue: acc + bias (+one-hot) (+relu) -> split hi/lo back into A image
__device__ __forceinline__ void epi_store_A(u16* __restrict__ A, float acc[16][4],
                                            const float* __restrict__ bias,
                                            const float* __restrict__ sOne, const int* __restrict__ sBk,
                                            bool relu, int wrow, int lane) {
    int q2 = (lane & 3) * 2;
    int rA = wrow + (lane >> 2), rB = rA + 8;
    const float* oneA = sOne ? (sOne + sBk[rA] * 132) : (const float*)0;
    const float* oneB = sOne ? (sOne + sBk[rB] * 132) : (const float*)0;
#pragma unroll
    for (int t = 0; t < 16; t++) {
        int c = t * 8 + q2;
        float v0 = acc[t][0] + bias[c], v1 = acc[t][1] + bias[c + 1];
        float w0 = acc[t][2] + bias[c], w1 = acc[t][3] + bias[c + 1];
        if (oneA) { v0 += oneA[c]; v1 += oneA[c + 1]; }
        if (oneB) { w0 += oneB[c]; w1 += oneB[c + 1]; }
        if (relu) { v0 = fmaxf(v0, 0.f); v1 = fmaxf(v1, 0.f); w0 = fmaxf(w0, 0.f); w1 = fmaxf(w1, 0.f); }
        u32 hp, lp;
        split_pair(v0, v1, hp, lp);
        *(u32*)(A + rA * KPAD + c) = hp;
        *(u32*)(A + rA * KPAD + 128 + c) = lp;
        split_pair(w0, w1, hp, lp);
        *(u32*)(A + rB * KPAD + c) = hp;
        *(u32*)(A + rB * KPAD + 128 + c) = lp;
    }
}

// ---------------- prep: split/transpose weights into bf16 hi/lo images ----------------
// img0 W_in (hi cols 0..85 in [0,96), lo at 96+k)  img1 Wg1  img2 Wg2
// img3 Wa=W1a+W1b  img4 Wb=W1c-W1b  img5 Wm2  img6 [W_out|W_attn] (n<26)
__global__ void prep_kernel(const float* __restrict__ W_in, const float* __restrict__ Wg1,
                            const float* __restrict__ Wg2, const float* __restrict__ Wm1,
                            const float* __restrict__ Wm2, const float* __restrict__ Wout,
                            const float* __restrict__ Wattn) {
    int idx = blockIdx.x * 256 + threadIdx.x;
    if (idx >= 7 * 16384) return;
    int img = idx >> 14, r = idx & 16383, n = r >> 7, k = r & 127;
    float w; int locol;
    if (img == 0)      { if (k >= FEAT) return; w = W_in[k * H + n]; locol = 96 + k; }
    else if (img == 1) { w = Wg1[k * H + n]; locol = 128 + k; }
    else if (img == 2) { w = Wg2[k * H + n]; locol = 128 + k; }
    else if (img == 3) { w = Wm1[k * H + n] + Wm1[(H + k) * H + n]; locol = 128 + k; }
    else if (img == 4) { w = Wm1[(2 * H + k) * H + n] - Wm1[(H + k) * H + n]; locol = 128 + k; }
    else if (img == 5) { w = Wm2[k * H + n]; locol = 128 + k; }
    else               { if (n >= 26) return;
                         w = (n < 13) ? Wout[k * 13 + n] : Wattn[k * 13 + (n - 13)]; locol = 128 + k; }
    __nv_bfloat16 hb = __float2bfloat16(w);
    __nv_bfloat16 lb = __float2bfloat16(w - __bfloat162float(hb));
    u16* ib = g_imgs + img * IMG16 + n * KPAD;
    ib[k]     = __bfloat16_as_ushort(hb);
    ib[locol] = __bfloat16_as_ushort(lb);
}

// ---------------- root encoder (tiny, SIMT) ----------------
__global__ void root_enc_kernel(const float* __restrict__ root_repr,
                                const float* __restrict__ W_root,
                                const float* __restrict__ b_root) {
    __shared__ float sX[FEAT];
    int r = blockIdx.x, n = threadIdx.x;
    for (int k = n; k < FEAT; k += 128) sX[k] = root_repr[r * FEAT + k];
    __syncthreads();
    float s = b_root[n];
#pragma unroll 2
    for (int k = 0; k < FEAT; k++) s += sX[k] * W_root[k * H + n];
    g_root_emb[r * H + n] = fmaxf(s, 0.f);
}

// ---------------- node chain: 3 layers of tensor-core GEMM + pooling ----------------
__global__ __launch_bounds__(256, 1) void node_chain_kernel(
    const float* __restrict__ node_h, const int* __restrict__ seg,
    const float* __restrict__ b_in, const float* __restrict__ b_g1,
    const float* __restrict__ b_g2) {
    extern __shared__ __align__(16) u16 sm16[];
    u16* A  = sm16;
    u16* W0 = A + IMG16;
    u16* W1 = W0 + IMG16;
    __shared__ int sSeg[128];
    __shared__ float sB[3][128];

    int tid = threadIdx.x, lane = tid & 31, wrow = (tid >> 5) * 16;
    int tilebase = blockIdx.x * 128;   // NN = 6250*128 exactly
    u32 w0a = smem_u32(W0), w1a = smem_u32(W1);

    // start async W loads (g0 = W_in, g1 = W_g1)
    for (int i = tid; i < IMGV4; i += 256) cpa16(w0a + i * 16, (const uint4*)g_imgs + i);
    CPA_COMMIT();
    for (int i = tid; i < IMGV4; i += 256) cpa16(w1a + i * 16, (const uint4*)(g_imgs + IMG16) + i);
    CPA_COMMIT();

    // zero A, load seg + biases
    for (int i = tid; i < IMGV4; i += 256) ((uint4*)A)[i] = make_uint4(0, 0, 0, 0);
    if (tid < 128) { sSeg[tid] = seg[tilebase + tid]; sB[0][tid] = b_in[tid]; sB[1][tid] = b_g1[tid]; sB[2][tid] = b_g2[tid]; }
    __syncthreads();

    // stage node_h: hi cols 0..85, lo cols 96..181
    for (int idx = tid; idx < 128 * 43; idx += 256) {
        int m = idx / 43, k = (idx - m * 43) * 2;
        float2 v = *(const float2*)(node_h + (size_t)(tilebase + m) * FEAT + k);
        u32 hp, lp; split_pair(v.x, v.y, hp, lp);
        *(u32*)(A + m * KPAD + k) = hp;
        *(u32*)(A + m * KPAD + 96 + k) = lp;
    }
    CPA_WAIT(1);       // W_in ready
    __syncthreads();

    float acc[16][4];

    // L1: x @ W_in + b_in (no relu), KH=96
#pragma unroll
    for (int t = 0; t < 16; t++) { acc[t][0] = acc[t][1] = acc[t][2] = acc[t][3] = 0.f; }
    mma_passes<16>(acc, A, W0, 96, wrow, lane);
    __syncthreads();
    // prefetch W_g2 into W0 (reads of W0 done)
    for (int i = tid; i < IMGV4; i += 256) cpa16(w0a + i * 16, (const uint4*)(g_imgs + 2 * IMG16) + i);
    CPA_COMMIT();
    epi_store_A(A, acc, sB[0], (const float*)0, (const int*)0, false, wrow, lane);
    __syncthreads();

    // L2: relu(h @ W_g1 + b_g1)
#pragma unroll
    for (int t = 0; t < 16; t++) { acc[t][0] = acc[t][1] = acc[t][2] = acc[t][3] = 0.f; }
    mma_passes<16>(acc, A, W1, 128, wrow, lane);
    __syncthreads();
    epi_store_A(A, acc, sB[1], (const float*)0, (const int*)0, true, wrow, lane);
    CPA_WAIT(0);       // W_g2 ready
    __syncthreads();

    // L3: relu(h @ W_g2 + b_g2) -> pool (fp32, overlays W1)
#pragma unroll
    for (int t = 0; t < 16; t++) { acc[t][0] = acc[t][1] = acc[t][2] = acc[t][3] = 0.f; }
    mma_passes<16>(acc, A, W0, 128, wrow, lane);
    __syncthreads();
    {
        float* pool = (float*)W1;
        int q2 = (lane & 3) * 2;
        int rA = wrow + (lane >> 2), rB = rA + 8;
#pragma unroll
        for (int t = 0; t < 16; t++) {
            int c = t * 8 + q2;
            *(float2*)(pool + rA * 130 + c) =
                make_float2(fmaxf(acc[t][0] + sB[2][c], 0.f), fmaxf(acc[t][1] + sB[2][c + 1], 0.f));
            *(float2*)(pool + rB * 130 + c) =
                make_float2(fmaxf(acc[t][2] + sB[2][c], 0.f), fmaxf(acc[t][3] + sB[2][c + 1], 0.f));
        }
    }
    __syncthreads();

    // sorted-segment run-length pooling, one atomic per boundary
    const float* pool = (const float*)W1;
    if (tid < 128) {
        int n = tid;
        float r = 0.f; int cur = sSeg[0];
        for (int m = 0; m < 128; m++) {
            int s = sSeg[m];
            if (s != cur) { atomicAdd(&g_frag_sum[(size_t)cur * H + n], r); r = 0.f; cur = s; }
            r += pool[m * 130 + n];
        }
        atomicAdd(&g_frag_sum[(size_t)cur * H + n], r);
    } else if (tid == 128) {
        float c = 0.f; int cur = sSeg[0];
        for (int m = 0; m < 128; m++) {
            int s = sSeg[m];
            if (s != cur) { atomicAdd(&g_cnt[cur], c); c = 0.f; cur = s; }
            c += 1.f;
        }
        atomicAdd(&g_cnt[cur], c);
    }
}

// ---------------- fragment MLP head ----------------
__global__ __launch_bounds__(256, 1) void frag_mlp_kernel(
    const int* __restrict__ ind_maps, const int* __restrict__ broken,
    const float* __restrict__ W_m1, const float* __restrict__ b_m1,
    const float* __restrict__ b_m2, const float* __restrict__ b_out,
    const float* __restrict__ b_attn, float* __restrict__ out) {
    extern __shared__ __align__(16) u16 sm16[];
    u16* A  = sm16;
    u16* W0 = A + IMG16;
    u16* W1 = W0 + IMG16;
    __shared__ int sInd[128]; __shared__ float sInv[128]; __shared__ int sBk[128];
    __shared__ float sB1[128], sB2[128], sBo[26];
    __shared__ float sOne[13 * 132];

    int tid = threadIdx.x, lane = tid & 31, wrow = (tid >> 5) * 16;
    int base = blockIdx.x * 128;
    u32 w0a = smem_u32(W0), w1a = smem_u32(W1);

    // async W loads: g0 = Wa, g1 = Wb
    for (int i = tid; i < IMGV4; i += 256) cpa16(w0a + i * 16, (const uint4*)(g_imgs + 3 * IMG16) + i);
    CPA_COMMIT();
    for (int i = tid; i < IMGV4; i += 256) cpa16(w1a + i * 16, (const uint4*)(g_imgs + 4 * IMG16) + i);
    CPA_COMMIT();

    if (tid < 128) {
        int f = base + tid;
        sInd[tid] = (f < NF) ? ind_maps[f] : 0;
        sInv[tid] = (f < NF) ? 1.f / fmaxf(g_cnt[f], 1.f) : 0.f;
        int b = (f < NF) ? broken[f] : 0;
        sBk[tid] = min(max(b, 0), 12);
        sB1[tid] = b_m1[tid]; sB2[tid] = b_m2[tid];
    }
    if (tid < 26) sBo[tid] = (tid < 13) ? b_out[tid] : b_attn[tid - 13];
    for (int i = tid; i < 13 * 128; i += 256) {
        int rr = i >> 7, c = i & 127;
        sOne[rr * 132 + c] = W_m1[(size_t)(384 + rr) * H + c];
    }
    __syncthreads();

    // stage ext-root rows (hi 0..127, lo 128..255)
    for (int idx = tid; idx < 128 * 64; idx += 256) {
        int m = idx >> 6, k = (idx & 63) * 2;
        float2 v = *(const float2*)(g_root_emb + (size_t)sInd[m] * H + k);
        u32 hp, lp; split_pair(v.x, v.y, hp, lp);
        *(u32*)(A + m * KPAD + k) = hp;
        *(u32*)(A + m * KPAD + 128 + k) = lp;
    }
    CPA_WAIT(1);       // Wa ready
    __syncthreads();

    float acc[16][4];
#pragma unroll
    for (int t = 0; t < 16; t++) { acc[t][0] = acc[t][1] = acc[t][2] = acc[t][3] = 0.f; }

    // L1 part 1: ext @ Wa
    mma_passes<16>(acc, A, W0, 128, wrow, lane);
    __syncthreads();

    // restage A = mean rows; prefetch Wm2 -> W0
    for (int idx = tid; idx < 128 * 64; idx += 256) {
        int m = idx >> 6, k = (idx & 63) * 2;
        int f = base + m;
        float2 v = make_float2(0.f, 0.f);
        if (f < NF) {
            v = *(const float2*)(g_frag_sum + (size_t)f * H + k);
            v.x *= sInv[m]; v.y *= sInv[m];
        }
        u32 hp, lp; split_pair(v.x, v.y, hp, lp);
        *(u32*)(A + m * KPAD + k) = hp;
        *(u32*)(A + m * KPAD + 128 + k) = lp;
    }
    for (int i = tid; i < IMGV4; i += 256) cpa16(w0a + i * 16, (const uint4*)(g_imgs + 5 * IMG16) + i);
    CPA_COMMIT();
    __syncthreads();

    // L1 part 2: += mean @ Wb
    mma_passes<16>(acc, A, W1, 128, wrow, lane);
    __syncthreads();

    // epilogue L1 (bias + one-hot + relu) -> A; prefetch Wout -> W1
    epi_store_A(A, acc, sB1, sOne, sBk, true, wrow, lane);
    for (int i = tid; i < IMGV4; i += 256) cpa16(w1a + i * 16, (const uint4*)(g_imgs + 6 * IMG16) + i);
    CPA_COMMIT();
    CPA_WAIT(1);       // Wm2 ready
    __syncthreads();

    // L2: relu(H1 @ Wm2 + b_m2)
#pragma unroll
    for (int t = 0; t < 16; t++) { acc[t][0] = acc[t][1] = acc[t][2] = acc[t][3] = 0.f; }
    mma_passes<16>(acc, A, W0, 128, wrow, lane);
    __syncthreads();
    epi_store_A(A, acc, sB2, (const float*)0, (const int*)0, true, wrow, lane);
    CPA_WAIT(0);       // Wout ready
    __syncthreads();

    // output layer: 26 cols (4 n-tiles)
    float acc4[4][4];
#pragma unroll
    for (int t = 0; t < 4; t++) { acc4[t][0] = acc4[t][1] = acc4[t][2] = acc4[t][3] = 0.f; }
    mma_passes<4>(acc4, A, W1, 128, wrow, lane);

    {
        int q2 = (lane & 3) * 2;
        int rA = wrow + (lane >> 2), rB = rA + 8;
        int fA = base + rA, fB = base + rB;
#pragma unroll
        for (int t = 0; t < 4; t++) {
#pragma unroll
            for (int e = 0; e < 2; e++) {
                int c = t * 8 + q2 + e;
                if (c >= 26) continue;
                if (fA < NF) {
                    float v = acc4[t][e] + sBo[c];
                    if (c < 13) out[(size_t)fA * 13 + c] = 1.f / (1.f + __expf(-v));
                    else        out[(size_t)NF * 13 + (size_t)fA * 13 + (c - 13)] = v;
                }
                if (fB < NF) {
                    float v = acc4[t][2 + e] + sBo[c];
                    if (c < 13) out[(size_t)fB * 13 + c] = 1.f / (1.f + __expf(-v));
                    else        out[(size_t)NF * 13 + (size_t)fB * 13 + (c - 13)] = v;
                }
            }
        }
    }
}

// ---------------- launcher ----------------
extern "C" void kernel_launch(void* const* d_in, const int* in_sizes, int n_in,
                              void* d_out, int out_size) {
    const float* node_h    = (const float*)d_in[0];
    const int*   seg       = (const int*)d_in[1];
    const float* root_repr = (const float*)d_in[2];
    const int*   ind_maps  = (const int*)d_in[3];
    const int*   broken    = (const int*)d_in[4];
    const float* W_root = (const float*)d_in[5];  const float* b_root = (const float*)d_in[6];
    const float* W_in   = (const float*)d_in[7];  const float* b_in   = (const float*)d_in[8];
    const float* W_g1   = (const float*)d_in[9];  const float* b_g1   = (const float*)d_in[10];
    const float* W_g2   = (const float*)d_in[11]; const float* b_g2   = (const float*)d_in[12];
    const float* W_m1   = (const float*)d_in[13]; const float* b_m1   = (const float*)d_in[14];
    const float* W_m2   = (const float*)d_in[15]; const float* b_m2   = (const float*)d_in[16];
    const float* W_out  = (const float*)d_in[17]; const float* b_out  = (const float*)d_in[18];
    const float* W_attn = (const float*)d_in[19]; const float* b_attn = (const float*)d_in[20];
    float* out = (float*)d_out;

    void* p = 0;
    cudaGetSymbolAddress(&p, g_frag_sum);
    cudaMemsetAsync(p, 0, (size_t)NF * H * sizeof(float), 0);
    cudaGetSymbolAddress(&p, g_cnt);
    cudaMemsetAsync(p, 0, (size_t)NF * sizeof(float), 0);
    cudaGetSymbolAddress(&p, g_imgs);
    cudaMemsetAsync(p, 0, (size_t)7 * IMG16 * sizeof(u16), 0);

    cudaFuncSetAttribute(node_chain_kernel, cudaFuncAttributeMaxDynamicSharedMemorySize, DYN_SMEM);
    cudaFuncSetAttribute(frag_mlp_kernel,   cudaFuncAttributeMaxDynamicSharedMemorySize, DYN_SMEM);

    prep_kernel<<<(7 * 16384 + 255) / 256, 256>>>(W_in, W_g1, W_g2, W_m1, W_m2, W_out, W_attn);
    root_enc_kernel<<<NR, 128>>>(root_repr, W_root, b_root);
    node_chain_kernel<<<NN / 128, 256, DYN_SMEM>>>(node_h, seg, b_in, b_g1, b_g2);
    frag_mlp_kernel<<<(NF + 127) / 128, 256, DYN_SMEM>>>(ind_maps, broken, W_m1, b_m1,
                                                         b_m2, b_out, b_attn, out);
}

// round 6
// speedup vs baseline: 1.8886x; 1.0236x over previous
#include <cuda_runtime.h>
#include <cuda_bf16.h>

typedef unsigned int u32; typedef unsigned short u16;

#define NN    800000
#define NF    100000
#define NR    2000
#define FEAT  86
#define H     128
#define KPAD  264                 // u16 per row (stride 132 words -> conflict-free)
#define IMG16 (128 * KPAD)        // 33792 u16 per weight image
#define IMGV4 (IMG16 / 8)
#define AROWS 256
#define A16   (AROWS * KPAD)      // 67584 u16
#define DYN_SMEM ((A16 + IMG16) * 2)   // 202752 B

// ---------------- device scratch ----------------
__device__ __align__(16) u16   g_imgs[7 * IMG16];
__device__ __align__(16) float g_root_emb[NR * H];
__device__ __align__(16) float g_frag_sum[(size_t)NF * H];
__device__ float g_cnt[NF];

// ---------------- helpers ----------------
__device__ __forceinline__ u32 smem_u32(const void* p) {
    u32 a; asm("{ .reg .u64 t; cvta.to.shared.u64 t, %1; cvt.u32.u64 %0, t; }" : "=r"(a) : "l"(p));
    return a;
}
__device__ __forceinline__ void cpa16(u32 dst, const void* src) {
    asm volatile("cp.async.ca.shared.global [%0], [%1], 16;" :: "r"(dst), "l"(src));
}
#define CPA_COMMIT() asm volatile("cp.async.commit_group;" ::: "memory")
#define CPA_WAIT0()  asm volatile("cp.async.wait_group 0;" ::: "memory")

#define LDSM4(d0, d1, d2, d3, a) \
    asm volatile("ldmatrix.sync.aligned.m8n8.x4.shared.b16 {%0,%1,%2,%3}, [%4];" \
                 : "=r"(d0), "=r"(d1), "=r"(d2), "=r"(d3) : "r"(a))

__device__ __forceinline__ u32 pack_bf2(float lo, float hi) {
    u32 r; asm("cvt.rn.bf16x2.f32 %0, %1, %2;" : "=r"(r) : "f"(hi), "f"(lo)); return r;
}
__device__ __forceinline__ void split_pair(float v0, float v1, u32& hp, u32& lp) {
    hp = pack_bf2(v0, v1);
    float r0 = v0 - __uint_as_float(hp << 16);
    float r1 = v1 - __uint_as_float(hp & 0xFFFF0000u);
    lp = pack_bf2(r0, r1);
}
__device__ __forceinline__ void mma16816(float* c, u32 a0, u32 a1, u32 a2, u32 a3, u32 b0, u32 b1) {
    asm volatile("mma.sync.aligned.m16n8k16.row.col.f32.bf16.bf16.f32 "
                 "{%0,%1,%2,%3}, {%4,%5,%6,%7}, {%8,%9}, {%0,%1,%2,%3};"
                 : "+f"(c[0]), "+f"(c[1]), "+f"(c[2]), "+f"(c[3])
                 : "r"(a0), "r"(a1), "r"(a2), "r"(a3), "r"(b0), "r"(b1));
}

// ---------------- 64x32 warp-tile GEMM core (hi/lo split: 3 passes) ----------------
// aBase: lane-adjusted smem addr of A hi region; bBase: same for W.
__device__ __forceinline__ void mma_block(float acc[4][4][4], u32 aBase, u32 bBase, int KH) {
    int nk = KH >> 4;
#pragma unroll
    for (int p = 0; p < 3; p++) {
        u32 aAddr = aBase + ((p == 2) ? (u32)(KH * 2) : 0u);
        u32 bAddr = bBase + ((p == 1) ? (u32)(KH * 2) : 0u);
        for (int ks = 0; ks < nk; ks++) {
            u32 a[4][4], b[2][4];
#pragma unroll
            for (int mt = 0; mt < 4; mt++)
                LDSM4(a[mt][0], a[mt][1], a[mt][2], a[mt][3], aAddr + mt * (16 * KPAD * 2));
#pragma unroll
            for (int h = 0; h < 2; h++)
                LDSM4(b[h][0], b[h][1], b[h][2], b[h][3], bAddr + h * (16 * KPAD * 2));
#pragma unroll
            for (int mt = 0; mt < 4; mt++) {
                mma16816(acc[mt][0], a[mt][0], a[mt][1], a[mt][2], a[mt][3], b[0][0], b[0][1]);
                mma16816(acc[mt][1], a[mt][0], a[mt][1], a[mt][2], a[mt][3], b[0][2], b[0][3]);
                mma16816(acc[mt][2], a[mt][0], a[mt][1], a[mt][2], a[mt][3], b[1][0], b[1][1]);
                mma16816(acc[mt][3], a[mt][0], a[mt][1], a[mt][2], a[mt][3], b[1][2], b[1][3]);
            }
            aAddr += 32; bAddr += 32;
        }
    }
}
__device__ __forceinline__ void acc_zero(float acc[4][4][4]) {
#pragma unroll
    for (int mt = 0; mt < 4; mt++)
#pragma unroll
        for (int nt = 0; nt < 4; nt++)
#pragma unroll
            for (int e = 0; e < 4; e++) acc[mt][nt][e] = 0.f;
}

// epilogue: acc + bias (+one-hot) (+relu) -> split hi/lo back into A image
__device__ __forceinline__ void epi_store(u16* __restrict__ A, float acc[4][4][4],
                                          const float* __restrict__ bias,
                                          const float* __restrict__ sOne, const int* __restrict__ sBk,
                                          bool relu, int mrow0, int ncol0, int lane) {
    int gr = lane >> 2, q2 = (lane & 3) * 2;
#pragma unroll
    for (int mt = 0; mt < 4; mt++) {
        int r0 = mrow0 + mt * 16 + gr, r1 = r0 + 8;
        const float* oA = sOne ? (sOne + sBk[r0] * 132) : (const float*)0;
        const float* oB = sOne ? (sOne + sBk[r1] * 132) : (const float*)0;
#pragma unroll
        for (int nt = 0; nt < 4; nt++) {
            int c = ncol0 + nt * 8 + q2;
            float v0 = acc[mt][nt][0] + bias[c], v1 = acc[mt][nt][1] + bias[c + 1];
            float w0 = acc[mt][nt][2] + bias[c], w1 = acc[mt][nt][3] + bias[c + 1];
            if (oA) { v0 += oA[c]; v1 += oA[c + 1]; }
            if (oB) { w0 += oB[c]; w1 += oB[c + 1]; }
            if (relu) { v0 = fmaxf(v0, 0.f); v1 = fmaxf(v1, 0.f); w0 = fmaxf(w0, 0.f); w1 = fmaxf(w1, 0.f); }
            u32 hp, lp;
            split_pair(v0, v1, hp, lp);
            *(u32*)(A + r0 * KPAD + c) = hp;
            *(u32*)(A + r0 * KPAD + 128 + c) = lp;
            split_pair(w0, w1, hp, lp);
            *(u32*)(A + r1 * KPAD + c) = hp;
            *(u32*)(A + r1 * KPAD + 128 + c) = lp;
        }
    }
}

// ---------------- prep: split/transpose weights into bf16 hi/lo images ----------------
__global__ void prep_kernel(const float* __restrict__ W_in, const float* __restrict__ Wg1,
                            const float* __restrict__ Wg2, const float* __restrict__ Wm1,
                            const float* __restrict__ Wm2, const float* __restrict__ Wout,
                            const float* __restrict__ Wattn) {
    int idx = blockIdx.x * 256 + threadIdx.x;
    if (idx >= 7 * 16384) return;
    int img = idx >> 14, r = idx & 16383, n = r >> 7, k = r & 127;
    float w; int locol;
    if (img == 0)      { if (k >= FEAT) return; w = W_in[k * H + n]; locol = 96 + k; }
    else if (img == 1) { w = Wg1[k * H + n]; locol = 128 + k; }
    else if (img == 2) { w = Wg2[k * H + n]; locol = 128 + k; }
    else if (img == 3) { w = Wm1[k * H + n] + Wm1[(H + k) * H + n]; locol = 128 + k; }
    else if (img == 4) { w = Wm1[(2 * H + k) * H + n] - Wm1[(H + k) * H + n]; locol = 128 + k; }
    else if (img == 5) { w = Wm2[k * H + n]; locol = 128 + k; }
    else               { if (n >= 26) return;
                         w = (n < 13) ? Wout[k * 13 + n] : Wattn[k * 13 + (n - 13)]; locol = 128 + k; }
    __nv_bfloat16 hb = __float2bfloat16(w);
    __nv_bfloat16 lb = __float2bfloat16(w - __bfloat162float(hb));
    u16* ib = g_imgs + img * IMG16 + n * KPAD;
    ib[k]     = __bfloat16_as_ushort(hb);
    ib[locol] = __bfloat16_as_ushort(lb);
}

// ---------------- root encoder (tiny, SIMT) ----------------
__global__ void root_enc_kernel(const float* __restrict__ root_repr,
                                const float* __restrict__ W_root,
                                const float* __restrict__ b_root) {
    __shared__ float sX[FEAT];
    int r = blockIdx.x, n = threadIdx.x;
    for (int k = n; k < FEAT; k += 128) sX[k] = root_repr[r * FEAT + k];
    __syncthreads();
    float s = b_root[n];
#pragma unroll 2
    for (int k = 0; k < FEAT; k++) s += sX[k] * W_root[k * H + n];
    g_root_emb[r * H + n] = fmaxf(s, 0.f);
}

// ---------------- node chain: 256 rows/CTA, 512 threads ----------------
__global__ __launch_bounds__(512, 1) void node_chain_kernel(
    const float* __restrict__ node_h, const int* __restrict__ seg,
    const float* __restrict__ b_in, const float* __restrict__ b_g1,
    const float* __restrict__ b_g2) {
    extern __shared__ __align__(16) u16 sm16[];
    u16* A = sm16;
    u16* W = A + A16;
    __shared__ int sSeg[AROWS];
    __shared__ float sB[3][128];

    int tid = threadIdx.x, lane = tid & 31, w = tid >> 5;
    int mrow0 = (w >> 2) * 64, ncol0 = (w & 3) * 32;
    int tilebase = blockIdx.x * AROWS;       // NN = 3125*256 exactly
    u32 wAdr = smem_u32(W);

    for (int i = tid; i < IMGV4; i += 512) cpa16(wAdr + i * 16, (const uint4*)g_imgs + i);
    CPA_COMMIT();

    // zero pad slivers (hi 86..95, lo 182..191)
    for (int i = tid; i < AROWS * 5; i += 512) {
        int m = i / 5, j = i - 5 * (i / 5);
        *(u32*)(A + m * KPAD + 86 + 2 * j) = 0;
        *(u32*)(A + m * KPAD + 182 + 2 * j) = 0;
    }
    if (tid < AROWS) sSeg[tid] = seg[tilebase + tid];
    if (tid < 128) { sB[0][tid] = b_in[tid]; sB[1][tid] = b_g1[tid]; sB[2][tid] = b_g2[tid]; }
    // stage node_h: hi cols 0..85, lo at 96+k
    for (int idx = tid; idx < AROWS * 43; idx += 512) {
        int m = idx / 43, k = (idx - m * 43) * 2;
        float2 v = *(const float2*)(node_h + (size_t)(tilebase + m) * FEAT + k);
        u32 hp, lp; split_pair(v.x, v.y, hp, lp);
        *(u32*)(A + m * KPAD + k) = hp;
        *(u32*)(A + m * KPAD + 96 + k) = lp;
    }
    CPA_WAIT0(); __syncthreads();

    u32 aBase = smem_u32(A) + ((mrow0 + (lane & 15)) * KPAD + ((lane >> 4) << 3)) * 2;
    u32 bBase = smem_u32(W) + ((ncol0 + (lane & 7) + ((lane >> 4) << 3)) * KPAD + (((lane >> 3) & 1) << 3)) * 2;

    float acc[4][4][4];

    // L1: x @ W_in + b_in (KH=96, no relu)
    acc_zero(acc);
    mma_block(acc, aBase, bBase, 96);
    __syncthreads();
    for (int i = tid; i < IMGV4; i += 512) cpa16(wAdr + i * 16, (const uint4*)(g_imgs + IMG16) + i);
    CPA_COMMIT();
    epi_store(A, acc, sB[0], (const float*)0, (const int*)0, false, mrow0, ncol0, lane);
    CPA_WAIT0(); __syncthreads();

    // L2
    acc_zero(acc);
    mma_block(acc, aBase, bBase, 128);
    __syncthreads();
    for (int i = tid; i < IMGV4; i += 512) cpa16(wAdr + i * 16, (const uint4*)(g_imgs + 2 * IMG16) + i);
    CPA_COMMIT();
    epi_store(A, acc, sB[1], (const float*)0, (const int*)0, true, mrow0, ncol0, lane);
    CPA_WAIT0(); __syncthreads();

    // L3 -> pool fp32 (overlays A)
    acc_zero(acc);
    mma_block(acc, aBase, bBase, 128);
    __syncthreads();
    {
        float* pool = (float*)A;
        int gr = lane >> 2, q2 = (lane & 3) * 2;
#pragma unroll
        for (int mt = 0; mt < 4; mt++) {
            int r0 = mrow0 + mt * 16 + gr, r1 = r0 + 8;
#pragma unroll
            for (int nt = 0; nt < 4; nt++) {
                int c = ncol0 + nt * 8 + q2;
                *(float2*)(pool + r0 * 130 + c) =
                    make_float2(fmaxf(acc[mt][nt][0] + sB[2][c], 0.f),
                                fmaxf(acc[mt][nt][1] + sB[2][c + 1], 0.f));
                *(float2*)(pool + r1 * 130 + c) =
                    make_float2(fmaxf(acc[mt][nt][2] + sB[2][c], 0.f),
                                fmaxf(acc[mt][nt][3] + sB[2][c + 1], 0.f));
            }
        }
    }
    __syncthreads();

    // sorted-segment run-length pooling
    const float* pool = (const float*)A;
    if (tid < 128) {
        int n = tid;
        float r = 0.f; int cur = sSeg[0];
        for (int m = 0; m < AROWS; m++) {
            int s = sSeg[m];
            if (s != cur) { atomicAdd(&g_frag_sum[(size_t)cur * H + n], r); r = 0.f; cur = s; }
            r += pool[m * 130 + n];
        }
        atomicAdd(&g_frag_sum[(size_t)cur * H + n], r);
    } else if (tid == 128) {
        float c = 0.f; int cur = sSeg[0];
        for (int m = 0; m < AROWS; m++) {
            int s = sSeg[m];
            if (s != cur) { atomicAdd(&g_cnt[cur], c); c = 0.f; cur = s; }
            c += 1.f;
        }
        atomicAdd(&g_cnt[cur], c);
    }
}

// ---------------- fragment MLP head: 256 rows/CTA, 512 threads ----------------
__global__ __launch_bounds__(512, 1) void frag_mlp_kernel(
    const int* __restrict__ ind_maps, const int* __restrict__ broken,
    const float* __restrict__ W_m1, const float* __restrict__ b_m1,
    const float* __restrict__ b_m2, const float* __restrict__ b_out,
    const float* __restrict__ b_attn, float* __restrict__ out) {
    extern __shared__ __align__(16) u16 sm16[];
    u16* A = sm16;
    u16* W = A + A16;
    __shared__ int sInd[AROWS]; __shared__ float sInv[AROWS]; __shared__ int sBk[AROWS];
    __shared__ float sB1[128], sB2[128], sBo[26];
    __shared__ float sOne[13 * 132];

    int tid = threadIdx.x, lane = tid & 31, w = tid >> 5;
    int mrow0 = (w >> 2) * 64, ncol0 = (w & 3) * 32;
    int base = blockIdx.x * AROWS;
    u32 wAdr = smem_u32(W);

    for (int i = tid; i < IMGV4; i += 512) cpa16(wAdr + i * 16, (const uint4*)(g_imgs + 3 * IMG16) + i);
    CPA_COMMIT();

    if (tid < AROWS) {
        int f = base + tid;
        sInd[tid] = (f < NF) ? ind_maps[f] : 0;
        sInv[tid] = (f < NF) ? 1.f / fmaxf(g_cnt[f], 1.f) : 0.f;
        int b = (f < NF) ? broken[f] : 0;
        sBk[tid] = min(max(b, 0), 12);
    }
    if (tid < 128) { sB1[tid] = b_m1[tid]; sB2[tid] = b_m2[tid]; }
    if (tid < 26) sBo[tid] = (tid < 13) ? b_out[tid] : b_attn[tid - 13];
    for (int i = tid; i < 13 * 128; i += 512) {
        int rr = i >> 7, c = i & 127;
        sOne[rr * 132 + c] = W_m1[(size_t)(384 + rr) * H + c];
    }
    __syncthreads();

    // stage ext-root rows (hi 0..127, lo 128..255)
    for (int idx = tid; idx < AROWS * 64; idx += 512) {
        int m = idx >> 6, k = (idx & 63) * 2;
        float2 v = *(const float2*)(g_root_emb + (size_t)sInd[m] * H + k);
        u32 hp, lp; split_pair(v.x, v.y, hp, lp);
        *(u32*)(A + m * KPAD + k) = hp;
        *(u32*)(A + m * KPAD + 128 + k) = lp;
    }
    CPA_WAIT0(); __syncthreads();

    u32 aBase = smem_u32(A) + ((mrow0 + (lane & 15)) * KPAD + ((lane >> 4) << 3)) * 2;
    u32 bBase = smem_u32(W) + ((ncol0 + (lane & 7) + ((lane >> 4) << 3)) * KPAD + (((lane >> 3) & 1) << 3)) * 2;

    float acc[4][4][4];
    acc_zero(acc);

    // L1 part 1: ext @ Wa
    mma_block(acc, aBase, bBase, 128);
    __syncthreads();

    // restage A = mean rows; load Wb
    for (int i = tid; i < IMGV4; i += 512) cpa16(wAdr + i * 16, (const uint4*)(g_imgs + 4 * IMG16) + i);
    CPA_COMMIT();
    for (int idx = tid; idx < AROWS * 64; idx += 512) {
        int m = idx >> 6, k = (idx & 63) * 2;
        int f = base + m;
        float2 v = make_float2(0.f, 0.f);
        if (f < NF) {
            v = *(const float2*)(g_frag_sum + (size_t)f * H + k);
            v.x *= sInv[m]; v.y *= sInv[m];
        }
        u32 hp, lp; split_pair(v.x, v.y, hp, lp);
        *(u32*)(A + m * KPAD + k) = hp;
        *(u32*)(A + m * KPAD + 128 + k) = lp;
    }
    CPA_WAIT0(); __syncthreads();

    // L1 part 2: += mean @ Wb
    mma_block(acc, aBase, bBase, 128);
    __syncthreads();

    // epilogue L1 (bias + one-hot + relu) -> A; load Wm2
    for (int i = tid; i < IMGV4; i += 512) cpa16(wAdr + i * 16, (const uint4*)(g_imgs + 5 * IMG16) + i);
    CPA_COMMIT();
    epi_store(A, acc, sB1, sOne, sBk, true, mrow0, ncol0, lane);
    CPA_WAIT0(); __syncthreads();

    // L2
    acc_zero(acc);
    mma_block(acc, aBase, bBase, 128);
    __syncthreads();
    for (int i = tid; i < IMGV4; i += 512) cpa16(wAdr + i * 16, (const uint4*)(g_imgs + 6 * IMG16) + i);
    CPA_COMMIT();
    epi_store(A, acc, sB2, (const float*)0, (const int*)0, true, mrow0, ncol0, lane);
    CPA_WAIT0(); __syncthreads();

    // output layer: cols 0..25 — only warps with ncol0==0 compute (their bBase covers cols 0..31)
    if ((w & 3) == 0) {
        acc_zero(acc);
        mma_block(acc, aBase, bBase, 128);
        int gr = lane >> 2, q2 = (lane & 3) * 2;
#pragma unroll
        for (int mt = 0; mt < 4; mt++) {
            int r0 = mrow0 + mt * 16 + gr, r1 = r0 + 8;
            int fA = base + r0, fB = base + r1;
#pragma unroll
            for (int nt = 0; nt < 4; nt++) {
#pragma unroll
                for (int e = 0; e < 2; e++) {
                    int c = nt * 8 + q2 + e;
                    if (c >= 26) continue;
                    if (fA < NF) {
                        float v = acc[mt][nt][e] + sBo[c];
                        if (c < 13) out[(size_t)fA * 13 + c] = 1.f / (1.f + __expf(-v));
                        else        out[(size_t)NF * 13 + (size_t)fA * 13 + (c - 13)] = v;
                    }
                    if (fB < NF) {
                        float v = acc[mt][nt][2 + e] + sBo[c];
                        if (c < 13) out[(size_t)fB * 13 + c] = 1.f / (1.f + __expf(-v));
                        else        out[(size_t)NF * 13 + (size_t)fB * 13 + (c - 13)] = v;
                    }
                }
            }
        }
    }
}

// ---------------- launcher ----------------
extern "C" void kernel_launch(void* const* d_in, const int* in_sizes, int n_in,
                              void* d_out, int out_size) {
    const float* node_h    = (const float*)d_in[0];
    const int*   seg       = (const int*)d_in[1];
    const float* root_repr = (const float*)d_in[2];
    const int*   ind_maps  = (const int*)d_in[3];
    const int*   broken    = (const int*)d_in[4];
    const float* W_root = (const float*)d_in[5];  const float* b_root = (const float*)d_in[6];
    const float* W_in   = (const float*)d_in[7];  const float* b_in   = (const float*)d_in[8];
    const float* W_g1   = (const float*)d_in[9];  const float* b_g1   = (const float*)d_in[10];
    const float* W_g2   = (const float*)d_in[11]; const float* b_g2   = (const float*)d_in[12];
    const float* W_m1   = (const float*)d_in[13]; const float* b_m1   = (const float*)d_in[14];
    const float* W_m2   = (const float*)d_in[15]; const float* b_m2   = (const float*)d_in[16];
    const float* W_out  = (const float*)d_in[17]; const float* b_out  = (const float*)d_in[18];
    const float* W_attn = (const float*)d_in[19]; const float* b_attn = (const float*)d_in[20];
    float* out = (float*)d_out;

    void* p = 0;
    cudaGetSymbolAddress(&p, g_frag_sum);
    cudaMemsetAsync(p, 0, (size_t)NF * H * sizeof(float), 0);
    cudaGetSymbolAddress(&p, g_cnt);
    cudaMemsetAsync(p, 0, (size_t)NF * sizeof(float), 0);
    cudaGetSymbolAddress(&p, g_imgs);
    cudaMemsetAsync(p, 0, (size_t)7 * IMG16 * sizeof(u16), 0);

    cudaFuncSetAttribute(node_chain_kernel, cudaFuncAttributeMaxDynamicSharedMemorySize, DYN_SMEM);
    cudaFuncSetAttribute(frag_mlp_kernel,   cudaFuncAttributeMaxDynamicSharedMemorySize, DYN_SMEM);

    prep_kernel<<<(7 * 16384 + 255) / 256, 256>>>(W_in, W_g1, W_g2, W_m1, W_m2, W_out, W_attn);
    root_enc_kernel<<<NR, 128>>>(root_repr, W_root, b_root);
    node_chain_kernel<<<NN / AROWS, 512, DYN_SMEM>>>(node_h, seg, b_in, b_g1, b_g2);
    frag_mlp_kernel<<<(NF + AROWS - 1) / AROWS, 512, DYN_SMEM>>>(ind_maps, broken, W_m1, b_m1,
                                                                 b_m2, b_out, b_attn, out);
}

// round 7
// speedup vs baseline: 2.2247x; 1.1780x over previous
#include <cuda_runtime.h>
#include <cuda_bf16.h>

typedef unsigned int u32; typedef unsigned short u16;

#define NN   800000
#define NF   100000
#define NR   2000
#define FEAT 86
#define H    128

#define SLOT_B   32768           // one W half-image (128 n-rows x 128 k u16, swizzled)
#define A_NODE_B 131072          // 256 rows x 512 B
#define A_FRAG_B 65536           // 128 rows x 512 B
#define NODE_DYN (A_NODE_B + 3 * SLOT_B)   // 229376
#define FRAG_DYN (A_FRAG_B + 3 * SLOT_B)   // 163840
#define PSTR 132                 // pool stride (floats)

// ---------------- device scratch ----------------
__device__ __align__(16) u16   g_imgs[7 * 32768];   // per layer: [hi 16384 u16][lo 16384 u16], pre-swizzled
__device__ __align__(16) float g_root_emb[NR * H];
__device__ __align__(16) float g_frag_sum[(size_t)NF * H];
__device__ float g_cnt[NF];

// ---------------- helpers ----------------
__device__ __forceinline__ u32 smem_u32(const void* p) {
    u32 a; asm("{ .reg .u64 t; cvta.to.shared.u64 t, %1; cvt.u32.u64 %0, t; }" : "=r"(a) : "l"(p));
    return a;
}
__device__ __forceinline__ void cpa16(u32 dst, const void* src) {
    asm volatile("cp.async.ca.shared.global [%0], [%1], 16;" :: "r"(dst), "l"(src));
}
#define CPA_COMMIT() asm volatile("cp.async.commit_group;" ::: "memory")
#define CPA_WAIT0()  asm volatile("cp.async.wait_group 0;" ::: "memory")

#define LDSM4(d0, d1, d2, d3, a) \
    asm volatile("ldmatrix.sync.aligned.m8n8.x4.shared.b16 {%0,%1,%2,%3}, [%4];" \
                 : "=r"(d0), "=r"(d1), "=r"(d2), "=r"(d3) : "r"(a))

__device__ __forceinline__ u32 pack_bf2(float lo, float hi) {
    u32 r; asm("cvt.rn.bf16x2.f32 %0, %1, %2;" : "=r"(r) : "f"(hi), "f"(lo)); return r;
}
__device__ __forceinline__ void split_pair(float v0, float v1, u32& hp, u32& lp) {
    hp = pack_bf2(v0, v1);
    float r0 = v0 - __uint_as_float(hp << 16);
    float r1 = v1 - __uint_as_float(hp & 0xFFFF0000u);
    lp = pack_bf2(r0, r1);
}
__device__ __forceinline__ void mma16816(float* c, u32 a0, u32 a1, u32 a2, u32 a3, u32 b0, u32 b1) {
    asm volatile("mma.sync.aligned.m16n8k16.row.col.f32.bf16.bf16.f32 "
                 "{%0,%1,%2,%3}, {%4,%5,%6,%7}, {%8,%9}, {%0,%1,%2,%3};"
                 : "+f"(c[0]), "+f"(c[1]), "+f"(c[2]), "+f"(c[3])
                 : "r"(a0), "r"(a1), "r"(a2), "r"(a3), "r"(b0), "r"(b1));
}

// swizzled byte offset inside an activation row (512B/row) or W row (256B/row):
// chunk16 index ^ (row & 7). A-lo region = hi addr + 256 bytes (chunk +16).
__device__ __forceinline__ int a_off(int r, int c) {       // c = u16 col 0..127 (hi)
    return r * 512 + (((c >> 3) ^ (r & 7)) << 4) + (c & 7) * 2;
}

// ---------------- fully-unrolled GEMM pass ----------------
// warp tile: 64 rows x (NB*16) cols. NB=2 -> acc[4][4][4] (node), NB=1 -> acc[4][2][4] (frag).
template<int NB, int NK>
__device__ __forceinline__ void mma_pass(float (&acc)[4][2 * NB][4],
                                         u32 aRow0, int aXor, int aCS,   // aCS = aCbase + aSel
                                         u32 wRow0, int wXor, int wSel) {
#pragma unroll
    for (int ks = 0; ks < NK; ks++) {
        u32 a[4][4];
#pragma unroll
        for (int mt = 0; mt < 4; mt++) {
            u32 ad = aRow0 + mt * 8192 + (u32)((((aCS + 2 * ks) ^ aXor) << 4));
            LDSM4(a[mt][0], a[mt][1], a[mt][2], a[mt][3], ad);
        }
        u32 b[NB][4];
#pragma unroll
        for (int nb = 0; nb < NB; nb++) {
            u32 bd = wRow0 + nb * 4096 + (u32)((((2 * ks + wSel) ^ wXor) << 4));
            LDSM4(b[nb][0], b[nb][1], b[nb][2], b[nb][3], bd);
        }
#pragma unroll
        for (int mt = 0; mt < 4; mt++)
#pragma unroll
            for (int nb = 0; nb < NB; nb++) {
                mma16816(acc[mt][2 * nb + 0], a[mt][0], a[mt][1], a[mt][2], a[mt][3], b[nb][0], b[nb][1]);
                mma16816(acc[mt][2 * nb + 1], a[mt][0], a[mt][1], a[mt][2], a[mt][3], b[nb][2], b[nb][3]);
            }
    }
}

template<int NTn>
__device__ __forceinline__ void acc_zero(float (&acc)[4][NTn][4]) {
#pragma unroll
    for (int mt = 0; mt < 4; mt++)
#pragma unroll
        for (int nt = 0; nt < NTn; nt++)
#pragma unroll
            for (int e = 0; e < 4; e++) acc[mt][nt][e] = 0.f;
}

// epilogue: acc + bias (+onehot) (+relu) -> split hi/lo into swizzled A
template<int NTn>
__device__ __forceinline__ void epi_store(char* Ab, float (&acc)[4][NTn][4],
                                          const float* __restrict__ bias,
                                          const float* __restrict__ sOne, const int* __restrict__ sBk,
                                          bool relu, int mrow0, int ncol0, int lane) {
    int gr = lane >> 2, q2 = (lane & 3) * 2;
#pragma unroll
    for (int mt = 0; mt < 4; mt++) {
        int r0 = mrow0 + mt * 16 + gr, r1 = r0 + 8;
        const float* oA = sOne ? (sOne + sBk[r0] * 132) : (const float*)0;
        const float* oB = sOne ? (sOne + sBk[r1] * 132) : (const float*)0;
#pragma unroll
        for (int nt = 0; nt < NTn; nt++) {
            int c = ncol0 + nt * 8 + q2;
            float v0 = acc[mt][nt][0] + bias[c], v1 = acc[mt][nt][1] + bias[c + 1];
            float w0 = acc[mt][nt][2] + bias[c], w1 = acc[mt][nt][3] + bias[c + 1];
            if (oA) { v0 += oA[c]; v1 += oA[c + 1]; }
            if (oB) { w0 += oB[c]; w1 += oB[c + 1]; }
            if (relu) { v0 = fmaxf(v0, 0.f); v1 = fmaxf(v1, 0.f); w0 = fmaxf(w0, 0.f); w1 = fmaxf(w1, 0.f); }
            u32 hp, lp;
            int o0 = a_off(r0, c);
            split_pair(v0, v1, hp, lp);
            *(u32*)(Ab + o0) = hp; *(u32*)(Ab + o0 + 256) = lp;
            int o1 = a_off(r1, c);
            split_pair(w0, w1, hp, lp);
            *(u32*)(Ab + o1) = hp; *(u32*)(Ab + o1 + 256) = lp;
        }
    }
}

__device__ __forceinline__ void load_half(u32 slot, const u16* src, int tid, int nthr) {
    const uint4* s = (const uint4*)src;
    for (int i = tid; i < 2048; i += nthr) cpa16(slot + i * 16, s + i);
}

// ---------------- prep: split/transpose weights into swizzled hi/lo images ----------------
__global__ void prep_kernel(const float* __restrict__ W_in, const float* __restrict__ Wg1,
                            const float* __restrict__ Wg2, const float* __restrict__ Wm1,
                            const float* __restrict__ Wm2, const float* __restrict__ Wout,
                            const float* __restrict__ Wattn) {
    int idx = blockIdx.x * 256 + threadIdx.x;
    if (idx >= 7 * 16384) return;
    int img = idx >> 14, r = idx & 16383, n = r >> 7, k = r & 127;
    float w;
    if (img == 0)      { if (k >= FEAT) return; w = W_in[k * H + n]; }
    else if (img == 1) w = Wg1[k * H + n];
    else if (img == 2) w = Wg2[k * H + n];
    else if (img == 3) w = Wm1[k * H + n] + Wm1[(H + k) * H + n];
    else if (img == 4) w = Wm1[(2 * H + k) * H + n] - Wm1[(H + k) * H + n];
    else if (img == 5) w = Wm2[k * H + n];
    else               { if (n >= 26) return;
                         w = (n < 13) ? Wout[k * 13 + n] : Wattn[k * 13 + (n - 13)]; }
    __nv_bfloat16 hb = __float2bfloat16(w);
    __nv_bfloat16 lb = __float2bfloat16(w - __bfloat162float(hb));
    int off = n * 128 + (((k >> 3) ^ (n & 7)) << 3) + (k & 7);   // u16 units, W row = 256B
    u16* base = g_imgs + img * 32768;
    base[off]         = __bfloat16_as_ushort(hb);
    base[off + 16384] = __bfloat16_as_ushort(lb);
}

// ---------------- root encoder ----------------
__global__ void root_enc_kernel(const float* __restrict__ root_repr,
                                const float* __restrict__ W_root,
                                const float* __restrict__ b_root) {
    __shared__ float sX[FEAT];
    int r = blockIdx.x, n = threadIdx.x;
    for (int k = n; k < FEAT; k += 128) sX[k] = root_repr[r * FEAT + k];
    __syncthreads();
    float s = b_root[n];
#pragma unroll 2
    for (int k = 0; k < FEAT; k++) s += sX[k] * W_root[k * H + n];
    g_root_emb[r * H + n] = fmaxf(s, 0.f);
}

// ---------------- node chain: 256 rows/CTA, 512 threads, warp 64x32 ----------------
__global__ __launch_bounds__(512, 1) void node_chain_kernel(
    const float* __restrict__ node_h, const int* __restrict__ seg,
    const float* __restrict__ b_in, const float* __restrict__ b_g1,
    const float* __restrict__ b_g2) {
    extern __shared__ __align__(16) char Ab[];
    __shared__ float sB[3][128];

    int tid = threadIdx.x, lane = tid & 31, w = tid >> 5;
    int mrow0 = (w >> 2) * 64, ncol0 = (w & 3) * 32;
    int tilebase = blockIdx.x * 256;          // NN = 3125 * 256
    u32 smA = smem_u32(Ab);
    u32 S[3] = { smA + A_NODE_B, smA + A_NODE_B + SLOT_B, smA + A_NODE_B + 2 * SLOT_B };

    load_half(S[0], g_imgs, tid, 512);                 // L0 hi
    load_half(S[1], g_imgs + 16384, tid, 512);         // L0 lo
    CPA_COMMIT();

    int segReg = (tid < 256) ? seg[tilebase + tid] : 0;
    if (tid < 128) { sB[0][tid] = b_in[tid]; sB[1][tid] = b_g1[tid]; sB[2][tid] = b_g2[tid]; }

    // zero pad cols 86..95 (hi) / 214..223 (lo)
    for (int i = tid; i < 256 * 5; i += 512) {
        int m = i / 5, k = 86 + (i - 5 * (i / 5)) * 2;
        int o = a_off(m, k);
        *(u32*)(Ab + o) = 0; *(u32*)(Ab + o + 256) = 0;
    }
    // stage node_h: hi col k, lo col 128+k
    for (int idx = tid; idx < 256 * 43; idx += 512) {
        int m = idx / 43, k = (idx - m * 43) * 2;
        float2 v = *(const float2*)(node_h + (size_t)(tilebase + m) * FEAT + k);
        u32 hp, lp; split_pair(v.x, v.y, hp, lp);
        int o = a_off(m, k);
        *(u32*)(Ab + o) = hp; *(u32*)(Ab + o + 256) = lp;
    }
    CPA_WAIT0(); __syncthreads();

    // per-lane fragment addressing
    int rowA = mrow0 + (lane & 15);
    u32 aRow0 = smA + rowA * 512; int aXor = rowA & 7; int aSel = lane >> 4;
    int rowB = ncol0 + (lane & 7) + ((lane >> 4) << 3);
    u32 wRowOff = rowB * 256; int wXor = rowB & 7; int wSel = (lane >> 3) & 1;

    float acc[4][4][4];

    // ---- L0 (K=96) ----
    acc_zero(acc);
    mma_pass<2, 6>(acc, aRow0, aXor, 0 + aSel,  S[0] + wRowOff, wXor, wSel);
    mma_pass<2, 6>(acc, aRow0, aXor, 16 + aSel, S[0] + wRowOff, wXor, wSel);
    load_half(S[2], g_imgs + 32768, tid, 512); CPA_COMMIT();          // L1 hi
    mma_pass<2, 6>(acc, aRow0, aXor, 0 + aSel,  S[1] + wRowOff, wXor, wSel);
    __syncthreads();
    load_half(S[0], g_imgs + 32768 + 16384, tid, 512); CPA_COMMIT();  // L1 lo
    epi_store(Ab, acc, sB[0], (const float*)0, (const int*)0, false, mrow0, ncol0, lane);
    CPA_WAIT0(); __syncthreads();

    // ---- L1 ----   hi=S2 lo=S0 free=S1
    acc_zero(acc);
    mma_pass<2, 8>(acc, aRow0, aXor, 0 + aSel,  S[2] + wRowOff, wXor, wSel);
    mma_pass<2, 8>(acc, aRow0, aXor, 16 + aSel, S[2] + wRowOff, wXor, wSel);
    load_half(S[1], g_imgs + 2 * 32768, tid, 512); CPA_COMMIT();      // L2 hi
    mma_pass<2, 8>(acc, aRow0, aXor, 0 + aSel,  S[0] + wRowOff, wXor, wSel);
    __syncthreads();
    load_half(S[2], g_imgs + 2 * 32768 + 16384, tid, 512); CPA_COMMIT();  // L2 lo
    epi_store(Ab, acc, sB[1], (const float*)0, (const int*)0, true, mrow0, ncol0, lane);
    CPA_WAIT0(); __syncthreads();

    // ---- L2 ----   hi=S1 lo=S2
    acc_zero(acc);
    mma_pass<2, 8>(acc, aRow0, aXor, 0 + aSel,  S[1] + wRowOff, wXor, wSel);
    mma_pass<2, 8>(acc, aRow0, aXor, 16 + aSel, S[1] + wRowOff, wXor, wSel);
    mma_pass<2, 8>(acc, aRow0, aXor, 0 + aSel,  S[2] + wRowOff, wXor, wSel);
    __syncthreads();

    // pool epilogue: fp32 relu(acc + b_g2) into pool (overlays A, stride PSTR)
    {
        float* pool = (float*)Ab;
        int gr = lane >> 2, q2 = (lane & 3) * 2;
#pragma unroll
        for (int mt = 0; mt < 4; mt++) {
            int r0 = mrow0 + mt * 16 + gr, r1 = r0 + 8;
#pragma unroll
            for (int nt = 0; nt < 4; nt++) {
                int c = ncol0 + nt * 8 + q2;
                *(float2*)(pool + r0 * PSTR + c) =
                    make_float2(fmaxf(acc[mt][nt][0] + sB[2][c], 0.f),
                                fmaxf(acc[mt][nt][1] + sB[2][c + 1], 0.f));
                *(float2*)(pool + r1 * PSTR + c) =
                    make_float2(fmaxf(acc[mt][nt][2] + sB[2][c], 0.f),
                                fmaxf(acc[mt][nt][3] + sB[2][c + 1], 0.f));
            }
        }
    }
    int* sSeg = (int*)(Ab + 256 * PSTR * 4);   // 135168, inside slot area (done)
    if (tid < 256) sSeg[tid] = segReg;
    __syncthreads();

    // sorted-segment run-length pooling
    const float* pool = (const float*)Ab;
    if (tid < 128) {
        int n = tid;
        float r = 0.f; int cur = sSeg[0];
        for (int m = 0; m < 256; m++) {
            int s = sSeg[m];
            if (s != cur) { atomicAdd(&g_frag_sum[(size_t)cur * H + n], r); r = 0.f; cur = s; }
            r += pool[m * PSTR + n];
        }
        atomicAdd(&g_frag_sum[(size_t)cur * H + n], r);
    } else if (tid == 128) {
        float c = 0.f; int cur = sSeg[0];
        for (int m = 0; m < 256; m++) {
            int s = sSeg[m];
            if (s != cur) { atomicAdd(&g_cnt[cur], c); c = 0.f; cur = s; }
            c += 1.f;
        }
        atomicAdd(&g_cnt[cur], c);
    }
}

// ---------------- fragment head: 128 rows/CTA, 512 threads, warp 64x16 ----------------
__global__ __launch_bounds__(512, 1) void frag_mlp_kernel(
    const int* __restrict__ ind_maps, const int* __restrict__ broken,
    const float* __restrict__ W_m1, const float* __restrict__ b_m1,
    const float* __restrict__ b_m2, const float* __restrict__ b_out,
    const float* __restrict__ b_attn, float* __restrict__ out) {
    extern __shared__ __align__(16) char Ab[];
    __shared__ int sInd[128]; __shared__ float sInv[128]; __shared__ int sBk[128];
    __shared__ float sB1[128], sB2[128], sBo[26];
    __shared__ float sOne[13 * 132];

    int tid = threadIdx.x, lane = tid & 31, w = tid >> 5;
    int mrow0 = (w >> 3) * 64, ncol0 = (w & 7) * 16;
    int base = blockIdx.x * 128;
    u32 smA = smem_u32(Ab);
    u32 S[3] = { smA + A_FRAG_B, smA + A_FRAG_B + SLOT_B, smA + A_FRAG_B + 2 * SLOT_B };

    load_half(S[0], g_imgs + 3 * 32768, tid, 512);             // Wa hi
    load_half(S[1], g_imgs + 3 * 32768 + 16384, tid, 512);     // Wa lo
    CPA_COMMIT();

    if (tid < 128) {
        int f = base + tid;
        sInd[tid] = (f < NF) ? ind_maps[f] : 0;
        sInv[tid] = (f < NF) ? 1.f / fmaxf(g_cnt[f], 1.f) : 0.f;
        int b = (f < NF) ? broken[f] : 0;
        sBk[tid] = min(max(b, 0), 12);
        sB1[tid] = b_m1[tid]; sB2[tid] = b_m2[tid];
    }
    if (tid < 26) sBo[tid] = (tid < 13) ? b_out[tid] : b_attn[tid - 13];
    for (int i = tid; i < 13 * 128; i += 512) {
        int rr = i >> 7, c = i & 127;
        sOne[rr * 132 + c] = W_m1[(size_t)(384 + rr) * H + c];
    }
    __syncthreads();

    // stage ext-root rows
    for (int idx = tid; idx < 128 * 64; idx += 512) {
        int m = idx >> 6, k = (idx & 63) * 2;
        float2 v = *(const float2*)(g_root_emb + (size_t)sInd[m] * H + k);
        u32 hp, lp; split_pair(v.x, v.y, hp, lp);
        int o = a_off(m, k);
        *(u32*)(Ab + o) = hp; *(u32*)(Ab + o + 256) = lp;
    }
    CPA_WAIT0(); __syncthreads();

    int rowA = mrow0 + (lane & 15);
    u32 aRow0 = smA + rowA * 512; int aXor = rowA & 7; int aSel = lane >> 4;
    int rowB = ncol0 + (lane & 7) + ((lane >> 4) << 3);
    u32 wRowOff = rowB * 256; int wXor = rowB & 7; int wSel = (lane >> 3) & 1;

    float acc[4][2][4];
    acc_zero(acc);

    // ---- L1a: ext @ Wa ----   hi=S0 lo=S1 free=S2
    mma_pass<1, 8>(acc, aRow0, aXor, 0 + aSel,  S[0] + wRowOff, wXor, wSel);
    mma_pass<1, 8>(acc, aRow0, aXor, 16 + aSel, S[0] + wRowOff, wXor, wSel);
    load_half(S[2], g_imgs + 4 * 32768, tid, 512); CPA_COMMIT();           // Wb hi
    mma_pass<1, 8>(acc, aRow0, aXor, 0 + aSel,  S[1] + wRowOff, wXor, wSel);
    __syncthreads();
    load_half(S[0], g_imgs + 4 * 32768 + 16384, tid, 512); CPA_COMMIT();   // Wb lo
    // restage A = mean rows (overlaps Wb lo load)
    for (int idx = tid; idx < 128 * 64; idx += 512) {
        int m = idx >> 6, k = (idx & 63) * 2;
        int f = base + m;
        float2 v = make_float2(0.f, 0.f);
        if (f < NF) {
            v = *(const float2*)(g_frag_sum + (size_t)f * H + k);
            v.x *= sInv[m]; v.y *= sInv[m];
        }
        u32 hp, lp; split_pair(v.x, v.y, hp, lp);
        int o = a_off(m, k);
        *(u32*)(Ab + o) = hp; *(u32*)(Ab + o + 256) = lp;
    }
    CPA_WAIT0(); __syncthreads();

    // ---- L1b: += mean @ Wb ----   hi=S2 lo=S0 free=S1
    mma_pass<1, 8>(acc, aRow0, aXor, 0 + aSel,  S[2] + wRowOff, wXor, wSel);
    mma_pass<1, 8>(acc, aRow0, aXor, 16 + aSel, S[2] + wRowOff, wXor, wSel);
    load_half(S[1], g_imgs + 5 * 32768, tid, 512); CPA_COMMIT();           // Wm2 hi
    mma_pass<1, 8>(acc, aRow0, aXor, 0 + aSel,  S[0] + wRowOff, wXor, wSel);
    __syncthreads();
    load_half(S[2], g_imgs + 5 * 32768 + 16384, tid, 512); CPA_COMMIT();   // Wm2 lo
    epi_store(Ab, acc, sB1, sOne, sBk, true, mrow0, ncol0, lane);
    CPA_WAIT0(); __syncthreads();

    // ---- L2 ----   hi=S1 lo=S2 free=S0
    acc_zero(acc);
    mma_pass<1, 8>(acc, aRow0, aXor, 0 + aSel,  S[1] + wRowOff, wXor, wSel);
    mma_pass<1, 8>(acc, aRow0, aXor, 16 + aSel, S[1] + wRowOff, wXor, wSel);
    load_half(S[0], g_imgs + 6 * 32768, tid, 512); CPA_COMMIT();           // Wout hi
    mma_pass<1, 8>(acc, aRow0, aXor, 0 + aSel,  S[2] + wRowOff, wXor, wSel);
    __syncthreads();
    load_half(S[1], g_imgs + 6 * 32768 + 16384, tid, 512); CPA_COMMIT();   // Wout lo
    epi_store(Ab, acc, sB2, (const float*)0, (const int*)0, true, mrow0, ncol0, lane);
    CPA_WAIT0(); __syncthreads();

    // ---- out layer: cols 0..25 -> n-groups 0,1 only ----   hi=S0 lo=S1
    if ((w & 7) < 2) {
        acc_zero(acc);
        mma_pass<1, 8>(acc, aRow0, aXor, 0 + aSel,  S[0] + wRowOff, wXor, wSel);
        mma_pass<1, 8>(acc, aRow0, aXor, 16 + aSel, S[0] + wRowOff, wXor, wSel);
        mma_pass<1, 8>(acc, aRow0, aXor, 0 + aSel,  S[1] + wRowOff, wXor, wSel);

        int gr = lane >> 2, q2 = (lane & 3) * 2;
#pragma unroll
        for (int mt = 0; mt < 4; mt++) {
            int r0 = mrow0 + mt * 16 + gr, r1 = r0 + 8;
            int fA = base + r0, fB = base + r1;
#pragma unroll
            for (int nt = 0; nt < 2; nt++) {
#pragma unroll
                for (int e = 0; e < 2; e++) {
                    int c = ncol0 + nt * 8 + q2 + e;
                    if (c >= 26) continue;
                    if (fA < NF) {
                        float v = acc[mt][nt][e] + sBo[c];
                        if (c < 13) out[(size_t)fA * 13 + c] = 1.f / (1.f + __expf(-v));
                        else        out[(size_t)NF * 13 + (size_t)fA * 13 + (c - 13)] = v;
                    }
                    if (fB < NF) {
                        float v = acc[mt][nt][2 + e] + sBo[c];
                        if (c < 13) out[(size_t)fB * 13 + c] = 1.f / (1.f + __expf(-v));
                        else        out[(size_t)NF * 13 + (size_t)fB * 13 + (c - 13)] = v;
                    }
                }
            }
        }
    }
}

// ---------------- launcher ----------------
extern "C" void kernel_launch(void* const* d_in, const int* in_sizes, int n_in,
                              void* d_out, int out_size) {
    const float* node_h    = (const float*)d_in[0];
    const int*   seg       = (const int*)d_in[1];
    const float* root_repr = (const float*)d_in[2];
    const int*   ind_maps  = (const int*)d_in[3];
    const int*   broken    = (const int*)d_in[4];
    const float* W_root = (const float*)d_in[5];  const float* b_root = (const float*)d_in[6];
    const float* W_in   = (const float*)d_in[7];  const float* b_in   = (const float*)d_in[8];
    const float* W_g1   = (const float*)d_in[9];  const float* b_g1   = (const float*)d_in[10];
    const float* W_g2   = (const float*)d_in[11]; const float* b_g2   = (const float*)d_in[12];
    const float* W_m1   = (const float*)d_in[13]; const float* b_m1   = (const float*)d_in[14];
    const float* W_m2   = (const float*)d_in[15]; const float* b_m2   = (const float*)d_in[16];
    const float* W_out  = (const float*)d_in[17]; const float* b_out  = (const float*)d_in[18];
    const float* W_attn = (const float*)d_in[19]; const float* b_attn = (const float*)d_in[20];
    float* out = (float*)d_out;

    void* p = 0;
    cudaGetSymbolAddress(&p, g_frag_sum);
    cudaMemsetAsync(p, 0, (size_t)NF * H * sizeof(float), 0);
    cudaGetSymbolAddress(&p, g_cnt);
    cudaMemsetAsync(p, 0, (size_t)NF * sizeof(float), 0);
    cudaGetSymbolAddress(&p, g_imgs);
    cudaMemsetAsync(p, 0, (size_t)7 * 32768 * sizeof(u16), 0);

    cudaFuncSetAttribute(node_chain_kernel, cudaFuncAttributeMaxDynamicSharedMemorySize, NODE_DYN);
    cudaFuncSetAttribute(frag_mlp_kernel,   cudaFuncAttributeMaxDynamicSharedMemorySize, FRAG_DYN);

    prep_kernel<<<(7 * 16384 + 255) / 256, 256>>>(W_in, W_g1, W_g2, W_m1, W_m2, W_out, W_attn);
    root_enc_kernel<<<NR, 128>>>(root_repr, W_root, b_root);
    node_chain_kernel<<<NN / 256, 512, NODE_DYN>>>(node_h, seg, b_in, b_g1, b_g2);
    frag_mlp_kernel<<<(NF + 127) / 128, 512, FRAG_DYN>>>(ind_maps, broken, W_m1, b_m1,
                                                         b_m2, b_out, b_attn, out);
}

// round 8
// speedup vs baseline: 2.9561x; 1.3288x over previous
#include <cuda_runtime.h>
#include <cuda_bf16.h>

typedef unsigned int u32; typedef unsigned short u16;

#define NN   800000
#define NF   100000
#define NR   2000
#define FEAT 86
#define H    128

#define SLOT_B 32768            // one W half-image (128 n-rows x 128 k u16, swizzled)
#define A_B    65536            // 128 rows x 512 B
#define DYN    (A_B + SLOT_B)   // 98304 -> 2 CTAs/SM
#define PSTR   132              // pool stride (floats)

// ---------------- device scratch ----------------
__device__ __align__(16) u16   g_imgs[7 * 32768];   // per image: [hi 16384 u16][lo 16384 u16], pre-swizzled
__device__ __align__(16) float g_root_emb[NR * H];
__device__ __align__(16) float g_frag_sum[(size_t)NF * H];
__device__ float g_cnt[NF];

// ---------------- helpers ----------------
__device__ __forceinline__ u32 smem_u32(const void* p) {
    u32 a; asm("{ .reg .u64 t; cvta.to.shared.u64 t, %1; cvt.u32.u64 %0, t; }" : "=r"(a) : "l"(p));
    return a;
}
__device__ __forceinline__ void cpa16(u32 dst, const void* src) {
    asm volatile("cp.async.ca.shared.global [%0], [%1], 16;" :: "r"(dst), "l"(src));
}
#define CPA_COMMIT() asm volatile("cp.async.commit_group;" ::: "memory")
#define CPA_WAIT0()  asm volatile("cp.async.wait_group 0;" ::: "memory")

#define LDSM4(d0, d1, d2, d3, a) \
    asm volatile("ldmatrix.sync.aligned.m8n8.x4.shared.b16 {%0,%1,%2,%3}, [%4];" \
                 : "=r"(d0), "=r"(d1), "=r"(d2), "=r"(d3) : "r"(a))

__device__ __forceinline__ u32 pack_bf2(float lo, float hi) {
    u32 r; asm("cvt.rn.bf16x2.f32 %0, %1, %2;" : "=r"(r) : "f"(hi), "f"(lo)); return r;
}
__device__ __forceinline__ void split_pair(float v0, float v1, u32& hp, u32& lp) {
    hp = pack_bf2(v0, v1);
    float r0 = v0 - __uint_as_float(hp << 16);
    float r1 = v1 - __uint_as_float(hp & 0xFFFF0000u);
    lp = pack_bf2(r0, r1);
}
__device__ __forceinline__ void mma16816(float* c, u32 a0, u32 a1, u32 a2, u32 a3, u32 b0, u32 b1) {
    asm volatile("mma.sync.aligned.m16n8k16.row.col.f32.bf16.bf16.f32 "
                 "{%0,%1,%2,%3}, {%4,%5,%6,%7}, {%8,%9}, {%0,%1,%2,%3};"
                 : "+f"(c[0]), "+f"(c[1]), "+f"(c[2]), "+f"(c[3])
                 : "r"(a0), "r"(a1), "r"(a2), "r"(a3), "r"(b0), "r"(b1));
}

// swizzled byte offset inside an activation row (512B/row): chunk16 ^ (row & 7); lo = +256B
__device__ __forceinline__ int a_off(int r, int c) {
    return r * 512 + (((c >> 3) ^ (r & 7)) << 4) + (c & 7) * 2;
}

// ---------------- fully-unrolled GEMM pass: warp tile 64 x 32 ----------------
template<int NK>
__device__ __forceinline__ void mma_pass(float (&acc)[4][4][4],
                                         u32 aRow0, int aXor, int aCS,
                                         u32 wRow0, int wXor, int wSel) {
#pragma unroll
    for (int ks = 0; ks < NK; ks++) {
        u32 a[4][4];
#pragma unroll
        for (int mt = 0; mt < 4; mt++) {
            u32 ad = aRow0 + mt * 8192 + (u32)((((aCS + 2 * ks) ^ aXor) << 4));
            LDSM4(a[mt][0], a[mt][1], a[mt][2], a[mt][3], ad);
        }
        u32 b[2][4];
#pragma unroll
        for (int nb = 0; nb < 2; nb++) {
            u32 bd = wRow0 + nb * 4096 + (u32)((((2 * ks + wSel) ^ wXor) << 4));
            LDSM4(b[nb][0], b[nb][1], b[nb][2], b[nb][3], bd);
        }
#pragma unroll
        for (int mt = 0; mt < 4; mt++)
#pragma unroll
            for (int nb = 0; nb < 2; nb++) {
                mma16816(acc[mt][2 * nb + 0], a[mt][0], a[mt][1], a[mt][2], a[mt][3], b[nb][0], b[nb][1]);
                mma16816(acc[mt][2 * nb + 1], a[mt][0], a[mt][1], a[mt][2], a[mt][3], b[nb][2], b[nb][3]);
            }
    }
}
__device__ __forceinline__ void acc_zero(float (&acc)[4][4][4]) {
#pragma unroll
    for (int mt = 0; mt < 4; mt++)
#pragma unroll
        for (int nt = 0; nt < 4; nt++)
#pragma unroll
            for (int e = 0; e < 4; e++) acc[mt][nt][e] = 0.f;
}

// epilogue: acc + bias (+onehot) (+relu) -> split hi/lo into swizzled A
__device__ __forceinline__ void epi_store(char* Ab, float (&acc)[4][4][4],
                                          const float* __restrict__ bias,
                                          const float* __restrict__ sOne, const int* __restrict__ sBk,
                                          bool relu, int mrow0, int ncol0, int lane) {
    int gr = lane >> 2, q2 = (lane & 3) * 2;
#pragma unroll
    for (int mt = 0; mt < 4; mt++) {
        int r0 = mrow0 + mt * 16 + gr, r1 = r0 + 8;
        const float* oA = sOne ? (sOne + sBk[r0] * 132) : (const float*)0;
        const float* oB = sOne ? (sOne + sBk[r1] * 132) : (const float*)0;
#pragma unroll
        for (int nt = 0; nt < 4; nt++) {
            int c = ncol0 + nt * 8 + q2;
            float v0 = acc[mt][nt][0] + bias[c], v1 = acc[mt][nt][1] + bias[c + 1];
            float w0 = acc[mt][nt][2] + bias[c], w1 = acc[mt][nt][3] + bias[c + 1];
            if (oA) { v0 += oA[c]; v1 += oA[c + 1]; }
            if (oB) { w0 += oB[c]; w1 += oB[c + 1]; }
            if (relu) { v0 = fmaxf(v0, 0.f); v1 = fmaxf(v1, 0.f); w0 = fmaxf(w0, 0.f); w1 = fmaxf(w1, 0.f); }
            u32 hp, lp;
            int o0 = a_off(r0, c);
            split_pair(v0, v1, hp, lp);
            *(u32*)(Ab + o0) = hp; *(u32*)(Ab + o0 + 256) = lp;
            int o1 = a_off(r1, c);
            split_pair(w0, w1, hp, lp);
            *(u32*)(Ab + o1) = hp; *(u32*)(Ab + o1 + 256) = lp;
        }
    }
}

__device__ __forceinline__ void load_half(u32 slot, const u16* src, int tid) {
    const uint4* s = (const uint4*)src;
    for (int i = tid; i < 2048; i += 256) cpa16(slot + i * 16, s + i);
}

// ---------------- prep ----------------
__global__ void prep_kernel(const float* __restrict__ W_in, const float* __restrict__ Wg1,
                            const float* __restrict__ Wg2, const float* __restrict__ Wm1,
                            const float* __restrict__ Wm2, const float* __restrict__ Wout,
                            const float* __restrict__ Wattn) {
    int idx = blockIdx.x * 256 + threadIdx.x;
    if (idx >= 7 * 16384) return;
    int img = idx >> 14, r = idx & 16383, n = r >> 7, k = r & 127;
    float w;
    if (img == 0)      { if (k >= FEAT) return; w = W_in[k * H + n]; }
    else if (img == 1) w = Wg1[k * H + n];
    else if (img == 2) w = Wg2[k * H + n];
    else if (img == 3) w = Wm1[k * H + n] + Wm1[(H + k) * H + n];
    else if (img == 4) w = Wm1[(2 * H + k) * H + n] - Wm1[(H + k) * H + n];
    else if (img == 5) w = Wm2[k * H + n];
    else               { if (n >= 26) return;
                         w = (n < 13) ? Wout[k * 13 + n] : Wattn[k * 13 + (n - 13)]; }
    __nv_bfloat16 hb = __float2bfloat16(w);
    __nv_bfloat16 lb = __float2bfloat16(w - __bfloat162float(hb));
    int off = n * 128 + (((k >> 3) ^ (n & 7)) << 3) + (k & 7);
    u16* base = g_imgs + img * 32768;
    base[off]         = __bfloat16_as_ushort(hb);
    base[off + 16384] = __bfloat16_as_ushort(lb);
}

// ---------------- root encoder ----------------
__global__ void root_enc_kernel(const float* __restrict__ root_repr,
                                const float* __restrict__ W_root,
                                const float* __restrict__ b_root) {
    __shared__ float sX[FEAT];
    int r = blockIdx.x, n = threadIdx.x;
    for (int k = n; k < FEAT; k += 128) sX[k] = root_repr[r * FEAT + k];
    __syncthreads();
    float s = b_root[n];
#pragma unroll 2
    for (int k = 0; k < FEAT; k++) s += sX[k] * W_root[k * H + n];
    g_root_emb[r * H + n] = fmaxf(s, 0.f);
}

// ---------------- node chain: 128 rows/CTA, 256 threads, 2 CTAs/SM ----------------
__global__ __launch_bounds__(256, 2) void node_chain_kernel(
    const float* __restrict__ node_h, const int* __restrict__ seg,
    const float* __restrict__ b_in, const float* __restrict__ b_g1,
    const float* __restrict__ b_g2) {
    extern __shared__ __align__(16) char Ab[];
    __shared__ float sB[3][128];
    __shared__ int sSeg[128];

    int tid = threadIdx.x, lane = tid & 31, w = tid >> 5;
    int mrow0 = (w >> 2) * 64, ncol0 = (w & 3) * 32;
    int tilebase = blockIdx.x * 128;          // NN = 6250 * 128
    u32 smA = smem_u32(Ab);
    u32 S = smA + A_B;

    load_half(S, g_imgs, tid);  CPA_COMMIT();                 // L0 hi

    if (tid < 128) { sSeg[tid] = seg[tilebase + tid];
                     sB[0][tid] = b_in[tid]; sB[1][tid] = b_g1[tid]; sB[2][tid] = b_g2[tid]; }

    // zero pad cols 86..95 (hi & lo)
    for (int i = tid; i < 128 * 5; i += 256) {
        int m = i / 5, k = 86 + (i - 5 * (i / 5)) * 2;
        int o = a_off(m, k);
        *(u32*)(Ab + o) = 0; *(u32*)(Ab + o + 256) = 0;
    }
    // stage node_h
    for (int idx = tid; idx < 128 * 43; idx += 256) {
        int m = idx / 43, k = (idx - m * 43) * 2;
        float2 v = *(const float2*)(node_h + (size_t)(tilebase + m) * FEAT + k);
        u32 hp, lp; split_pair(v.x, v.y, hp, lp);
        int o = a_off(m, k);
        *(u32*)(Ab + o) = hp; *(u32*)(Ab + o + 256) = lp;
    }
    CPA_WAIT0(); __syncthreads();

    int rowA = mrow0 + (lane & 15);
    u32 aRow0 = smA + rowA * 512; int aXor = rowA & 7; int aSel = lane >> 4;
    int rowB = ncol0 + (lane & 7) + ((lane >> 4) << 3);
    u32 wR = S + rowB * 256; int wXor = rowB & 7; int wSel = (lane >> 3) & 1;

    float acc[4][4][4];

#define NODE_LAYER(NK, IMG, BIAS, RELU, LAST)                                    \
    acc_zero(acc);                                                               \
    mma_pass<NK>(acc, aRow0, aXor, 0 + aSel,  wR, wXor, wSel);                   \
    mma_pass<NK>(acc, aRow0, aXor, 16 + aSel, wR, wXor, wSel);                   \
    __syncthreads();                                                             \
    load_half(S, g_imgs + (IMG) * 32768 + 16384, tid); CPA_COMMIT(); CPA_WAIT0();\
    __syncthreads();                                                             \
    mma_pass<NK>(acc, aRow0, aXor, 0 + aSel, wR, wXor, wSel);                    \
    __syncthreads();                                                             \
    if (!(LAST)) { load_half(S, g_imgs + ((IMG) + 1) * 32768, tid); CPA_COMMIT(); } \
    epi_store(Ab, acc, BIAS, (const float*)0, (const int*)0, RELU, mrow0, ncol0, lane); \
    if (!(LAST)) { CPA_WAIT0(); }                                                \
    __syncthreads();

    NODE_LAYER(6, 0, sB[0], false, false)
    NODE_LAYER(8, 1, sB[1], true,  false)

    // L2: last layer -> pool epilogue instead of epi_store
    acc_zero(acc);
    mma_pass<8>(acc, aRow0, aXor, 0 + aSel,  wR, wXor, wSel);
    mma_pass<8>(acc, aRow0, aXor, 16 + aSel, wR, wXor, wSel);
    __syncthreads();
    load_half(S, g_imgs + 2 * 32768 + 16384, tid); CPA_COMMIT(); CPA_WAIT0();
    __syncthreads();
    mma_pass<8>(acc, aRow0, aXor, 0 + aSel, wR, wXor, wSel);
    __syncthreads();
    {
        float* pool = (float*)Ab;     // 128*132*4 = 67584 B, spills into W slot (done)
        int gr = lane >> 2, q2 = (lane & 3) * 2;
#pragma unroll
        for (int mt = 0; mt < 4; mt++) {
            int r0 = mrow0 + mt * 16 + gr, r1 = r0 + 8;
#pragma unroll
            for (int nt = 0; nt < 4; nt++) {
                int c = ncol0 + nt * 8 + q2;
                *(float2*)(pool + r0 * PSTR + c) =
                    make_float2(fmaxf(acc[mt][nt][0] + sB[2][c], 0.f),
                                fmaxf(acc[mt][nt][1] + sB[2][c + 1], 0.f));
                *(float2*)(pool + r1 * PSTR + c) =
                    make_float2(fmaxf(acc[mt][nt][2] + sB[2][c], 0.f),
                                fmaxf(acc[mt][nt][3] + sB[2][c + 1], 0.f));
            }
        }
    }
    __syncthreads();

    const float* pool = (const float*)Ab;
    if (tid < 128) {
        int n = tid;
        float r = 0.f; int cur = sSeg[0];
        for (int m = 0; m < 128; m++) {
            int s = sSeg[m];
            if (s != cur) { atomicAdd(&g_frag_sum[(size_t)cur * H + n], r); r = 0.f; cur = s; }
            r += pool[m * PSTR + n];
        }
        atomicAdd(&g_frag_sum[(size_t)cur * H + n], r);
    } else if (tid == 128) {
        float c = 0.f; int cur = sSeg[0];
        for (int m = 0; m < 128; m++) {
            int s = sSeg[m];
            if (s != cur) { atomicAdd(&g_cnt[cur], c); c = 0.f; cur = s; }
            c += 1.f;
        }
        atomicAdd(&g_cnt[cur], c);
    }
}

// ---------------- fragment head: 128 rows/CTA, 256 threads, 2 CTAs/SM ----------------
__global__ __launch_bounds__(256, 2) void frag_mlp_kernel(
    const int* __restrict__ ind_maps, const int* __restrict__ broken,
    const float* __restrict__ W_m1, const float* __restrict__ b_m1,
    const float* __restrict__ b_m2, const float* __restrict__ b_out,
    const float* __restrict__ b_attn, float* __restrict__ out) {
    extern __shared__ __align__(16) char Ab[];
    __shared__ int sInd[128]; __shared__ float sInv[128]; __shared__ int sBk[128];
    __shared__ float sB1[128], sB2[128], sBo[26];
    __shared__ float sOne[13 * 132];

    int tid = threadIdx.x, lane = tid & 31, w = tid >> 5;
    int mrow0 = (w >> 2) * 64, ncol0 = (w & 3) * 32;
    int base = blockIdx.x * 128;
    u32 smA = smem_u32(Ab);
    u32 S = smA + A_B;

    load_half(S, g_imgs + 3 * 32768, tid); CPA_COMMIT();         // Wa hi

    if (tid < 128) {
        int f = base + tid;
        sInd[tid] = (f < NF) ? ind_maps[f] : 0;
        sInv[tid] = (f < NF) ? 1.f / fmaxf(g_cnt[f], 1.f) : 0.f;
        int b = (f < NF) ? broken[f] : 0;
        sBk[tid] = min(max(b, 0), 12);
        sB1[tid] = b_m1[tid]; sB2[tid] = b_m2[tid];
    }
    if (tid < 26) sBo[tid] = (tid < 13) ? b_out[tid] : b_attn[tid - 13];
    for (int i = tid; i < 13 * 128; i += 256) {
        int rr = i >> 7, c = i & 127;
        sOne[rr * 132 + c] = W_m1[(size_t)(384 + rr) * H + c];
    }

    // stage ext-root rows
    for (int idx = tid; idx < 128 * 64; idx += 256) {
        int m = idx >> 6, k = (idx & 63) * 2;
        int f = base + m;
        int ind = (f < NF) ? ind_maps[f] : 0;
        float2 v = *(const float2*)(g_root_emb + (size_t)ind * H + k);
        u32 hp, lp; split_pair(v.x, v.y, hp, lp);
        int o = a_off(m, k);
        *(u32*)(Ab + o) = hp; *(u32*)(Ab + o + 256) = lp;
    }
    CPA_WAIT0(); __syncthreads();

    int rowA = mrow0 + (lane & 15);
    u32 aRow0 = smA + rowA * 512; int aXor = rowA & 7; int aSel = lane >> 4;
    int rowB = ncol0 + (lane & 7) + ((lane >> 4) << 3);
    u32 wR = S + rowB * 256; int wXor = rowB & 7; int wSel = (lane >> 3) & 1;

    float acc[4][4][4];
    acc_zero(acc);

    // ---- L1a: ext @ Wa ----
    mma_pass<8>(acc, aRow0, aXor, 0 + aSel,  wR, wXor, wSel);
    mma_pass<8>(acc, aRow0, aXor, 16 + aSel, wR, wXor, wSel);
    __syncthreads();
    load_half(S, g_imgs + 3 * 32768 + 16384, tid); CPA_COMMIT(); CPA_WAIT0();   // Wa lo
    __syncthreads();
    mma_pass<8>(acc, aRow0, aXor, 0 + aSel, wR, wXor, wSel);
    __syncthreads();
    // restage A = mean rows; load Wb hi
    load_half(S, g_imgs + 4 * 32768, tid); CPA_COMMIT();
    for (int idx = tid; idx < 128 * 64; idx += 256) {
        int m = idx >> 6, k = (idx & 63) * 2;
        int f = base + m;
        float2 v = make_float2(0.f, 0.f);
        if (f < NF) {
            v = *(const float2*)(g_frag_sum + (size_t)f * H + k);
            v.x *= sInv[m]; v.y *= sInv[m];
        }
        u32 hp, lp; split_pair(v.x, v.y, hp, lp);
        int o = a_off(m, k);
        *(u32*)(Ab + o) = hp; *(u32*)(Ab + o + 256) = lp;
    }
    CPA_WAIT0(); __syncthreads();

    // ---- L1b: += mean @ Wb ----
    mma_pass<8>(acc, aRow0, aXor, 0 + aSel,  wR, wXor, wSel);
    mma_pass<8>(acc, aRow0, aXor, 16 + aSel, wR, wXor, wSel);
    __syncthreads();
    load_half(S, g_imgs + 4 * 32768 + 16384, tid); CPA_COMMIT(); CPA_WAIT0();   // Wb lo
    __syncthreads();
    mma_pass<8>(acc, aRow0, aXor, 0 + aSel, wR, wXor, wSel);
    __syncthreads();
    load_half(S, g_imgs + 5 * 32768, tid); CPA_COMMIT();                        // Wm2 hi
    epi_store(Ab, acc, sB1, sOne, sBk, true, mrow0, ncol0, lane);
    CPA_WAIT0(); __syncthreads();

    // ---- L2 ----
    acc_zero(acc);
    mma_pass<8>(acc, aRow0, aXor, 0 + aSel,  wR, wXor, wSel);
    mma_pass<8>(acc, aRow0, aXor, 16 + aSel, wR, wXor, wSel);
    __syncthreads();
    load_half(S, g_imgs + 5 * 32768 + 16384, tid); CPA_COMMIT(); CPA_WAIT0();   // Wm2 lo
    __syncthreads();
    mma_pass<8>(acc, aRow0, aXor, 0 + aSel, wR, wXor, wSel);
    __syncthreads();
    load_half(S, g_imgs + 6 * 32768, tid); CPA_COMMIT();                        // Wout hi
    epi_store(Ab, acc, sB2, (const float*)0, (const int*)0, true, mrow0, ncol0, lane);
    CPA_WAIT0(); __syncthreads();

    // ---- out layer: cols 0..25 (warps with ncol0==0 only compute) ----
    bool active = (ncol0 == 0);
    acc_zero(acc);
    if (active) {
        mma_pass<8>(acc, aRow0, aXor, 0 + aSel,  wR, wXor, wSel);
        mma_pass<8>(acc, aRow0, aXor, 16 + aSel, wR, wXor, wSel);
    }
    __syncthreads();
    load_half(S, g_imgs + 6 * 32768 + 16384, tid); CPA_COMMIT(); CPA_WAIT0();   // Wout lo
    __syncthreads();
    if (active) {
        mma_pass<8>(acc, aRow0, aXor, 0 + aSel, wR, wXor, wSel);
        int gr = lane >> 2, q2 = (lane & 3) * 2;
#pragma unroll
        for (int mt = 0; mt < 4; mt++) {
            int r0 = mrow0 + mt * 16 + gr, r1 = r0 + 8;
            int fA = base + r0, fB = base + r1;
#pragma unroll
            for (int nt = 0; nt < 4; nt++) {
#pragma unroll
                for (int e = 0; e < 2; e++) {
                    int c = nt * 8 + q2 + e;
                    if (c >= 26) continue;
                    if (fA < NF) {
                        float v = acc[mt][nt][e] + sBo[c];
                        if (c < 13) out[(size_t)fA * 13 + c] = 1.f / (1.f + __expf(-v));
                        else        out[(size_t)NF * 13 + (size_t)fA * 13 + (c - 13)] = v;
                    }
                    if (fB < NF) {
                        float v = acc[mt][nt][2 + e] + sBo[c];
                        if (c < 13) out[(size_t)fB * 13 + c] = 1.f / (1.f + __expf(-v));
                        else        out[(size_t)NF * 13 + (size_t)fB * 13 + (c - 13)] = v;
                    }
                }
            }
        }
    }
}

// ---------------- launcher ----------------
extern "C" void kernel_launch(void* const* d_in, const int* in_sizes, int n_in,
                              void* d_out, int out_size) {
    const float* node_h    = (const float*)d_in[0];
    const int*   seg       = (const int*)d_in[1];
    const float* root_repr = (const float*)d_in[2];
    const int*   ind_maps  = (const int*)d_in[3];
    const int*   broken    = (const int*)d_in[4];
    const float* W_root = (const float*)d_in[5];  const float* b_root = (const float*)d_in[6];
    const float* W_in   = (const float*)d_in[7];  const float* b_in   = (const float*)d_in[8];
    const float* W_g1   = (const float*)d_in[9];  const float* b_g1   = (const float*)d_in[10];
    const float* W_g2   = (const float*)d_in[11]; const float* b_g2   = (const float*)d_in[12];
    const float* W_m1   = (const float*)d_in[13]; const float* b_m1   = (const float*)d_in[14];
    const float* W_m2   = (const float*)d_in[15]; const float* b_m2   = (const float*)d_in[16];
    const float* W_out  = (const float*)d_in[17]; const float* b_out  = (const float*)d_in[18];
    const float* W_attn = (const float*)d_in[19]; const float* b_attn = (const float*)d_in[20];
    float* out = (float*)d_out;

    void* p = 0;
    cudaGetSymbolAddress(&p, g_frag_sum);
    cudaMemsetAsync(p, 0, (size_t)NF * H * sizeof(float), 0);
    cudaGetSymbolAddress(&p, g_cnt);
    cudaMemsetAsync(p, 0, (size_t)NF * sizeof(float), 0);
    cudaGetSymbolAddress(&p, g_imgs);
    cudaMemsetAsync(p, 0, (size_t)7 * 32768 * sizeof(u16), 0);

    cudaFuncSetAttribute(node_chain_kernel, cudaFuncAttributeMaxDynamicSharedMemorySize, DYN);
    cudaFuncSetAttribute(frag_mlp_kernel,   cudaFuncAttributeMaxDynamicSharedMemorySize, DYN);

    prep_kernel<<<(7 * 16384 + 255) / 256, 256>>>(W_in, W_g1, W_g2, W_m1, W_m2, W_out, W_attn);
    root_enc_kernel<<<NR, 128>>>(root_repr, W_root, b_root);
    node_chain_kernel<<<NN / 128, 256, DYN>>>(node_h, seg, b_in, b_g1, b_g2);
    frag_mlp_kernel<<<(NF + 127) / 128, 256, DYN>>>(ind_maps, broken, W_m1, b_m1,
                                                    b_m2, b_out, b_attn, out);
}

// round 9
// speedup vs baseline: 3.6875x; 1.2474x over previous
#include <cuda_runtime.h>
#include <cuda_fp16.h>

typedef unsigned int u32; typedef unsigned short u16;

#define NN   800000
#define NF   100000
#define NR   2000
#define FEAT 86
#define H    128

#define SLOT_B 32768            // one W half-image (128 n-rows x 128 k u16, swizzled)
#define A_B    65536            // 128 rows x 512 B
#define DYN    (A_B + SLOT_B)   // 98304 -> 2 CTAs/SM
#define PSTR   132              // pool stride (floats)

// ---------------- device scratch ----------------
__device__ __align__(16) u16   g_imgs[7 * 32768];   // per image: [hi 16384 u16][lo 16384 u16], fp16, pre-swizzled
__device__ __align__(16) float g_root_emb[NR * H];
__device__ __align__(16) float g_frag_sum[(size_t)NF * H];
__device__ float g_cnt[NF];

// ---------------- helpers ----------------
__device__ __forceinline__ u32 smem_u32(const void* p) {
    u32 a; asm("{ .reg .u64 t; cvta.to.shared.u64 t, %1; cvt.u32.u64 %0, t; }" : "=r"(a) : "l"(p));
    return a;
}
__device__ __forceinline__ void cpa16(u32 dst, const void* src) {
    asm volatile("cp.async.ca.shared.global [%0], [%1], 16;" :: "r"(dst), "l"(src));
}
#define CPA_COMMIT() asm volatile("cp.async.commit_group;" ::: "memory")
#define CPA_WAIT0()  asm volatile("cp.async.wait_group 0;" ::: "memory")

#define LDSM4(d0, d1, d2, d3, a) \
    asm volatile("ldmatrix.sync.aligned.m8n8.x4.shared.b16 {%0,%1,%2,%3}, [%4];" \
                 : "=r"(d0), "=r"(d1), "=r"(d2), "=r"(d3) : "r"(a))

// fp16 hi/lo split of a float pair (lo lane = first arg)
__device__ __forceinline__ void split_pair(float v0, float v1, u32& hp, u32& lp) {
    __half2 h = __floats2half2_rn(v0, v1);
    hp = *(u32*)&h;
    float r0 = v0 - __half2float(__low2half(h));
    float r1 = v1 - __half2float(__high2half(h));
    __half2 l = __floats2half2_rn(r0, r1);
    lp = *(u32*)&l;
}
__device__ __forceinline__ void mma16816(float* c, u32 a0, u32 a1, u32 a2, u32 a3, u32 b0, u32 b1) {
    asm volatile("mma.sync.aligned.m16n8k16.row.col.f32.f16.f16.f32 "
                 "{%0,%1,%2,%3}, {%4,%5,%6,%7}, {%8,%9}, {%0,%1,%2,%3};"
                 : "+f"(c[0]), "+f"(c[1]), "+f"(c[2]), "+f"(c[3])
                 : "r"(a0), "r"(a1), "r"(a2), "r"(a3), "r"(b0), "r"(b1));
}

// swizzled byte offset inside an activation row (512B/row): chunk16 ^ (row & 7); lo = +256B
__device__ __forceinline__ int a_off(int r, int c) {
    return r * 512 + (((c >> 3) ^ (r & 7)) << 4) + (c & 7) * 2;
}

// ---------------- fully-unrolled GEMM pass: warp tile 64 x 32 ----------------
template<int NK>
__device__ __forceinline__ void mma_pass(float (&acc)[4][4][4],
                                         u32 aRow0, int aXor, int aCS,
                                         u32 wRow0, int wXor, int wSel) {
#pragma unroll
    for (int ks = 0; ks < NK; ks++) {
        u32 a[4][4];
#pragma unroll
        for (int mt = 0; mt < 4; mt++) {
            u32 ad = aRow0 + mt * 8192 + (u32)((((aCS + 2 * ks) ^ aXor) << 4));
            LDSM4(a[mt][0], a[mt][1], a[mt][2], a[mt][3], ad);
        }
        u32 b[2][4];
#pragma unroll
        for (int nb = 0; nb < 2; nb++) {
            u32 bd = wRow0 + nb * 4096 + (u32)((((2 * ks + wSel) ^ wXor) << 4));
            LDSM4(b[nb][0], b[nb][1], b[nb][2], b[nb][3], bd);
        }
#pragma unroll
        for (int mt = 0; mt < 4; mt++)
#pragma unroll
            for (int nb = 0; nb < 2; nb++) {
                mma16816(acc[mt][2 * nb + 0], a[mt][0], a[mt][1], a[mt][2], a[mt][3], b[nb][0], b[nb][1]);
                mma16816(acc[mt][2 * nb + 1], a[mt][0], a[mt][1], a[mt][2], a[mt][3], b[nb][2], b[nb][3]);
            }
    }
}
__device__ __forceinline__ void acc_zero(float (&acc)[4][4][4]) {
#pragma unroll
    for (int mt = 0; mt < 4; mt++)
#pragma unroll
        for (int nt = 0; nt < 4; nt++)
#pragma unroll
            for (int e = 0; e < 4; e++) acc[mt][nt][e] = 0.f;
}

// epilogue: acc + bias (+onehot) (+relu) -> split hi/lo into swizzled A
__device__ __forceinline__ void epi_store(char* Ab, float (&acc)[4][4][4],
                                          const float* __restrict__ bias,
                                          const float* __restrict__ sOne, const int* __restrict__ sBk,
                                          bool relu, int mrow0, int ncol0, int lane) {
    int gr = lane >> 2, q2 = (lane & 3) * 2;
#pragma unroll
    for (int mt = 0; mt < 4; mt++) {
        int r0 = mrow0 + mt * 16 + gr, r1 = r0 + 8;
        const float* oA = sOne ? (sOne + sBk[r0] * 132) : (const float*)0;
        const float* oB = sOne ? (sOne + sBk[r1] * 132) : (const float*)0;
#pragma unroll
        for (int nt = 0; nt < 4; nt++) {
            int c = ncol0 + nt * 8 + q2;
            float v0 = acc[mt][nt][0] + bias[c], v1 = acc[mt][nt][1] + bias[c + 1];
            float w0 = acc[mt][nt][2] + bias[c], w1 = acc[mt][nt][3] + bias[c + 1];
            if (oA) { v0 += oA[c]; v1 += oA[c + 1]; }
            if (oB) { w0 += oB[c]; w1 += oB[c + 1]; }
            if (relu) { v0 = fmaxf(v0, 0.f); v1 = fmaxf(v1, 0.f); w0 = fmaxf(w0, 0.f); w1 = fmaxf(w1, 0.f); }
            u32 hp, lp;
            int o0 = a_off(r0, c);
            split_pair(v0, v1, hp, lp);
            *(u32*)(Ab + o0) = hp; *(u32*)(Ab + o0 + 256) = lp;
            int o1 = a_off(r1, c);
            split_pair(w0, w1, hp, lp);
            *(u32*)(Ab + o1) = hp; *(u32*)(Ab + o1 + 256) = lp;
        }
    }
}

__device__ __forceinline__ void load_half(u32 slot, const u16* src, int tid) {
    const uint4* s = (const uint4*)src;
    for (int i = tid; i < 2048; i += 256) cpa16(slot + i * 16, s + i);
}

// ---------------- prep: split/transpose weights into fp16 hi/lo images ----------------
__global__ void prep_kernel(const float* __restrict__ W_in, const float* __restrict__ Wg1,
                            const float* __restrict__ Wg2, const float* __restrict__ Wm1,
                            const float* __restrict__ Wm2, const float* __restrict__ Wout,
                            const float* __restrict__ Wattn) {
    int idx = blockIdx.x * 256 + threadIdx.x;
    if (idx >= 7 * 16384) return;
    int img = idx >> 14, r = idx & 16383, n = r >> 7, k = r & 127;
    float w;
    if (img == 0)      { if (k >= FEAT) return; w = W_in[k * H + n]; }
    else if (img == 1) w = Wg1[k * H + n];
    else if (img == 2) w = Wg2[k * H + n];
    else if (img == 3) w = Wm1[k * H + n] + Wm1[(H + k) * H + n];
    else if (img == 4) w = Wm1[(2 * H + k) * H + n] - Wm1[(H + k) * H + n];
    else if (img == 5) w = Wm2[k * H + n];
    else               { if (n >= 26) return;
                         w = (n < 13) ? Wout[k * 13 + n] : Wattn[k * 13 + (n - 13)]; }
    __half hb = __float2half_rn(w);
    __half lb = __float2half_rn(w - __half2float(hb));
    int off = n * 128 + (((k >> 3) ^ (n & 7)) << 3) + (k & 7);
    u16* base = g_imgs + img * 32768;
    base[off]         = __half_as_ushort(hb);
    base[off + 16384] = __half_as_ushort(lb);
}

// ---------------- root encoder ----------------
__global__ void root_enc_kernel(const float* __restrict__ root_repr,
                                const float* __restrict__ W_root,
                                const float* __restrict__ b_root) {
    __shared__ float sX[FEAT];
    int r = blockIdx.x, n = threadIdx.x;
    for (int k = n; k < FEAT; k += 128) sX[k] = root_repr[r * FEAT + k];
    __syncthreads();
    float s = b_root[n];
#pragma unroll 2
    for (int k = 0; k < FEAT; k++) s += sX[k] * W_root[k * H + n];
    g_root_emb[r * H + n] = fmaxf(s, 0.f);
}

// ---------------- node chain: fp16 2-pass, 128 rows/CTA, 2 CTAs/SM ----------------
__global__ __launch_bounds__(256, 2) void node_chain_kernel(
    const float* __restrict__ node_h, const int* __restrict__ seg,
    const float* __restrict__ b_in, const float* __restrict__ b_g1,
    const float* __restrict__ b_g2) {
    extern __shared__ __align__(16) char Ab[];
    __shared__ float sB[3][128];
    __shared__ int sSeg[128];

    int tid = threadIdx.x, lane = tid & 31, w = tid >> 5;
    int mrow0 = (w >> 2) * 64, ncol0 = (w & 3) * 32;
    int tilebase = blockIdx.x * 128;          // NN = 6250 * 128
    u32 smA = smem_u32(Ab);
    u32 S = smA + A_B;

    load_half(S, g_imgs, tid); CPA_COMMIT();           // W0 (fp16 hi image only)

    if (tid < 128) { sSeg[tid] = seg[tilebase + tid];
                     sB[0][tid] = b_in[tid]; sB[1][tid] = b_g1[tid]; sB[2][tid] = b_g2[tid]; }

    // zero pad cols 86..95 (hi & lo)
    for (int i = tid; i < 128 * 5; i += 256) {
        int m = i / 5, k = 86 + (i - 5 * (i / 5)) * 2;
        int o = a_off(m, k);
        *(u32*)(Ab + o) = 0; *(u32*)(Ab + o + 256) = 0;
    }
    // stage node_h split hi/lo
    for (int idx = tid; idx < 128 * 43; idx += 256) {
        int m = idx / 43, k = (idx - m * 43) * 2;
        float2 v = *(const float2*)(node_h + (size_t)(tilebase + m) * FEAT + k);
        u32 hp, lp; split_pair(v.x, v.y, hp, lp);
        int o = a_off(m, k);
        *(u32*)(Ab + o) = hp; *(u32*)(Ab + o + 256) = lp;
    }
    CPA_WAIT0(); __syncthreads();

    int rowA = mrow0 + (lane & 15);
    u32 aRow0 = smA + rowA * 512; int aXor = rowA & 7; int aSel = lane >> 4;
    int rowB = ncol0 + (lane & 7) + ((lane >> 4) << 3);
    u32 wR = S + rowB * 256; int wXor = rowB & 7; int wSel = (lane >> 3) & 1;

    float acc[4][4][4];

    // ---- L0 (K=96): 2 passes (A-hi, A-lo), no relu ----
    acc_zero(acc);
    mma_pass<6>(acc, aRow0, aXor, 0 + aSel,  wR, wXor, wSel);
    mma_pass<6>(acc, aRow0, aXor, 16 + aSel, wR, wXor, wSel);
    __syncthreads();
    load_half(S, g_imgs + 1 * 32768, tid); CPA_COMMIT();              // W1 prefetch
    epi_store(Ab, acc, sB[0], (const float*)0, (const int*)0, false, mrow0, ncol0, lane);
    CPA_WAIT0(); __syncthreads();

    // ---- L1 ----
    acc_zero(acc);
    mma_pass<8>(acc, aRow0, aXor, 0 + aSel,  wR, wXor, wSel);
    mma_pass<8>(acc, aRow0, aXor, 16 + aSel, wR, wXor, wSel);
    __syncthreads();
    load_half(S, g_imgs + 2 * 32768, tid); CPA_COMMIT();              // W2 prefetch
    epi_store(Ab, acc, sB[1], (const float*)0, (const int*)0, true, mrow0, ncol0, lane);
    CPA_WAIT0(); __syncthreads();

    // ---- L2 -> pool ----
    acc_zero(acc);
    mma_pass<8>(acc, aRow0, aXor, 0 + aSel,  wR, wXor, wSel);
    mma_pass<8>(acc, aRow0, aXor, 16 + aSel, wR, wXor, wSel);
    __syncthreads();
    {
        float* pool = (float*)Ab;     // 128*132*4 = 67584 B, spills into W slot (done)
        int gr = lane >> 2, q2 = (lane & 3) * 2;
#pragma unroll
        for (int mt = 0; mt < 4; mt++) {
            int r0 = mrow0 + mt * 16 + gr, r1 = r0 + 8;
#pragma unroll
            for (int nt = 0; nt < 4; nt++) {
                int c = ncol0 + nt * 8 + q2;
                *(float2*)(pool + r0 * PSTR + c) =
                    make_float2(fmaxf(acc[mt][nt][0] + sB[2][c], 0.f),
                                fmaxf(acc[mt][nt][1] + sB[2][c + 1], 0.f));
                *(float2*)(pool + r1 * PSTR + c) =
                    make_float2(fmaxf(acc[mt][nt][2] + sB[2][c], 0.f),
                                fmaxf(acc[mt][nt][3] + sB[2][c + 1], 0.f));
            }
        }
    }
    __syncthreads();

    // sorted-segment run-length pooling; atomics make any row partition correct.
    const float* pool = (const float*)Ab;
    {
        int col = tid & 127, hh = tid >> 7;       // 2 row-halves x 128 cols
        int r0 = hh * 64;
        float r = 0.f; int cur = sSeg[r0];
        for (int m = r0; m < r0 + 64; m++) {
            int s = sSeg[m];
            if (s != cur) { atomicAdd(&g_frag_sum[(size_t)cur * H + col], r); r = 0.f; cur = s; }
            r += pool[m * PSTR + col];
        }
        atomicAdd(&g_frag_sum[(size_t)cur * H + col], r);
    }
    if (tid < 8) {                                 // counts: 8 chunks of 16 rows
        int r0 = tid * 16;
        float c = 0.f; int cur = sSeg[r0];
        for (int m = r0; m < r0 + 16; m++) {
            int s = sSeg[m];
            if (s != cur) { atomicAdd(&g_cnt[cur], c); c = 0.f; cur = s; }
            c += 1.f;
        }
        atomicAdd(&g_cnt[cur], c);
    }
}

// ---------------- fragment head: fp16 3-pass, 128 rows/CTA, 2 CTAs/SM ----------------
__global__ __launch_bounds__(256, 2) void frag_mlp_kernel(
    const int* __restrict__ ind_maps, const int* __restrict__ broken,
    const float* __restrict__ W_m1, const float* __restrict__ b_m1,
    const float* __restrict__ b_m2, const float* __restrict__ b_out,
    const float* __restrict__ b_attn, float* __restrict__ out) {
    extern __shared__ __align__(16) char Ab[];
    __shared__ int sInd[128]; __shared__ float sInv[128]; __shared__ int sBk[128];
    __shared__ float sB1[128], sB2[128], sBo[26];
    __shared__ float sOne[13 * 132];

    int tid = threadIdx.x, lane = tid & 31, w = tid >> 5;
    int mrow0 = (w >> 2) * 64, ncol0 = (w & 3) * 32;
    int base = blockIdx.x * 128;
    u32 smA = smem_u32(Ab);
    u32 S = smA + A_B;

    load_half(S, g_imgs + 3 * 32768, tid); CPA_COMMIT();         // Wa hi

    if (tid < 128) {
        int f = base + tid;
        sInd[tid] = (f < NF) ? ind_maps[f] : 0;
        sInv[tid] = (f < NF) ? 1.f / fmaxf(g_cnt[f], 1.f) : 0.f;
        int b = (f < NF) ? broken[f] : 0;
        sBk[tid] = min(max(b, 0), 12);
        sB1[tid] = b_m1[tid]; sB2[tid] = b_m2[tid];
    }
    if (tid < 26) sBo[tid] = (tid < 13) ? b_out[tid] : b_attn[tid - 13];
    for (int i = tid; i < 13 * 128; i += 256) {
        int rr = i >> 7, c = i & 127;
        sOne[rr * 132 + c] = W_m1[(size_t)(384 + rr) * H + c];
    }
    __syncthreads();

    // stage ext-root rows via sInd
    for (int idx = tid; idx < 128 * 64; idx += 256) {
        int m = idx >> 6, k = (idx & 63) * 2;
        float2 v = *(const float2*)(g_root_emb + (size_t)sInd[m] * H + k);
        u32 hp, lp; split_pair(v.x, v.y, hp, lp);
        int o = a_off(m, k);
        *(u32*)(Ab + o) = hp; *(u32*)(Ab + o + 256) = lp;
    }
    CPA_WAIT0(); __syncthreads();

    int rowA = mrow0 + (lane & 15);
    u32 aRow0 = smA + rowA * 512; int aXor = rowA & 7; int aSel = lane >> 4;
    int rowB = ncol0 + (lane & 7) + ((lane >> 4) << 3);
    u32 wR = S + rowB * 256; int wXor = rowB & 7; int wSel = (lane >> 3) & 1;

    float acc[4][4][4];
    acc_zero(acc);

    // ---- L1a: ext @ Wa (3-pass) ----
    mma_pass<8>(acc, aRow0, aXor, 0 + aSel,  wR, wXor, wSel);
    mma_pass<8>(acc, aRow0, aXor, 16 + aSel, wR, wXor, wSel);
    __syncthreads();
    load_half(S, g_imgs + 3 * 32768 + 16384, tid); CPA_COMMIT(); CPA_WAIT0();   // Wa lo
    __syncthreads();
    mma_pass<8>(acc, aRow0, aXor, 0 + aSel, wR, wXor, wSel);
    __syncthreads();
    // restage A = mean rows; load Wb hi
    load_half(S, g_imgs + 4 * 32768, tid); CPA_COMMIT();
    for (int idx = tid; idx < 128 * 64; idx += 256) {
        int m = idx >> 6, k = (idx & 63) * 2;
        int f = base + m;
        float2 v = make_float2(0.f, 0.f);
        if (f < NF) {
            v = *(const float2*)(g_frag_sum + (size_t)f * H + k);
            v.x *= sInv[m]; v.y *= sInv[m];
        }
        u32 hp, lp; split_pair(v.x, v.y, hp, lp);
        int o = a_off(m, k);
        *(u32*)(Ab + o) = hp; *(u32*)(Ab + o + 256) = lp;
    }
    CPA_WAIT0(); __syncthreads();

    // ---- L1b: += mean @ Wb (3-pass) ----
    mma_pass<8>(acc, aRow0, aXor, 0 + aSel,  wR, wXor, wSel);
    mma_pass<8>(acc, aRow0, aXor, 16 + aSel, wR, wXor, wSel);
    __syncthreads();
    load_half(S, g_imgs + 4 * 32768 + 16384, tid); CPA_COMMIT(); CPA_WAIT0();   // Wb lo
    __syncthreads();
    mma_pass<8>(acc, aRow0, aXor, 0 + aSel, wR, wXor, wSel);
    __syncthreads();
    load_half(S, g_imgs + 5 * 32768, tid); CPA_COMMIT();                        // Wm2 hi
    epi_store(Ab, acc, sB1, sOne, sBk, true, mrow0, ncol0, lane);
    CPA_WAIT0(); __syncthreads();

    // ---- L2 (3-pass) ----
    acc_zero(acc);
    mma_pass<8>(acc, aRow0, aXor, 0 + aSel,  wR, wXor, wSel);
    mma_pass<8>(acc, aRow0, aXor, 16 + aSel, wR, wXor, wSel);
    __syncthreads();
    load_half(S, g_imgs + 5 * 32768 + 16384, tid); CPA_COMMIT(); CPA_WAIT0();   // Wm2 lo
    __syncthreads();
    mma_pass<8>(acc, aRow0, aXor, 0 + aSel, wR, wXor, wSel);
    __syncthreads();
    load_half(S, g_imgs + 6 * 32768, tid); CPA_COMMIT();                        // Wout hi
    epi_store(Ab, acc, sB2, (const float*)0, (const int*)0, true, mrow0, ncol0, lane);
    CPA_WAIT0(); __syncthreads();

    // ---- out layer: cols 0..25 (only warps with ncol0==0 compute) ----
    bool active = (ncol0 == 0);
    acc_zero(acc);
    if (active) {
        mma_pass<8>(acc, aRow0, aXor, 0 + aSel,  wR, wXor, wSel);
        mma_pass<8>(acc, aRow0, aXor, 16 + aSel, wR, wXor, wSel);
    }
    __syncthreads();
    load_half(S, g_imgs + 6 * 32768 + 16384, tid); CPA_COMMIT(); CPA_WAIT0();   // Wout lo
    __syncthreads();
    if (active) {
        mma_pass<8>(acc, aRow0, aXor, 0 + aSel, wR, wXor, wSel);
        int gr = lane >> 2, q2 = (lane & 3) * 2;
#pragma unroll
        for (int mt = 0; mt < 4; mt++) {
            int r0 = mrow0 + mt * 16 + gr, r1 = r0 + 8;
            int fA = base + r0, fB = base + r1;
#pragma unroll
            for (int nt = 0; nt < 4; nt++) {
#pragma unroll
                for (int e = 0; e < 2; e++) {
                    int c = nt * 8 + q2 + e;
                    if (c >= 26) continue;
                    if (fA < NF) {
                        float v = acc[mt][nt][e] + sBo[c];
                        if (c < 13) out[(size_t)fA * 13 + c] = 1.f / (1.f + __expf(-v));
                        else        out[(size_t)NF * 13 + (size_t)fA * 13 + (c - 13)] = v;
                    }
                    if (fB < NF) {
                        float v = acc[mt][nt][2 + e] + sBo[c];
                        if (c < 13) out[(size_t)fB * 13 + c] = 1.f / (1.f + __expf(-v));
                        else        out[(size_t)NF * 13 + (size_t)fB * 13 + (c - 13)] = v;
                    }
                }
            }
        }
    }
}

// ---------------- launcher ----------------
extern "C" void kernel_launch(void* const* d_in, const int* in_sizes, int n_in,
                              void* d_out, int out_size) {
    const float* node_h    = (const float*)d_in[0];
    const int*   seg       = (const int*)d_in[1];
    const float* root_repr = (const float*)d_in[2];
    const int*   ind_maps  = (const int*)d_in[3];
    const int*   broken    = (const int*)d_in[4];
    const float* W_root = (const float*)d_in[5];  const float* b_root = (const float*)d_in[6];
    const float* W_in   = (const float*)d_in[7];  const float* b_in   = (const float*)d_in[8];
    const float* W_g1   = (const float*)d_in[9];  const float* b_g1   = (const float*)d_in[10];
    const float* W_g2   = (const float*)d_in[11]; const float* b_g2   = (const float*)d_in[12];
    const float* W_m1   = (const float*)d_in[13]; const float* b_m1   = (const float*)d_in[14];
    const float* W_m2   = (const float*)d_in[15]; const float* b_m2   = (const float*)d_in[16];
    const float* W_out  = (const float*)d_in[17]; const float* b_out  = (const float*)d_in[18];
    const float* W_attn = (const float*)d_in[19]; const float* b_attn = (const float*)d_in[20];
    float* out = (float*)d_out;

    void* p = 0;
    cudaGetSymbolAddress(&p, g_frag_sum);
    cudaMemsetAsync(p, 0, (size_t)NF * H * sizeof(float), 0);
    cudaGetSymbolAddress(&p, g_cnt);
    cudaMemsetAsync(p, 0, (size_t)NF * sizeof(float), 0);
    cudaGetSymbolAddress(&p, g_imgs);
    cudaMemsetAsync(p, 0, (size_t)7 * 32768 * sizeof(u16), 0);

    cudaFuncSetAttribute(node_chain_kernel, cudaFuncAttributeMaxDynamicSharedMemorySize, DYN);
    cudaFuncSetAttribute(frag_mlp_kernel,   cudaFuncAttributeMaxDynamicSharedMemorySize, DYN);

    prep_kernel<<<(7 * 16384 + 255) / 256, 256>>>(W_in, W_g1, W_g2, W_m1, W_m2, W_out, W_attn);
    root_enc_kernel<<<NR, 128>>>(root_repr, W_root, b_root);
    node_chain_kernel<<<NN / 128, 256, DYN>>>(node_h, seg, b_in, b_g1, b_g2);
    frag_mlp_kernel<<<(NF + 127) / 128, 256, DYN>>>(ind_maps, broken, W_m1, b_m1,
                                                    b_m2, b_out, b_attn, out);
}

// round 10
// speedup vs baseline: 5.1981x; 1.4097x over previous
#include <cuda_runtime.h>
#include <cuda_fp16.h>

typedef unsigned int u32; typedef unsigned short u16;

#define NN   800000
#define NF   100000
#define NR   2000
#define FEAT 86
#define H    128

#define SLOT_B   32768          // one W half-image (128 n-rows x 128 k u16, swizzled)
#define A_NODE_B 32768          // node A: 128 rows x 256 B (fp16 hi only)
#define A_FRAG_B 65536          // frag A: 128 rows x 512 B (hi+lo)
#define NODE_DYN 67584          // max(A+W = 65536, pool 128*132*4 = 67584)
#define FRAG_DYN (A_FRAG_B + SLOT_B)   // 98304
#define PSTR     132            // pool stride (floats)

// ---------------- device scratch ----------------
__device__ __align__(16) u16   g_imgs[7 * 32768];   // per image: [hi 16384 u16][lo 16384 u16], fp16, pre-swizzled
__device__ __align__(16) float g_root_emb[NR * H];
__device__ __align__(16) float g_frag_sum[(size_t)NF * H];
__device__ float g_cnt[NF];

// ---------------- helpers ----------------
__device__ __forceinline__ u32 smem_u32(const void* p) {
    u32 a; asm("{ .reg .u64 t; cvta.to.shared.u64 t, %1; cvt.u32.u64 %0, t; }" : "=r"(a) : "l"(p));
    return a;
}
__device__ __forceinline__ void cpa16(u32 dst, const void* src) {
    asm volatile("cp.async.ca.shared.global [%0], [%1], 16;" :: "r"(dst), "l"(src));
}
#define CPA_COMMIT() asm volatile("cp.async.commit_group;" ::: "memory")
#define CPA_WAIT0()  asm volatile("cp.async.wait_group 0;" ::: "memory")

#define LDSM4(d0, d1, d2, d3, a) \
    asm volatile("ldmatrix.sync.aligned.m8n8.x4.shared.b16 {%0,%1,%2,%3}, [%4];" \
                 : "=r"(d0), "=r"(d1), "=r"(d2), "=r"(d3) : "r"(a))

__device__ __forceinline__ u32 pack_h2(float v0, float v1) {
    __half2 h = __floats2half2_rn(v0, v1);
    return *(u32*)&h;
}
__device__ __forceinline__ void split_pair(float v0, float v1, u32& hp, u32& lp) {
    __half2 h = __floats2half2_rn(v0, v1);
    hp = *(u32*)&h;
    float r0 = v0 - __half2float(__low2half(h));
    float r1 = v1 - __half2float(__high2half(h));
    __half2 l = __floats2half2_rn(r0, r1);
    lp = *(u32*)&l;
}
__device__ __forceinline__ void mma16816(float* c, u32 a0, u32 a1, u32 a2, u32 a3, u32 b0, u32 b1) {
    asm volatile("mma.sync.aligned.m16n8k16.row.col.f32.f16.f16.f32 "
                 "{%0,%1,%2,%3}, {%4,%5,%6,%7}, {%8,%9}, {%0,%1,%2,%3};"
                 : "+f"(c[0]), "+f"(c[1]), "+f"(c[2]), "+f"(c[3])
                 : "r"(a0), "r"(a1), "r"(a2), "r"(a3), "r"(b0), "r"(b1));
}

// swizzled byte offsets: chunk16 ^ (row & 7)
__device__ __forceinline__ int a_off256(int r, int c) {   // node A rows: 256 B (hi only)
    return r * 256 + (((c >> 3) ^ (r & 7)) << 4) + (c & 7) * 2;
}
__device__ __forceinline__ int a_off512(int r, int c) {   // frag A rows: 512 B (hi; lo = +256)
    return r * 512 + (((c >> 3) ^ (r & 7)) << 4) + (c & 7) * 2;
}

// ---------------- fully-unrolled GEMM pass: warp tile 64 x 32 ----------------
// MTSTEP = bytes per 16 A-rows (4096 node, 8192 frag)
template<int NK, int MTSTEP>
__device__ __forceinline__ void mma_pass(float (&acc)[4][4][4],
                                         u32 aRow0, int aXor, int aCS,
                                         u32 wRow0, int wXor, int wSel) {
#pragma unroll
    for (int ks = 0; ks < NK; ks++) {
        u32 a[4][4];
#pragma unroll
        for (int mt = 0; mt < 4; mt++) {
            u32 ad = aRow0 + mt * MTSTEP + (u32)((((aCS + 2 * ks) ^ aXor) << 4));
            LDSM4(a[mt][0], a[mt][1], a[mt][2], a[mt][3], ad);
        }
        u32 b[2][4];
#pragma unroll
        for (int nb = 0; nb < 2; nb++) {
            u32 bd = wRow0 + nb * 4096 + (u32)((((2 * ks + wSel) ^ wXor) << 4));
            LDSM4(b[nb][0], b[nb][1], b[nb][2], b[nb][3], bd);
        }
#pragma unroll
        for (int mt = 0; mt < 4; mt++)
#pragma unroll
            for (int nb = 0; nb < 2; nb++) {
                mma16816(acc[mt][2 * nb + 0], a[mt][0], a[mt][1], a[mt][2], a[mt][3], b[nb][0], b[nb][1]);
                mma16816(acc[mt][2 * nb + 1], a[mt][0], a[mt][1], a[mt][2], a[mt][3], b[nb][2], b[nb][3]);
            }
    }
}
__device__ __forceinline__ void acc_zero(float (&acc)[4][4][4]) {
#pragma unroll
    for (int mt = 0; mt < 4; mt++)
#pragma unroll
        for (int nt = 0; nt < 4; nt++)
#pragma unroll
            for (int e = 0; e < 4; e++) acc[mt][nt][e] = 0.f;
}

// node epilogue: acc + bias (+relu) -> fp16 hi only into 256B-row A
__device__ __forceinline__ void epi_node(char* Ab, float (&acc)[4][4][4],
                                         const float* __restrict__ bias,
                                         bool relu, int mrow0, int ncol0, int lane) {
    int gr = lane >> 2, q2 = (lane & 3) * 2;
#pragma unroll
    for (int mt = 0; mt < 4; mt++) {
        int r0 = mrow0 + mt * 16 + gr, r1 = r0 + 8;
#pragma unroll
        for (int nt = 0; nt < 4; nt++) {
            int c = ncol0 + nt * 8 + q2;
            float v0 = acc[mt][nt][0] + bias[c], v1 = acc[mt][nt][1] + bias[c + 1];
            float w0 = acc[mt][nt][2] + bias[c], w1 = acc[mt][nt][3] + bias[c + 1];
            if (relu) { v0 = fmaxf(v0, 0.f); v1 = fmaxf(v1, 0.f); w0 = fmaxf(w0, 0.f); w1 = fmaxf(w1, 0.f); }
            *(u32*)(Ab + a_off256(r0, c)) = pack_h2(v0, v1);
            *(u32*)(Ab + a_off256(r1, c)) = pack_h2(w0, w1);
        }
    }
}

// frag epilogue: acc + bias (+onehot) (+relu) -> split hi/lo into 512B-row A
__device__ __forceinline__ void epi_frag(char* Ab, float (&acc)[4][4][4],
                                         const float* __restrict__ bias,
                                         const float* __restrict__ sOne, const int* __restrict__ sBk,
                                         bool relu, int mrow0, int ncol0, int lane) {
    int gr = lane >> 2, q2 = (lane & 3) * 2;
#pragma unroll
    for (int mt = 0; mt < 4; mt++) {
        int r0 = mrow0 + mt * 16 + gr, r1 = r0 + 8;
        const float* oA = sOne ? (sOne + sBk[r0] * 132) : (const float*)0;
        const float* oB = sOne ? (sOne + sBk[r1] * 132) : (const float*)0;
#pragma unroll
        for (int nt = 0; nt < 4; nt++) {
            int c = ncol0 + nt * 8 + q2;
            float v0 = acc[mt][nt][0] + bias[c], v1 = acc[mt][nt][1] + bias[c + 1];
            float w0 = acc[mt][nt][2] + bias[c], w1 = acc[mt][nt][3] + bias[c + 1];
            if (oA) { v0 += oA[c]; v1 += oA[c + 1]; }
            if (oB) { w0 += oB[c]; w1 += oB[c + 1]; }
            if (relu) { v0 = fmaxf(v0, 0.f); v1 = fmaxf(v1, 0.f); w0 = fmaxf(w0, 0.f); w1 = fmaxf(w1, 0.f); }
            u32 hp, lp;
            int o0 = a_off512(r0, c);
            split_pair(v0, v1, hp, lp);
            *(u32*)(Ab + o0) = hp; *(u32*)(Ab + o0 + 256) = lp;
            int o1 = a_off512(r1, c);
            split_pair(w0, w1, hp, lp);
            *(u32*)(Ab + o1) = hp; *(u32*)(Ab + o1 + 256) = lp;
        }
    }
}

__device__ __forceinline__ void load_half(u32 slot, const u16* src, int tid) {
    const uint4* s = (const uint4*)src;
    for (int i = tid; i < 2048; i += 256) cpa16(slot + i * 16, s + i);
}

// ---------------- prep: transpose weights into fp16 images (hi used; lo kept for layout) ----------------
__global__ void prep_kernel(const float* __restrict__ W_in, const float* __restrict__ Wg1,
                            const float* __restrict__ Wg2, const float* __restrict__ Wm1,
                            const float* __restrict__ Wm2, const float* __restrict__ Wout,
                            const float* __restrict__ Wattn) {
    int idx = blockIdx.x * 256 + threadIdx.x;
    if (idx >= 7 * 16384) return;
    int img = idx >> 14, r = idx & 16383, n = r >> 7, k = r & 127;
    float w;
    if (img == 0)      { if (k >= FEAT) return; w = W_in[k * H + n]; }
    else if (img == 1) w = Wg1[k * H + n];
    else if (img == 2) w = Wg2[k * H + n];
    else if (img == 3) w = Wm1[k * H + n] + Wm1[(H + k) * H + n];
    else if (img == 4) w = Wm1[(2 * H + k) * H + n] - Wm1[(H + k) * H + n];
    else if (img == 5) w = Wm2[k * H + n];
    else               { if (n >= 26) return;
                         w = (n < 13) ? Wout[k * 13 + n] : Wattn[k * 13 + (n - 13)]; }
    int off = n * 128 + (((k >> 3) ^ (n & 7)) << 3) + (k & 7);
    g_imgs[img * 32768 + off] = __half_as_ushort(__float2half_rn(w));
}

// ---------------- root encoder ----------------
__global__ void root_enc_kernel(const float* __restrict__ root_repr,
                                const float* __restrict__ W_root,
                                const float* __restrict__ b_root) {
    __shared__ float sX[FEAT];
    int r = blockIdx.x, n = threadIdx.x;
    for (int k = n; k < FEAT; k += 128) sX[k] = root_repr[r * FEAT + k];
    __syncthreads();
    float s = b_root[n];
#pragma unroll 2
    for (int k = 0; k < FEAT; k++) s += sX[k] * W_root[k * H + n];
    g_root_emb[r * H + n] = fmaxf(s, 0.f);
}

// ---------------- node chain: pure fp16 single-pass, 128 rows/CTA, 2 CTAs/SM ----------------
__global__ __launch_bounds__(256, 2) void node_chain_kernel(
    const float* __restrict__ node_h, const int* __restrict__ seg,
    const float* __restrict__ b_in, const float* __restrict__ b_g1,
    const float* __restrict__ b_g2) {
    extern __shared__ __align__(16) char Ab[];
    __shared__ float sB[3][128];
    __shared__ int sSeg[128];

    int tid = threadIdx.x, lane = tid & 31, w = tid >> 5;
    int mrow0 = (w >> 2) * 64, ncol0 = (w & 3) * 32;
    int tilebase = blockIdx.x * 128;          // NN = 6250 * 128
    u32 smA = smem_u32(Ab);
    u32 S = smA + A_NODE_B;

    load_half(S, g_imgs, tid); CPA_COMMIT();           // W0

    if (tid < 128) { sSeg[tid] = seg[tilebase + tid];
                     sB[0][tid] = b_in[tid]; sB[1][tid] = b_g1[tid]; sB[2][tid] = b_g2[tid]; }

    // zero pad cols 86..95
    for (int i = tid; i < 128 * 5; i += 256) {
        int m = i / 5, k = 86 + (i - 5 * (i / 5)) * 2;
        *(u32*)(Ab + a_off256(m, k)) = 0;
    }
    // stage node_h (fp16 round)
    for (int idx = tid; idx < 128 * 43; idx += 256) {
        int m = idx / 43, k = (idx - m * 43) * 2;
        float2 v = *(const float2*)(node_h + (size_t)(tilebase + m) * FEAT + k);
        *(u32*)(Ab + a_off256(m, k)) = pack_h2(v.x, v.y);
    }
    CPA_WAIT0(); __syncthreads();

    int rowA = mrow0 + (lane & 15);
    u32 aRow0 = smA + rowA * 256; int aXor = rowA & 7; int aSel = lane >> 4;
    int rowB = ncol0 + (lane & 7) + ((lane >> 4) << 3);
    u32 wR = S + rowB * 256; int wXor = rowB & 7; int wSel = (lane >> 3) & 1;

    float acc[4][4][4];

    // ---- L0 (K=96), no relu ----
    acc_zero(acc);
    mma_pass<6, 4096>(acc, aRow0, aXor, aSel, wR, wXor, wSel);
    __syncthreads();
    load_half(S, g_imgs + 1 * 32768, tid); CPA_COMMIT();
    epi_node(Ab, acc, sB[0], false, mrow0, ncol0, lane);
    CPA_WAIT0(); __syncthreads();

    // ---- L1, relu ----
    acc_zero(acc);
    mma_pass<8, 4096>(acc, aRow0, aXor, aSel, wR, wXor, wSel);
    __syncthreads();
    load_half(S, g_imgs + 2 * 32768, tid); CPA_COMMIT();
    epi_node(Ab, acc, sB[1], true, mrow0, ncol0, lane);
    CPA_WAIT0(); __syncthreads();

    // ---- L2 -> pool ----
    acc_zero(acc);
    mma_pass<8, 4096>(acc, aRow0, aXor, aSel, wR, wXor, wSel);
    __syncthreads();
    {
        float* pool = (float*)Ab;     // 128*132*4 = 67584 B (covers A+W regions)
        int gr = lane >> 2, q2 = (lane & 3) * 2;
#pragma unroll
        for (int mt = 0; mt < 4; mt++) {
            int r0 = mrow0 + mt * 16 + gr, r1 = r0 + 8;
#pragma unroll
            for (int nt = 0; nt < 4; nt++) {
                int c = ncol0 + nt * 8 + q2;
                *(float2*)(pool + r0 * PSTR + c) =
                    make_float2(fmaxf(acc[mt][nt][0] + sB[2][c], 0.f),
                                fmaxf(acc[mt][nt][1] + sB[2][c + 1], 0.f));
                *(float2*)(pool + r1 * PSTR + c) =
                    make_float2(fmaxf(acc[mt][nt][2] + sB[2][c], 0.f),
                                fmaxf(acc[mt][nt][3] + sB[2][c + 1], 0.f));
            }
        }
    }
    __syncthreads();

    // sorted-segment run-length pooling (atomics tolerate any row partition)
    const float* pool = (const float*)Ab;
    {
        int col = tid & 127, hh = tid >> 7;       // 2 row-halves x 128 cols
        int r0 = hh * 64;
        float r = 0.f; int cur = sSeg[r0];
        for (int m = r0; m < r0 + 64; m++) {
            int s = sSeg[m];
            if (s != cur) { atomicAdd(&g_frag_sum[(size_t)cur * H + col], r); r = 0.f; cur = s; }
            r += pool[m * PSTR + col];
        }
        atomicAdd(&g_frag_sum[(size_t)cur * H + col], r);
    }
    if (tid < 8) {                                 // counts: 8 chunks of 16 rows
        int r0 = tid * 16;
        float c = 0.f; int cur = sSeg[r0];
        for (int m = r0; m < r0 + 16; m++) {
            int s = sSeg[m];
            if (s != cur) { atomicAdd(&g_cnt[cur], c); c = 0.f; cur = s; }
            c += 1.f;
        }
        atomicAdd(&g_cnt[cur], c);
    }
}

// ---------------- fragment head: 2-pass (A split, W rounded), 128 rows/CTA, 2 CTAs/SM ----------------
__global__ __launch_bounds__(256, 2) void frag_mlp_kernel(
    const int* __restrict__ ind_maps, const int* __restrict__ broken,
    const float* __restrict__ W_m1, const float* __restrict__ b_m1,
    const float* __restrict__ b_m2, const float* __restrict__ b_out,
    const float* __restrict__ b_attn, float* __restrict__ out) {
    extern __shared__ __align__(16) char Ab[];
    __shared__ int sInd[128]; __shared__ float sInv[128]; __shared__ int sBk[128];
    __shared__ float sB1[128], sB2[128], sBo[26];
    __shared__ float sOne[13 * 132];

    int tid = threadIdx.x, lane = tid & 31, w = tid >> 5;
    int mrow0 = (w >> 2) * 64, ncol0 = (w & 3) * 32;
    int base = blockIdx.x * 128;
    u32 smA = smem_u32(Ab);
    u32 S = smA + A_FRAG_B;

    load_half(S, g_imgs + 3 * 32768, tid); CPA_COMMIT();         // Wa

    if (tid < 128) {
        int f = base + tid;
        sInd[tid] = (f < NF) ? ind_maps[f] : 0;
        sInv[tid] = (f < NF) ? 1.f / fmaxf(g_cnt[f], 1.f) : 0.f;
        int b = (f < NF) ? broken[f] : 0;
        sBk[tid] = min(max(b, 0), 12);
        sB1[tid] = b_m1[tid]; sB2[tid] = b_m2[tid];
    }
    if (tid < 26) sBo[tid] = (tid < 13) ? b_out[tid] : b_attn[tid - 13];
    for (int i = tid; i < 13 * 128; i += 256) {
        int rr = i >> 7, c = i & 127;
        sOne[rr * 132 + c] = W_m1[(size_t)(384 + rr) * H + c];
    }
    __syncthreads();

    // stage ext-root rows (hi + lo)
    for (int idx = tid; idx < 128 * 64; idx += 256) {
        int m = idx >> 6, k = (idx & 63) * 2;
        float2 v = *(const float2*)(g_root_emb + (size_t)sInd[m] * H + k);
        u32 hp, lp; split_pair(v.x, v.y, hp, lp);
        int o = a_off512(m, k);
        *(u32*)(Ab + o) = hp; *(u32*)(Ab + o + 256) = lp;
    }
    CPA_WAIT0(); __syncthreads();

    int rowA = mrow0 + (lane & 15);
    u32 aRow0 = smA + rowA * 512; int aXor = rowA & 7; int aSel = lane >> 4;
    int rowB = ncol0 + (lane & 7) + ((lane >> 4) << 3);
    u32 wR = S + rowB * 256; int wXor = rowB & 7; int wSel = (lane >> 3) & 1;

    float acc[4][4][4];
    acc_zero(acc);

    // ---- L1a: ext @ Wa (A-hi, A-lo) ----
    mma_pass<8, 8192>(acc, aRow0, aXor, 0 + aSel,  wR, wXor, wSel);
    mma_pass<8, 8192>(acc, aRow0, aXor, 16 + aSel, wR, wXor, wSel);
    __syncthreads();
    // restage A = mean rows; prefetch Wb
    load_half(S, g_imgs + 4 * 32768, tid); CPA_COMMIT();
    for (int idx = tid; idx < 128 * 64; idx += 256) {
        int m = idx >> 6, k = (idx & 63) * 2;
        int f = base + m;
        float2 v = make_float2(0.f, 0.f);
        if (f < NF) {
            v = *(const float2*)(g_frag_sum + (size_t)f * H + k);
            v.x *= sInv[m]; v.y *= sInv[m];
        }
        u32 hp, lp; split_pair(v.x, v.y, hp, lp);
        int o = a_off512(m, k);
        *(u32*)(Ab + o) = hp; *(u32*)(Ab + o + 256) = lp;
    }
    CPA_WAIT0(); __syncthreads();

    // ---- L1b: += mean @ Wb ----
    mma_pass<8, 8192>(acc, aRow0, aXor, 0 + aSel,  wR, wXor, wSel);
    mma_pass<8, 8192>(acc, aRow0, aXor, 16 + aSel, wR, wXor, wSel);
    __syncthreads();
    load_half(S, g_imgs + 5 * 32768, tid); CPA_COMMIT();                        // Wm2
    epi_frag(Ab, acc, sB1, sOne, sBk, true, mrow0, ncol0, lane);
    CPA_WAIT0(); __syncthreads();

    // ---- L2 ----
    acc_zero(acc);
    mma_pass<8, 8192>(acc, aRow0, aXor, 0 + aSel,  wR, wXor, wSel);
    mma_pass<8, 8192>(acc, aRow0, aXor, 16 + aSel, wR, wXor, wSel);
    __syncthreads();
    load_half(S, g_imgs + 6 * 32768, tid); CPA_COMMIT();                        // Wout
    epi_frag(Ab, acc, sB2, (const float*)0, (const int*)0, true, mrow0, ncol0, lane);
    CPA_WAIT0(); __syncthreads();

    // ---- out layer: cols 0..25 (only warps with ncol0==0 compute) ----
    if (ncol0 == 0) {
        acc_zero(acc);
        mma_pass<8, 8192>(acc, aRow0, aXor, 0 + aSel,  wR, wXor, wSel);
        mma_pass<8, 8192>(acc, aRow0, aXor, 16 + aSel, wR, wXor, wSel);
        int gr = lane >> 2, q2 = (lane & 3) * 2;
#pragma unroll
        for (int mt = 0; mt < 4; mt++) {
            int r0 = mrow0 + mt * 16 + gr, r1 = r0 + 8;
            int fA = base + r0, fB = base + r1;
#pragma unroll
            for (int nt = 0; nt < 4; nt++) {
#pragma unroll
                for (int e = 0; e < 2; e++) {
                    int c = nt * 8 + q2 + e;
                    if (c >= 26) continue;
                    if (fA < NF) {
                        float v = acc[mt][nt][e] + sBo[c];
                        if (c < 13) out[(size_t)fA * 13 + c] = 1.f / (1.f + __expf(-v));
                        else        out[(size_t)NF * 13 + (size_t)fA * 13 + (c - 13)] = v;
                    }
                    if (fB < NF) {
                        float v = acc[mt][nt][2 + e] + sBo[c];
                        if (c < 13) out[(size_t)fB * 13 + c] = 1.f / (1.f + __expf(-v));
                        else        out[(size_t)NF * 13 + (size_t)fB * 13 + (c - 13)] = v;
                    }
                }
            }
        }
    }
}

// ---------------- launcher ----------------
extern "C" void kernel_launch(void* const* d_in, const int* in_sizes, int n_in,
                              void* d_out, int out_size) {
    const float* node_h    = (const float*)d_in[0];
    const int*   seg       = (const int*)d_in[1];
    const float* root_repr = (const float*)d_in[2];
    const int*   ind_maps  = (const int*)d_in[3];
    const int*   broken    = (const int*)d_in[4];
    const float* W_root = (const float*)d_in[5];  const float* b_root = (const float*)d_in[6];
    const float* W_in   = (const float*)d_in[7];  const float* b_in   = (const float*)d_in[8];
    const float* W_g1   = (const float*)d_in[9];  const float* b_g1   = (const float*)d_in[10];
    const float* W_g2   = (const float*)d_in[11]; const float* b_g2   = (const float*)d_in[12];
    const float* W_m1   = (const float*)d_in[13]; const float* b_m1   = (const float*)d_in[14];
    const float* W_m2   = (const float*)d_in[15]; const float* b_m2   = (const float*)d_in[16];
    const float* W_out  = (const float*)d_in[17]; const float* b_out  = (const float*)d_in[18];
    const float* W_attn = (const float*)d_in[19]; const float* b_attn = (const float*)d_in[20];
    float* out = (float*)d_out;

    void* p = 0;
    cudaGetSymbolAddress(&p, g_frag_sum);
    cudaMemsetAsync(p, 0, (size_t)NF * H * sizeof(float), 0);
    cudaGetSymbolAddress(&p, g_cnt);
    cudaMemsetAsync(p, 0, (size_t)NF * sizeof(float), 0);
    cudaGetSymbolAddress(&p, g_imgs);
    cudaMemsetAsync(p, 0, (size_t)7 * 32768 * sizeof(u16), 0);

    cudaFuncSetAttribute(node_chain_kernel, cudaFuncAttributeMaxDynamicSharedMemorySize, NODE_DYN);
    cudaFuncSetAttribute(frag_mlp_kernel,   cudaFuncAttributeMaxDynamicSharedMemorySize, FRAG_DYN);

    prep_kernel<<<(7 * 16384 + 255) / 256, 256>>>(W_in, W_g1, W_g2, W_m1, W_m2, W_out, W_attn);
    root_enc_kernel<<<NR, 128>>>(root_repr, W_root, b_root);
    node_chain_kernel<<<NN / 128, 256, NODE_DYN>>>(node_h, seg, b_in, b_g1, b_g2);
    frag_mlp_kernel<<<(NF + 127) / 128, 256, FRAG_DYN>>>(ind_maps, broken, W_m1, b_m1,
                                                         b_m2, b_out, b_attn, out);
}

// round 11
// speedup vs baseline: 5.5143x; 1.0608x over previous
#include <cuda_runtime.h>
#include <cuda_fp16.h>

typedef unsigned int u32; typedef unsigned short u16;

#define NN   800000
#define NF   100000
#define NR   2000
#define FEAT 86
#define H    128

#define A_B    32768            // A: 128 rows x 256 B (fp16)
#define S0_OFF 32768
#define S1_OFF 65536
#define DYN    98304            // A + 2 W slots -> 2 CTAs/SM

// ---------------- device scratch ----------------
__device__ __align__(16) u16   g_imgs[7 * 16384];   // fp16 weight images, swizzled, transposed
__device__ __align__(16) float g_root_emb[NR * H];
__device__ __align__(16) float g_frag_sum[(size_t)NF * H];
__device__ float g_cnt[NF];

// ---------------- helpers ----------------
__device__ __forceinline__ u32 smem_u32(const void* p) {
    u32 a; asm("{ .reg .u64 t; cvta.to.shared.u64 t, %1; cvt.u32.u64 %0, t; }" : "=r"(a) : "l"(p));
    return a;
}
__device__ __forceinline__ void cpa16(u32 dst, const void* src) {
    asm volatile("cp.async.ca.shared.global [%0], [%1], 16;" :: "r"(dst), "l"(src));
}
#define CPA_COMMIT() asm volatile("cp.async.commit_group;" ::: "memory")
#define CPA_WAIT0()  asm volatile("cp.async.wait_group 0;" ::: "memory")
#define CPA_WAIT1()  asm volatile("cp.async.wait_group 1;" ::: "memory")

#define LDSM4(d0, d1, d2, d3, a) \
    asm volatile("ldmatrix.sync.aligned.m8n8.x4.shared.b16 {%0,%1,%2,%3}, [%4];" \
                 : "=r"(d0), "=r"(d1), "=r"(d2), "=r"(d3) : "r"(a))

__device__ __forceinline__ u32 pack_h2(float v0, float v1) {
    __half2 h = __floats2half2_rn(v0, v1);
    return *(u32*)&h;
}
__device__ __forceinline__ void mma16816(float* c, u32 a0, u32 a1, u32 a2, u32 a3, u32 b0, u32 b1) {
    asm volatile("mma.sync.aligned.m16n8k16.row.col.f32.f16.f16.f32 "
                 "{%0,%1,%2,%3}, {%4,%5,%6,%7}, {%8,%9}, {%0,%1,%2,%3};"
                 : "+f"(c[0]), "+f"(c[1]), "+f"(c[2]), "+f"(c[3])
                 : "r"(a0), "r"(a1), "r"(a2), "r"(a3), "r"(b0), "r"(b1));
}

// swizzled byte offset, 256 B rows: chunk16 ^ (row & 7)
__device__ __forceinline__ int a_off(int r, int c) {      // c = u16 col 0..127
    return r * 256 + (((c >> 3) ^ (r & 7)) << 4) + (c & 7) * 2;
}
// pool: fp32, 512 B rows, 16B-chunk XOR swizzle (low 3 bits)
__device__ __forceinline__ int p_off(int r, int c) {      // c = f32 col 0..127
    return r * 512 + (((c >> 2) ^ (r & 7)) << 4) + (c & 3) * 4;
}

// ---------------- fully-unrolled GEMM pass: warp tile 64 x 32 ----------------
template<int NK>
__device__ __forceinline__ void mma_pass(float (&acc)[4][4][4],
                                         u32 aRow0, int aXor, int aSel,
                                         u32 wRow0, int wXor, int wSel) {
#pragma unroll
    for (int ks = 0; ks < NK; ks++) {
        u32 a[4][4];
#pragma unroll
        for (int mt = 0; mt < 4; mt++) {
            u32 ad = aRow0 + mt * 4096 + (u32)((((aSel + 2 * ks) ^ aXor) << 4));
            LDSM4(a[mt][0], a[mt][1], a[mt][2], a[mt][3], ad);
        }
        u32 b[2][4];
#pragma unroll
        for (int nb = 0; nb < 2; nb++) {
            u32 bd = wRow0 + nb * 4096 + (u32)((((2 * ks + wSel) ^ wXor) << 4));
            LDSM4(b[nb][0], b[nb][1], b[nb][2], b[nb][3], bd);
        }
#pragma unroll
        for (int mt = 0; mt < 4; mt++)
#pragma unroll
            for (int nb = 0; nb < 2; nb++) {
                mma16816(acc[mt][2 * nb + 0], a[mt][0], a[mt][1], a[mt][2], a[mt][3], b[nb][0], b[nb][1]);
                mma16816(acc[mt][2 * nb + 1], a[mt][0], a[mt][1], a[mt][2], a[mt][3], b[nb][2], b[nb][3]);
            }
    }
}
__device__ __forceinline__ void acc_zero(float (&acc)[4][4][4]) {
#pragma unroll
    for (int mt = 0; mt < 4; mt++)
#pragma unroll
        for (int nt = 0; nt < 4; nt++)
#pragma unroll
            for (int e = 0; e < 4; e++) acc[mt][nt][e] = 0.f;
}

// epilogue: acc + bias (+onehot) (+relu) -> fp16 into 256B-row A
__device__ __forceinline__ void epi16(char* Ab, float (&acc)[4][4][4],
                                      const float* __restrict__ bias,
                                      const float* __restrict__ sOne, const int* __restrict__ sBk,
                                      bool relu, int mrow0, int ncol0, int lane) {
    int gr = lane >> 2, q2 = (lane & 3) * 2;
#pragma unroll
    for (int mt = 0; mt < 4; mt++) {
        int r0 = mrow0 + mt * 16 + gr, r1 = r0 + 8;
        const float* oA = sOne ? (sOne + sBk[r0] * 132) : (const float*)0;
        const float* oB = sOne ? (sOne + sBk[r1] * 132) : (const float*)0;
#pragma unroll
        for (int nt = 0; nt < 4; nt++) {
            int c = ncol0 + nt * 8 + q2;
            float v0 = acc[mt][nt][0] + bias[c], v1 = acc[mt][nt][1] + bias[c + 1];
            float w0 = acc[mt][nt][2] + bias[c], w1 = acc[mt][nt][3] + bias[c + 1];
            if (oA) { v0 += oA[c]; v1 += oA[c + 1]; }
            if (oB) { w0 += oB[c]; w1 += oB[c + 1]; }
            if (relu) { v0 = fmaxf(v0, 0.f); v1 = fmaxf(v1, 0.f); w0 = fmaxf(w0, 0.f); w1 = fmaxf(w1, 0.f); }
            *(u32*)(Ab + a_off(r0, c)) = pack_h2(v0, v1);
            *(u32*)(Ab + a_off(r1, c)) = pack_h2(w0, w1);
        }
    }
}

__device__ __forceinline__ void load_img(u32 slot, const u16* src, int tid) {
    const uint4* s = (const uint4*)src;
    for (int i = tid; i < 2048; i += 256) cpa16(slot + i * 16, s + i);
}

// ---------------- fused prep (weights -> fp16 swizzled images) + root encoder ----------------
__global__ void prep_root_kernel(const float* __restrict__ W_in, const float* __restrict__ Wg1,
                                 const float* __restrict__ Wg2, const float* __restrict__ Wm1,
                                 const float* __restrict__ Wm2, const float* __restrict__ Wout,
                                 const float* __restrict__ Wattn,
                                 const float* __restrict__ root_repr,
                                 const float* __restrict__ W_root,
                                 const float* __restrict__ b_root) {
    int tid = threadIdx.x;
    if (blockIdx.x < 448) {
        int idx = blockIdx.x * 256 + tid;
        int img = idx >> 14, r = idx & 16383, n = r >> 7, k = r & 127;
        float w = 0.f;
        if (img == 0)      { w = (k < FEAT) ? W_in[k * H + n] : 0.f; }
        else if (img == 1) w = Wg1[k * H + n];
        else if (img == 2) w = Wg2[k * H + n];
        else if (img == 3) w = Wm1[k * H + n] + Wm1[(H + k) * H + n];
        else if (img == 4) w = Wm1[(2 * H + k) * H + n] - Wm1[(H + k) * H + n];
        else if (img == 5) w = Wm2[k * H + n];
        else               w = (n < 13) ? Wout[k * 13 + n] : ((n < 26) ? Wattn[k * 13 + (n - 13)] : 0.f);
        int off = n * 128 + (((k >> 3) ^ (n & 7)) << 3) + (k & 7);
        g_imgs[img * 16384 + off] = __half_as_ushort(__float2half_rn(w));
    } else {
        __shared__ float sX[2][FEAT];
        int half = tid >> 7, n = tid & 127;
        int r = (blockIdx.x - 448) * 2 + half;
        for (int k = n; k < FEAT; k += 128) sX[half][k] = root_repr[r * FEAT + k];
        __syncthreads();
        float s = b_root[n];
#pragma unroll 2
        for (int k = 0; k < FEAT; k++) s += sX[half][k] * W_root[k * H + n];
        g_root_emb[r * H + n] = fmaxf(s, 0.f);
    }
}

// ---------------- node chain: fp16 single-pass, double-buffered W, 2 CTAs/SM ----------------
__global__ __launch_bounds__(256, 2) void node_chain_kernel(
    const float* __restrict__ node_h, const int* __restrict__ seg,
    const float* __restrict__ b_in, const float* __restrict__ b_g1,
    const float* __restrict__ b_g2) {
    extern __shared__ __align__(16) char Ab[];
    __shared__ float sB[3][128];
    __shared__ int sSeg[128];

    int tid = threadIdx.x, lane = tid & 31, w = tid >> 5;
    int mrow0 = (w >> 2) * 64, ncol0 = (w & 3) * 32;
    int tilebase = blockIdx.x * 128;          // NN = 6250 * 128
    u32 smA = smem_u32(Ab);
    u32 S0 = smA + S0_OFF, S1 = smA + S1_OFF;

    load_img(S0, g_imgs, tid);           CPA_COMMIT();   // G1 = W0
    load_img(S1, g_imgs + 16384, tid);   CPA_COMMIT();   // G2 = W1

    if (tid < 128) { sSeg[tid] = seg[tilebase + tid];
                     sB[0][tid] = b_in[tid]; sB[1][tid] = b_g1[tid]; sB[2][tid] = b_g2[tid]; }

    // zero pad cols 86..95, stage node_h fp16
    for (int i = tid; i < 128 * 5; i += 256) {
        int m = i / 5, k = 86 + (i - 5 * (i / 5)) * 2;
        *(u32*)(Ab + a_off(m, k)) = 0;
    }
    for (int idx = tid; idx < 128 * 43; idx += 256) {
        int m = idx / 43, k = (idx - m * 43) * 2;
        float2 v = *(const float2*)(node_h + (size_t)(tilebase + m) * FEAT + k);
        *(u32*)(Ab + a_off(m, k)) = pack_h2(v.x, v.y);
    }
    CPA_WAIT1(); __syncthreads();        // W0 ready

    int rowA = mrow0 + (lane & 15);
    u32 aRow0 = smA + rowA * 256; int aXor = rowA & 7; int aSel = lane >> 4;
    int rowB = ncol0 + (lane & 7) + ((lane >> 4) << 3);
    u32 wOff = rowB * 256; int wXor = rowB & 7; int wSel = (lane >> 3) & 1;

    float acc[4][4][4];

    // ---- L0 (K=96) ----
    acc_zero(acc);
    mma_pass<6>(acc, aRow0, aXor, aSel, S0 + wOff, wXor, wSel);
    __syncthreads();
    load_img(S0, g_imgs + 2 * 16384, tid); CPA_COMMIT();   // G3 = W2 -> slot0
    epi16(Ab, acc, sB[0], (const float*)0, (const int*)0, false, mrow0, ncol0, lane);
    CPA_WAIT1(); __syncthreads();        // W1 ready (G3 may pend)

    // ---- L1 ----
    acc_zero(acc);
    mma_pass<8>(acc, aRow0, aXor, aSel, S1 + wOff, wXor, wSel);
    __syncthreads();
    epi16(Ab, acc, sB[1], (const float*)0, (const int*)0, true, mrow0, ncol0, lane);
    CPA_WAIT0(); __syncthreads();        // W2 ready

    // ---- L2 -> pool ----
    acc_zero(acc);
    mma_pass<8>(acc, aRow0, aXor, aSel, S0 + wOff, wXor, wSel);
    __syncthreads();
    {
        // pool fp32, swizzled 512B rows, overlays A + slot0 (64 KB)
        int gr = lane >> 2, q2 = (lane & 3) * 2;
#pragma unroll
        for (int mt = 0; mt < 4; mt++) {
            int r0 = mrow0 + mt * 16 + gr, r1 = r0 + 8;
#pragma unroll
            for (int nt = 0; nt < 4; nt++) {
                int c = ncol0 + nt * 8 + q2;
                *(float2*)(Ab + p_off(r0, c)) =
                    make_float2(fmaxf(acc[mt][nt][0] + sB[2][c], 0.f),
                                fmaxf(acc[mt][nt][1] + sB[2][c + 1], 0.f));
                *(float2*)(Ab + p_off(r1, c)) =
                    make_float2(fmaxf(acc[mt][nt][2] + sB[2][c], 0.f),
                                fmaxf(acc[mt][nt][3] + sB[2][c + 1], 0.f));
            }
        }
    }
    __syncthreads();

    // sorted-segment run-length pooling (atomics tolerate any row partition)
    {
        int col = tid & 127, hh = tid >> 7;       // 2 row-halves x 128 cols
        int r0 = hh * 64;
        float r = 0.f; int cur = sSeg[r0];
        for (int m = r0; m < r0 + 64; m++) {
            int s = sSeg[m];
            if (s != cur) { atomicAdd(&g_frag_sum[(size_t)cur * H + col], r); r = 0.f; cur = s; }
            r += *(const float*)(Ab + p_off(m, col));
        }
        atomicAdd(&g_frag_sum[(size_t)cur * H + col], r);
    }
    if (tid < 8) {                                 // counts: 8 chunks of 16 rows
        int r0 = tid * 16;
        float c = 0.f; int cur = sSeg[r0];
        for (int m = r0; m < r0 + 16; m++) {
            int s = sSeg[m];
            if (s != cur) { atomicAdd(&g_cnt[cur], c); c = 0.f; cur = s; }
            c += 1.f;
        }
        atomicAdd(&g_cnt[cur], c);
    }
}

// ---------------- fragment head: fp16 single-pass, double-buffered W, 2 CTAs/SM ----------------
__global__ __launch_bounds__(256, 2) void frag_mlp_kernel(
    const int* __restrict__ ind_maps, const int* __restrict__ broken,
    const float* __restrict__ W_m1, const float* __restrict__ b_m1,
    const float* __restrict__ b_m2, const float* __restrict__ b_out,
    const float* __restrict__ b_attn, float* __restrict__ out) {
    extern __shared__ __align__(16) char Ab[];
    __shared__ int sInd[128]; __shared__ float sInv[128]; __shared__ int sBk[128];
    __shared__ float sB1[128], sB2[128], sBo[26];
    __shared__ float sOne[13 * 132];

    int tid = threadIdx.x, lane = tid & 31, w = tid >> 5;
    int mrow0 = (w >> 2) * 64, ncol0 = (w & 3) * 32;
    int base = blockIdx.x * 128;
    u32 smA = smem_u32(Ab);
    u32 S0 = smA + S0_OFF, S1 = smA + S1_OFF;

    load_img(S0, g_imgs + 3 * 16384, tid); CPA_COMMIT();   // G1 = Wa
    load_img(S1, g_imgs + 4 * 16384, tid); CPA_COMMIT();   // G2 = Wb

    if (tid < 128) {
        int f = base + tid;
        sInd[tid] = (f < NF) ? ind_maps[f] : 0;
        sInv[tid] = (f < NF) ? 1.f / fmaxf(g_cnt[f], 1.f) : 0.f;
        int b = (f < NF) ? broken[f] : 0;
        sBk[tid] = min(max(b, 0), 12);
        sB1[tid] = b_m1[tid]; sB2[tid] = b_m2[tid];
    }
    if (tid < 26) sBo[tid] = (tid < 13) ? b_out[tid] : b_attn[tid - 13];
    for (int i = tid; i < 13 * 128; i += 256) {
        int rr = i >> 7, c = i & 127;
        sOne[rr * 132 + c] = W_m1[(size_t)(384 + rr) * H + c];
    }
    __syncthreads();

    // stage ext-root rows (fp16)
    for (int idx = tid; idx < 128 * 64; idx += 256) {
        int m = idx >> 6, k = (idx & 63) * 2;
        float2 v = *(const float2*)(g_root_emb + (size_t)sInd[m] * H + k);
        *(u32*)(Ab + a_off(m, k)) = pack_h2(v.x, v.y);
    }
    CPA_WAIT1(); __syncthreads();        // Wa ready

    int rowA = mrow0 + (lane & 15);
    u32 aRow0 = smA + rowA * 256; int aXor = rowA & 7; int aSel = lane >> 4;
    int rowB = ncol0 + (lane & 7) + ((lane >> 4) << 3);
    u32 wOff = rowB * 256; int wXor = rowB & 7; int wSel = (lane >> 3) & 1;

    float acc[4][4][4];
    acc_zero(acc);

    // ---- L1a: ext @ Wa ----
    mma_pass<8>(acc, aRow0, aXor, aSel, S0 + wOff, wXor, wSel);
    __syncthreads();
    load_img(S0, g_imgs + 5 * 16384, tid); CPA_COMMIT();   // G3 = Wm2 -> slot0
    // restage A = mean rows
    for (int idx = tid; idx < 128 * 64; idx += 256) {
        int m = idx >> 6, k = (idx & 63) * 2;
        int f = base + m;
        float2 v = make_float2(0.f, 0.f);
        if (f < NF) {
            v = *(const float2*)(g_frag_sum + (size_t)f * H + k);
            v.x *= sInv[m]; v.y *= sInv[m];
        }
        *(u32*)(Ab + a_off(m, k)) = pack_h2(v.x, v.y);
    }
    CPA_WAIT1(); __syncthreads();        // Wb ready

    // ---- L1b: += mean @ Wb ----
    mma_pass<8>(acc, aRow0, aXor, aSel, S1 + wOff, wXor, wSel);
    __syncthreads();
    load_img(S1, g_imgs + 6 * 16384, tid); CPA_COMMIT();   // G4 = Wout -> slot1
    epi16(Ab, acc, sB1, sOne, sBk, true, mrow0, ncol0, lane);
    CPA_WAIT1(); __syncthreads();        // Wm2 ready

    // ---- L2 ----
    acc_zero(acc);
    mma_pass<8>(acc, aRow0, aXor, aSel, S0 + wOff, wXor, wSel);
    __syncthreads();
    epi16(Ab, acc, sB2, (const float*)0, (const int*)0, true, mrow0, ncol0, lane);
    CPA_WAIT0(); __syncthreads();        // Wout ready

    // ---- out layer: cols 0..25 (warps with ncol0==0) ----
    if (ncol0 == 0) {
        acc_zero(acc);
        mma_pass<8>(acc, aRow0, aXor, aSel, S1 + wOff, wXor, wSel);
        int gr = lane >> 2, q2 = (lane & 3) * 2;
#pragma unroll
        for (int mt = 0; mt < 4; mt++) {
            int r0 = mrow0 + mt * 16 + gr, r1 = r0 + 8;
            int fA = base + r0, fB = base + r1;
#pragma unroll
            for (int nt = 0; nt < 4; nt++) {
#pragma unroll
                for (int e = 0; e < 2; e++) {
                    int c = nt * 8 + q2 + e;
                    if (c >= 26) continue;
                    if (fA < NF) {
                        float v = acc[mt][nt][e] + sBo[c];
                        if (c < 13) out[(size_t)fA * 13 + c] = 1.f / (1.f + __expf(-v));
                        else        out[(size_t)NF * 13 + (size_t)fA * 13 + (c - 13)] = v;
                    }
                    if (fB < NF) {
                        float v = acc[mt][nt][2 + e] + sBo[c];
                        if (c < 13) out[(size_t)fB * 13 + c] = 1.f / (1.f + __expf(-v));
                        else        out[(size_t)NF * 13 + (size_t)fB * 13 + (c - 13)] = v;
                    }
                }
            }
        }
    }
}

// ---------------- launcher ----------------
extern "C" void kernel_launch(void* const* d_in, const int* in_sizes, int n_in,
                              void* d_out, int out_size) {
    const float* node_h    = (const float*)d_in[0];
    const int*   seg       = (const int*)d_in[1];
    const float* root_repr = (const float*)d_in[2];
    const int*   ind_maps  = (const int*)d_in[3];
    const int*   broken    = (const int*)d_in[4];
    const float* W_root = (const float*)d_in[5];  const float* b_root = (const float*)d_in[6];
    const float* W_in   = (const float*)d_in[7];  const float* b_in   = (const float*)d_in[8];
    const float* W_g1   = (const float*)d_in[9];  const float* b_g1   = (const float*)d_in[10];
    const float* W_g2   = (const float*)d_in[11]; const float* b_g2   = (const float*)d_in[12];
    const float* W_m1   = (const float*)d_in[13]; const float* b_m1   = (const float*)d_in[14];
    const float* W_m2   = (const float*)d_in[15]; const float* b_m2   = (const float*)d_in[16];
    const float* W_out  = (const float*)d_in[17]; const float* b_out  = (const float*)d_in[18];
    const float* W_attn = (const float*)d_in[19]; const float* b_attn = (const float*)d_in[20];
    float* out = (float*)d_out;

    void* p = 0;
    cudaGetSymbolAddress(&p, g_frag_sum);
    cudaMemsetAsync(p, 0, (size_t)NF * H * sizeof(float), 0);
    cudaGetSymbolAddress(&p, g_cnt);
    cudaMemsetAsync(p, 0, (size_t)NF * sizeof(float), 0);

    cudaFuncSetAttribute(node_chain_kernel, cudaFuncAttributeMaxDynamicSharedMemorySize, DYN);
    cudaFuncSetAttribute(frag_mlp_kernel,   cudaFuncAttributeMaxDynamicSharedMemorySize, DYN);

    prep_root_kernel<<<448 + NR / 2, 256>>>(W_in, W_g1, W_g2, W_m1, W_m2, W_out, W_attn,
                                            root_repr, W_root, b_root);
    node_chain_kernel<<<NN / 128, 256, DYN>>>(node_h, seg, b_in, b_g1, b_g2);
    frag_mlp_kernel<<<(NF + 127) / 128, 256, DYN>>>(ind_maps, broken, W_m1, b_m1,
                                                    b_m2, b_out, b_attn, out);
}

// round 12
// speedup vs baseline: 5.8227x; 1.0559x over previous
#include <cuda_runtime.h>
#include <cuda_fp16.h>

typedef unsigned int u32; typedef unsigned short u16;

#define NN   800000
#define NF   100000
#define NR   2000
#define FEAT 86
#define H    128
#define NTILE_NODE 6250
#define NTILE_FRAG 782

#define A_B    32768            // A: 128 rows x 256 B (fp16)
#define S0_OFF 32768
#define S1_OFF 65536
#define DYN    98304            // A + 2 W slots -> 2 CTAs/SM

// ---------------- device scratch ----------------
__device__ __align__(16) u16   g_imgs[7 * 16384];   // fp16 weight images, swizzled, transposed
__device__ __align__(16) float g_root_emb[NR * H];
__device__ __align__(16) float g_frag_sum[(size_t)NF * H];
__device__ __align__(16) float g_cnt[NF];

// ---------------- helpers ----------------
__device__ __forceinline__ u32 smem_u32(const void* p) {
    u32 a; asm("{ .reg .u64 t; cvta.to.shared.u64 t, %1; cvt.u32.u64 %0, t; }" : "=r"(a) : "l"(p));
    return a;
}
__device__ __forceinline__ void cpa16(u32 dst, const void* src) {
    asm volatile("cp.async.ca.shared.global [%0], [%1], 16;" :: "r"(dst), "l"(src));
}
#define CPA_COMMIT() asm volatile("cp.async.commit_group;" ::: "memory")
#define CPA_WAIT0()  asm volatile("cp.async.wait_group 0;" ::: "memory")
#define CPA_WAIT1()  asm volatile("cp.async.wait_group 1;" ::: "memory")

#define LDSM4(d0, d1, d2, d3, a) \
    asm volatile("ldmatrix.sync.aligned.m8n8.x4.shared.b16 {%0,%1,%2,%3}, [%4];" \
                 : "=r"(d0), "=r"(d1), "=r"(d2), "=r"(d3) : "r"(a))

__device__ __forceinline__ u32 pack_h2(float v0, float v1) {
    __half2 h = __floats2half2_rn(v0, v1);
    return *(u32*)&h;
}
__device__ __forceinline__ void mma16816(float* c, u32 a0, u32 a1, u32 a2, u32 a3, u32 b0, u32 b1) {
    asm volatile("mma.sync.aligned.m16n8k16.row.col.f32.f16.f16.f32 "
                 "{%0,%1,%2,%3}, {%4,%5,%6,%7}, {%8,%9}, {%0,%1,%2,%3};"
                 : "+f"(c[0]), "+f"(c[1]), "+f"(c[2]), "+f"(c[3])
                 : "r"(a0), "r"(a1), "r"(a2), "r"(a3), "r"(b0), "r"(b1));
}

// swizzled byte offset, 256 B rows: chunk16 ^ (row & 7)
__device__ __forceinline__ int a_off(int r, int c) {      // c = u16 col 0..127
    return r * 256 + (((c >> 3) ^ (r & 7)) << 4) + (c & 7) * 2;
}
// pool: fp32, 512 B rows, 16B-chunk XOR swizzle
__device__ __forceinline__ int p_off(int r, int c) {      // c = f32 col 0..127
    return r * 512 + (((c >> 2) ^ (r & 7)) << 4) + (c & 3) * 4;
}

// ---------------- fully-unrolled GEMM pass: warp tile 64 x 32 ----------------
template<int NK>
__device__ __forceinline__ void mma_pass(float (&acc)[4][4][4],
                                         u32 aRow0, int aXor, int aSel,
                                         u32 wRow0, int wXor, int wSel) {
#pragma unroll
    for (int ks = 0; ks < NK; ks++) {
        u32 a[4][4];
#pragma unroll
        for (int mt = 0; mt < 4; mt++) {
            u32 ad = aRow0 + mt * 4096 + (u32)((((aSel + 2 * ks) ^ aXor) << 4));
            LDSM4(a[mt][0], a[mt][1], a[mt][2], a[mt][3], ad);
        }
        u32 b[2][4];
#pragma unroll
        for (int nb = 0; nb < 2; nb++) {
            u32 bd = wRow0 + nb * 4096 + (u32)((((2 * ks + wSel) ^ wXor) << 4));
            LDSM4(b[nb][0], b[nb][1], b[nb][2], b[nb][3], bd);
        }
#pragma unroll
        for (int mt = 0; mt < 4; mt++)
#pragma unroll
            for (int nb = 0; nb < 2; nb++) {
                mma16816(acc[mt][2 * nb + 0], a[mt][0], a[mt][1], a[mt][2], a[mt][3], b[nb][0], b[nb][1]);
                mma16816(acc[mt][2 * nb + 1], a[mt][0], a[mt][1], a[mt][2], a[mt][3], b[nb][2], b[nb][3]);
            }
    }
}
__device__ __forceinline__ void acc_zero(float (&acc)[4][4][4]) {
#pragma unroll
    for (int mt = 0; mt < 4; mt++)
#pragma unroll
        for (int nt = 0; nt < 4; nt++)
#pragma unroll
            for (int e = 0; e < 4; e++) acc[mt][nt][e] = 0.f;
}

// epilogue: acc + bias (+onehot) (+relu) -> fp16 into 256B-row A
__device__ __forceinline__ void epi16(char* Ab, float (&acc)[4][4][4],
                                      const float* __restrict__ bias,
                                      const float* __restrict__ sOne, const int* __restrict__ sBk,
                                      bool relu, int mrow0, int ncol0, int lane) {
    int gr = lane >> 2, q2 = (lane & 3) * 2;
#pragma unroll
    for (int mt = 0; mt < 4; mt++) {
        int r0 = mrow0 + mt * 16 + gr, r1 = r0 + 8;
        const float* oA = sOne ? (sOne + sBk[r0] * 132) : (const float*)0;
        const float* oB = sOne ? (sOne + sBk[r1] * 132) : (const float*)0;
#pragma unroll
        for (int nt = 0; nt < 4; nt++) {
            int c = ncol0 + nt * 8 + q2;
            float v0 = acc[mt][nt][0] + bias[c], v1 = acc[mt][nt][1] + bias[c + 1];
            float w0 = acc[mt][nt][2] + bias[c], w1 = acc[mt][nt][3] + bias[c + 1];
            if (oA) { v0 += oA[c]; v1 += oA[c + 1]; }
            if (oB) { w0 += oB[c]; w1 += oB[c + 1]; }
            if (relu) { v0 = fmaxf(v0, 0.f); v1 = fmaxf(v1, 0.f); w0 = fmaxf(w0, 0.f); w1 = fmaxf(w1, 0.f); }
            *(u32*)(Ab + a_off(r0, c)) = pack_h2(v0, v1);
            *(u32*)(Ab + a_off(r1, c)) = pack_h2(w0, w1);
        }
    }
}

__device__ __forceinline__ void load_img(u32 slot, const u16* src, int tid) {
    const uint4* s = (const uint4*)src;
    for (int i = tid; i < 2048; i += 256) cpa16(slot + i * 16, s + i);
}

// ---------------- fused prep + root encoder + scratch zeroing ----------------
#define PREP_IMG_B 448
#define PREP_ROOT_B (NR / 2)
#define PREP_ZERO_B 2048
__global__ void prep_root_kernel(const float* __restrict__ W_in, const float* __restrict__ Wg1,
                                 const float* __restrict__ Wg2, const float* __restrict__ Wm1,
                                 const float* __restrict__ Wm2, const float* __restrict__ Wout,
                                 const float* __restrict__ Wattn,
                                 const float* __restrict__ root_repr,
                                 const float* __restrict__ W_root,
                                 const float* __restrict__ b_root) {
    int tid = threadIdx.x;
    if (blockIdx.x < PREP_IMG_B) {
        int idx = blockIdx.x * 256 + tid;
        int img = idx >> 14, r = idx & 16383, n = r >> 7, k = r & 127;
        float w = 0.f;
        if (img == 0)      { w = (k < FEAT) ? W_in[k * H + n] : 0.f; }
        else if (img == 1) w = Wg1[k * H + n];
        else if (img == 2) w = Wg2[k * H + n];
        else if (img == 3) w = Wm1[k * H + n] + Wm1[(H + k) * H + n];
        else if (img == 4) w = Wm1[(2 * H + k) * H + n] - Wm1[(H + k) * H + n];
        else if (img == 5) w = Wm2[k * H + n];
        else               w = (n < 13) ? Wout[k * 13 + n] : ((n < 26) ? Wattn[k * 13 + (n - 13)] : 0.f);
        int off = n * 128 + (((k >> 3) ^ (n & 7)) << 3) + (k & 7);
        g_imgs[img * 16384 + off] = __half_as_ushort(__float2half_rn(w));
    } else if (blockIdx.x < PREP_IMG_B + PREP_ROOT_B) {
        __shared__ float sX[2][FEAT];
        int half = tid >> 7, n = tid & 127;
        int r = (blockIdx.x - PREP_IMG_B) * 2 + half;
        for (int k = n; k < FEAT; k += 128) sX[half][k] = root_repr[r * FEAT + k];
        __syncthreads();
        float s = b_root[n];
#pragma unroll 2
        for (int k = 0; k < FEAT; k++) s += sX[half][k] * W_root[k * H + n];
        g_root_emb[r * H + n] = fmaxf(s, 0.f);
    } else {
        // zero g_frag_sum (3.2M uint4) + g_cnt (25k uint4)
        int zb = blockIdx.x - PREP_IMG_B - PREP_ROOT_B;
        uint4 z = make_uint4(0, 0, 0, 0);
        uint4* fs = (uint4*)g_frag_sum;
        const int NFS = (int)(((size_t)NF * H) / 4);
        for (int i = zb * 256 + tid; i < NFS; i += PREP_ZERO_B * 256) fs[i] = z;
        uint4* ct = (uint4*)g_cnt;
        for (int i = zb * 256 + tid; i < NF / 4; i += PREP_ZERO_B * 256) ct[i] = z;
    }
}

// ---------------- node chain: persistent, fp16 single-pass ----------------
__global__ __launch_bounds__(256, 2) void node_chain_kernel(
    const float* __restrict__ node_h, const int* __restrict__ seg,
    const float* __restrict__ b_in, const float* __restrict__ b_g1,
    const float* __restrict__ b_g2) {
    extern __shared__ __align__(16) char Ab[];
    __shared__ float sB[3][128];
    __shared__ int sSeg[128];

    int tid = threadIdx.x, lane = tid & 31, w = tid >> 5;
    int mrow0 = (w >> 2) * 64, ncol0 = (w & 3) * 32;
    u32 smA = smem_u32(Ab);
    u32 S0 = smA + S0_OFF, S1 = smA + S1_OFF;

    load_img(S0, g_imgs, tid);           CPA_COMMIT();   // W0
    load_img(S1, g_imgs + 16384, tid);   CPA_COMMIT();   // W1 (resident forever)

    if (tid < 128) { sB[0][tid] = b_in[tid]; sB[1][tid] = b_g1[tid]; sB[2][tid] = b_g2[tid]; }

    int rowA = mrow0 + (lane & 15);
    u32 aRow0 = smA + rowA * 256; int aXor = rowA & 7; int aSel = lane >> 4;
    int rowB = ncol0 + (lane & 7) + ((lane >> 4) << 3);
    u32 wOff = rowB * 256; int wXor = rowB & 7; int wSel = (lane >> 3) & 1;

    for (int tile = blockIdx.x; tile < NTILE_NODE; tile += gridDim.x) {
        int tilebase = tile * 128;
        bool more = (tile + gridDim.x) < NTILE_NODE;

        if (tid < 128) sSeg[tid] = seg[tilebase + tid];
        for (int i = tid; i < 128 * 5; i += 256) {
            int m = i / 5, k = 86 + (i - 5 * (i / 5)) * 2;
            *(u32*)(Ab + a_off(m, k)) = 0;
        }
        for (int idx = tid; idx < 128 * 43; idx += 256) {
            int m = idx / 43, k = (idx - m * 43) * 2;
            float2 v = *(const float2*)(node_h + (size_t)(tilebase + m) * FEAT + k);
            *(u32*)(Ab + a_off(m, k)) = pack_h2(v.x, v.y);
        }
        CPA_WAIT0(); __syncthreads();       // W0 (and first-tile W1) ready

        float acc[4][4][4];

        // ---- L0 (K=96) ----
        acc_zero(acc);
        mma_pass<6>(acc, aRow0, aXor, aSel, S0 + wOff, wXor, wSel);
        __syncthreads();
        load_img(S0, g_imgs + 2 * 16384, tid); CPA_COMMIT();   // W2 -> S0
        epi16(Ab, acc, sB[0], (const float*)0, (const int*)0, false, mrow0, ncol0, lane);
        __syncthreads();

        // ---- L1 (W1 resident in S1) ----
        acc_zero(acc);
        mma_pass<8>(acc, aRow0, aXor, aSel, S1 + wOff, wXor, wSel);
        __syncthreads();
        epi16(Ab, acc, sB[1], (const float*)0, (const int*)0, true, mrow0, ncol0, lane);
        CPA_WAIT0(); __syncthreads();       // W2 ready

        // ---- L2 -> pool ----
        acc_zero(acc);
        mma_pass<8>(acc, aRow0, aXor, aSel, S0 + wOff, wXor, wSel);
        __syncthreads();
        {
            int gr = lane >> 2, q2 = (lane & 3) * 2;
#pragma unroll
            for (int mt = 0; mt < 4; mt++) {
                int r0 = mrow0 + mt * 16 + gr, r1 = r0 + 8;
#pragma unroll
                for (int nt = 0; nt < 4; nt++) {
                    int c = ncol0 + nt * 8 + q2;
                    *(float2*)(Ab + p_off(r0, c)) =
                        make_float2(fmaxf(acc[mt][nt][0] + sB[2][c], 0.f),
                                    fmaxf(acc[mt][nt][1] + sB[2][c + 1], 0.f));
                    *(float2*)(Ab + p_off(r1, c)) =
                        make_float2(fmaxf(acc[mt][nt][2] + sB[2][c], 0.f),
                                    fmaxf(acc[mt][nt][3] + sB[2][c + 1], 0.f));
                }
            }
        }
        __syncthreads();

        // sorted-segment run-length pooling
        {
            int col = tid & 127, hh = tid >> 7;
            int r0 = hh * 64;
            float r = 0.f; int cur = sSeg[r0];
            for (int m = r0; m < r0 + 64; m++) {
                int s = sSeg[m];
                if (s != cur) { atomicAdd(&g_frag_sum[(size_t)cur * H + col], r); r = 0.f; cur = s; }
                r += *(const float*)(Ab + p_off(m, col));
            }
            atomicAdd(&g_frag_sum[(size_t)cur * H + col], r);
        }
        if (tid < 8) {
            int r0 = tid * 16;
            float c = 0.f; int cur = sSeg[r0];
            for (int m = r0; m < r0 + 16; m++) {
                int s = sSeg[m];
                if (s != cur) { atomicAdd(&g_cnt[cur], c); c = 0.f; cur = s; }
                c += 1.f;
            }
            atomicAdd(&g_cnt[cur], c);
        }
        __syncthreads();
        if (more) { load_img(S0, g_imgs, tid); CPA_COMMIT(); }   // W0 reload under next stage
    }
}

// ---------------- fragment head: persistent, fp16 single-pass ----------------
__global__ __launch_bounds__(256, 2) void frag_mlp_kernel(
    const int* __restrict__ ind_maps, const int* __restrict__ broken,
    const float* __restrict__ W_m1, const float* __restrict__ b_m1,
    const float* __restrict__ b_m2, const float* __restrict__ b_out,
    const float* __restrict__ b_attn, float* __restrict__ out) {
    extern __shared__ __align__(16) char Ab[];
    __shared__ int sInd[128]; __shared__ float sInv[128]; __shared__ int sBk[128];
    __shared__ float sB1[128], sB2[128], sBo[26];
    __shared__ float sOne[13 * 132];

    int tid = threadIdx.x, lane = tid & 31, w = tid >> 5;
    int mrow0 = (w >> 2) * 64, ncol0 = (w & 3) * 32;
    u32 smA = smem_u32(Ab);
    u32 S0 = smA + S0_OFF, S1 = smA + S1_OFF;

    load_img(S0, g_imgs + 3 * 16384, tid); CPA_COMMIT();   // Wa
    load_img(S1, g_imgs + 4 * 16384, tid); CPA_COMMIT();   // Wb

    if (tid < 128) { sB1[tid] = b_m1[tid]; sB2[tid] = b_m2[tid]; }
    if (tid < 26) sBo[tid] = (tid < 13) ? b_out[tid] : b_attn[tid - 13];
    for (int i = tid; i < 13 * 128; i += 256) {
        int rr = i >> 7, c = i & 127;
        sOne[rr * 132 + c] = W_m1[(size_t)(384 + rr) * H + c];
    }

    int rowA = mrow0 + (lane & 15);
    u32 aRow0 = smA + rowA * 256; int aXor = rowA & 7; int aSel = lane >> 4;
    int rowB = ncol0 + (lane & 7) + ((lane >> 4) << 3);
    u32 wOff = rowB * 256; int wXor = rowB & 7; int wSel = (lane >> 3) & 1;

    for (int tile = blockIdx.x; tile < NTILE_FRAG; tile += gridDim.x) {
        int base = tile * 128;
        bool more = (tile + gridDim.x) < NTILE_FRAG;

        if (tid < 128) {
            int f = base + tid;
            sInd[tid] = (f < NF) ? ind_maps[f] : 0;
            sInv[tid] = (f < NF) ? 1.f / fmaxf(g_cnt[f], 1.f) : 0.f;
            int b = (f < NF) ? broken[f] : 0;
            sBk[tid] = min(max(b, 0), 12);
        }
        __syncthreads();

        // stage ext-root rows
        for (int idx = tid; idx < 128 * 64; idx += 256) {
            int m = idx >> 6, k = (idx & 63) * 2;
            float2 v = *(const float2*)(g_root_emb + (size_t)sInd[m] * H + k);
            *(u32*)(Ab + a_off(m, k)) = pack_h2(v.x, v.y);
        }
        CPA_WAIT0(); __syncthreads();       // Wa, Wb ready

        float acc[4][4][4];
        acc_zero(acc);

        // ---- L1a: ext @ Wa ----
        mma_pass<8>(acc, aRow0, aXor, aSel, S0 + wOff, wXor, wSel);
        __syncthreads();
        load_img(S0, g_imgs + 5 * 16384, tid); CPA_COMMIT();   // Wm2 -> S0
        for (int idx = tid; idx < 128 * 64; idx += 256) {      // restage A = mean rows
            int m = idx >> 6, k = (idx & 63) * 2;
            int f = base + m;
            float2 v = make_float2(0.f, 0.f);
            if (f < NF) {
                v = *(const float2*)(g_frag_sum + (size_t)f * H + k);
                v.x *= sInv[m]; v.y *= sInv[m];
            }
            *(u32*)(Ab + a_off(m, k)) = pack_h2(v.x, v.y);
        }
        __syncthreads();

        // ---- L1b: += mean @ Wb ----
        mma_pass<8>(acc, aRow0, aXor, aSel, S1 + wOff, wXor, wSel);
        __syncthreads();
        load_img(S1, g_imgs + 6 * 16384, tid); CPA_COMMIT();   // Wout -> S1
        epi16(Ab, acc, sB1, sOne, sBk, true, mrow0, ncol0, lane);
        CPA_WAIT1(); __syncthreads();       // Wm2 ready (FIFO)

        // ---- L2 ----
        acc_zero(acc);
        mma_pass<8>(acc, aRow0, aXor, aSel, S0 + wOff, wXor, wSel);
        __syncthreads();
        epi16(Ab, acc, sB2, (const float*)0, (const int*)0, true, mrow0, ncol0, lane);
        CPA_WAIT0(); __syncthreads();       // Wout ready

        // ---- out layer: cols 0..25 ----
        if (ncol0 == 0) {
            acc_zero(acc);
            mma_pass<8>(acc, aRow0, aXor, aSel, S1 + wOff, wXor, wSel);
            int gr = lane >> 2, q2 = (lane & 3) * 2;
#pragma unroll
            for (int mt = 0; mt < 4; mt++) {
                int r0 = mrow0 + mt * 16 + gr, r1 = r0 + 8;
                int fA = base + r0, fB = base + r1;
#pragma unroll
                for (int nt = 0; nt < 4; nt++) {
#pragma unroll
                    for (int e = 0; e < 2; e++) {
                        int c = nt * 8 + q2 + e;
                        if (c >= 26) continue;
                        if (fA < NF) {
                            float v = acc[mt][nt][e] + sBo[c];
                            if (c < 13) out[(size_t)fA * 13 + c] = 1.f / (1.f + __expf(-v));
                            else        out[(size_t)NF * 13 + (size_t)fA * 13 + (c - 13)] = v;
                        }
                        if (fB < NF) {
                            float v = acc[mt][nt][2 + e] + sBo[c];
                            if (c < 13) out[(size_t)fB * 13 + c] = 1.f / (1.f + __expf(-v));
                            else        out[(size_t)NF * 13 + (size_t)fB * 13 + (c - 13)] = v;
                        }
                    }
                }
            }
        }
        __syncthreads();
        if (more) {
            load_img(S0, g_imgs + 3 * 16384, tid); CPA_COMMIT();   // Wa
            load_img(S1, g_imgs + 4 * 16384, tid); CPA_COMMIT();   // Wb
        }
    }
}

// ---------------- launcher ----------------
extern "C" void kernel_launch(void* const* d_in, const int* in_sizes, int n_in,
                              void* d_out, int out_size) {
    const float* node_h    = (const float*)d_in[0];
    const int*   seg       = (const int*)d_in[1];
    const float* root_repr = (const float*)d_in[2];
    const int*   ind_maps  = (const int*)d_in[3];
    const int*   broken    = (const int*)d_in[4];
    const float* W_root = (const float*)d_in[5];  const float* b_root = (const float*)d_in[6];
    const float* W_in   = (const float*)d_in[7];  const float* b_in   = (const float*)d_in[8];
    const float* W_g1   = (const float*)d_in[9];  const float* b_g1   = (const float*)d_in[10];
    const float* W_g2   = (const float*)d_in[11]; const float* b_g2   = (const float*)d_in[12];
    const float* W_m1   = (const float*)d_in[13]; const float* b_m1   = (const float*)d_in[14];
    const float* W_m2   = (const float*)d_in[15]; const float* b_m2   = (const float*)d_in[16];
    const float* W_out  = (const float*)d_in[17]; const float* b_out  = (const float*)d_in[18];
    const float* W_attn = (const float*)d_in[19]; const float* b_attn = (const float*)d_in[20];
    float* out = (float*)d_out;

    int nsm = 148;
    cudaDeviceGetAttribute(&nsm, cudaDevAttrMultiProcessorCount, 0);
    int grid = 2 * nsm;

    cudaFuncSetAttribute(node_chain_kernel, cudaFuncAttributeMaxDynamicSharedMemorySize, DYN);
    cudaFuncSetAttribute(frag_mlp_kernel,   cudaFuncAttributeMaxDynamicSharedMemorySize, DYN);

    prep_root_kernel<<<PREP_IMG_B + PREP_ROOT_B + PREP_ZERO_B, 256>>>(
        W_in, W_g1, W_g2, W_m1, W_m2, W_out, W_attn, root_repr, W_root, b_root);
    node_chain_kernel<<<grid, 256, DYN>>>(node_h, seg, b_in, b_g1, b_g2);
    frag_mlp_kernel<<<grid, 256, DYN>>>(ind_maps, broken, W_m1, b_m1,
                                        b_m2, b_out, b_attn, out);
}

// round 13
// speedup vs baseline: 6.1706x; 1.0597x over previous
#include <cuda_runtime.h>
#include <cuda_fp16.h>

typedef unsigned int u32; typedef unsigned short u16;

#define NN   800000
#define NF   100000
#define NR   2000
#define FEAT 86
#define H    128
#define NTILE_NODE 6250
#define NTILE_FRAG 782

#define A_B    32768            // A: 128 rows x 256 B (fp16)
#define S0_OFF 32768
#define S1_OFF 65536
#define DYN    98304            // A + 2 W slots -> 2 CTAs/SM

// ---------------- device scratch ----------------
__device__ __align__(16) u16   g_imgs[7 * 16384];   // fp16 weight images, swizzled, transposed
__device__ __align__(16) float g_root_emb[NR * H];
__device__ __align__(16) float g_frag_sum[(size_t)NF * H];
__device__ __align__(16) float g_cnt[NF];
__device__ u32 g_ctr[2];                            // work-stealing counters (node, frag)

// ---------------- helpers ----------------
__device__ __forceinline__ u32 smem_u32(const void* p) {
    u32 a; asm("{ .reg .u64 t; cvta.to.shared.u64 t, %1; cvt.u32.u64 %0, t; }" : "=r"(a) : "l"(p));
    return a;
}
__device__ __forceinline__ void cpa16(u32 dst, const void* src) {
    asm volatile("cp.async.ca.shared.global [%0], [%1], 16;" :: "r"(dst), "l"(src));
}
#define CPA_COMMIT() asm volatile("cp.async.commit_group;" ::: "memory")
#define CPA_WAIT0()  asm volatile("cp.async.wait_group 0;" ::: "memory")
#define CPA_WAIT1()  asm volatile("cp.async.wait_group 1;" ::: "memory")

#define LDSM4(d0, d1, d2, d3, a) \
    asm volatile("ldmatrix.sync.aligned.m8n8.x4.shared.b16 {%0,%1,%2,%3}, [%4];" \
                 : "=r"(d0), "=r"(d1), "=r"(d2), "=r"(d3) : "r"(a))

__device__ __forceinline__ u32 pack_h2(float v0, float v1) {
    __half2 h = __floats2half2_rn(v0, v1);
    return *(u32*)&h;
}
__device__ __forceinline__ void mma16816(float* c, u32 a0, u32 a1, u32 a2, u32 a3, u32 b0, u32 b1) {
    asm volatile("mma.sync.aligned.m16n8k16.row.col.f32.f16.f16.f32 "
                 "{%0,%1,%2,%3}, {%4,%5,%6,%7}, {%8,%9}, {%0,%1,%2,%3};"
                 : "+f"(c[0]), "+f"(c[1]), "+f"(c[2]), "+f"(c[3])
                 : "r"(a0), "r"(a1), "r"(a2), "r"(a3), "r"(b0), "r"(b1));
}

// swizzled byte offset, 256 B rows: chunk16 ^ (row & 7)
__device__ __forceinline__ int a_off(int r, int c) {      // c = u16 col 0..127
    return r * 256 + (((c >> 3) ^ (r & 7)) << 4) + (c & 7) * 2;
}
// pool: fp32, 512 B rows, 16B-chunk XOR swizzle
__device__ __forceinline__ int p_off(int r, int c) {      // c = f32 col 0..127
    return r * 512 + (((c >> 2) ^ (r & 7)) << 4) + (c & 3) * 4;
}

// ---------------- fully-unrolled GEMM pass: warp tile 64 x 32 ----------------
template<int NK>
__device__ __forceinline__ void mma_pass(float (&acc)[4][4][4],
                                         u32 aRow0, int aXor, int aSel,
                                         u32 wRow0, int wXor, int wSel) {
#pragma unroll
    for (int ks = 0; ks < NK; ks++) {
        u32 a[4][4];
#pragma unroll
        for (int mt = 0; mt < 4; mt++) {
            u32 ad = aRow0 + mt * 4096 + (u32)((((aSel + 2 * ks) ^ aXor) << 4));
            LDSM4(a[mt][0], a[mt][1], a[mt][2], a[mt][3], ad);
        }
        u32 b[2][4];
#pragma unroll
        for (int nb = 0; nb < 2; nb++) {
            u32 bd = wRow0 + nb * 4096 + (u32)((((2 * ks + wSel) ^ wXor) << 4));
            LDSM4(b[nb][0], b[nb][1], b[nb][2], b[nb][3], bd);
        }
#pragma unroll
        for (int mt = 0; mt < 4; mt++)
#pragma unroll
            for (int nb = 0; nb < 2; nb++) {
                mma16816(acc[mt][2 * nb + 0], a[mt][0], a[mt][1], a[mt][2], a[mt][3], b[nb][0], b[nb][1]);
                mma16816(acc[mt][2 * nb + 1], a[mt][0], a[mt][1], a[mt][2], a[mt][3], b[nb][2], b[nb][3]);
            }
    }
}
__device__ __forceinline__ void acc_zero(float (&acc)[4][4][4]) {
#pragma unroll
    for (int mt = 0; mt < 4; mt++)
#pragma unroll
        for (int nt = 0; nt < 4; nt++)
#pragma unroll
            for (int e = 0; e < 4; e++) acc[mt][nt][e] = 0.f;
}

// epilogue: acc + bias (+onehot) (+relu) -> fp16 into 256B-row A
__device__ __forceinline__ void epi16(char* Ab, float (&acc)[4][4][4],
                                      const float* __restrict__ bias,
                                      const float* __restrict__ sOne, const int* __restrict__ sBk,
                                      bool relu, int mrow0, int ncol0, int lane) {
    int gr = lane >> 2, q2 = (lane & 3) * 2;
#pragma unroll
    for (int mt = 0; mt < 4; mt++) {
        int r0 = mrow0 + mt * 16 + gr, r1 = r0 + 8;
        const float* oA = sOne ? (sOne + sBk[r0] * 132) : (const float*)0;
        const float* oB = sOne ? (sOne + sBk[r1] * 132) : (const float*)0;
#pragma unroll
        for (int nt = 0; nt < 4; nt++) {
            int c = ncol0 + nt * 8 + q2;
            float v0 = acc[mt][nt][0] + bias[c], v1 = acc[mt][nt][1] + bias[c + 1];
            float w0 = acc[mt][nt][2] + bias[c], w1 = acc[mt][nt][3] + bias[c + 1];
            if (oA) { v0 += oA[c]; v1 += oA[c + 1]; }
            if (oB) { w0 += oB[c]; w1 += oB[c + 1]; }
            if (relu) { v0 = fmaxf(v0, 0.f); v1 = fmaxf(v1, 0.f); w0 = fmaxf(w0, 0.f); w1 = fmaxf(w1, 0.f); }
            *(u32*)(Ab + a_off(r0, c)) = pack_h2(v0, v1);
            *(u32*)(Ab + a_off(r1, c)) = pack_h2(w0, w1);
        }
    }
}

__device__ __forceinline__ void load_img(u32 slot, const u16* src, int tid) {
    const uint4* s = (const uint4*)src;
    for (int i = tid; i < 2048; i += 256) cpa16(slot + i * 16, s + i);
}

// ---------------- fused prep + root encoder + scratch zeroing + counter reset ----------------
#define PREP_IMG_B 448
#define PREP_ROOT_B (NR / 2)
#define PREP_ZERO_B 2048
__global__ void prep_root_kernel(const float* __restrict__ W_in, const float* __restrict__ Wg1,
                                 const float* __restrict__ Wg2, const float* __restrict__ Wm1,
                                 const float* __restrict__ Wm2, const float* __restrict__ Wout,
                                 const float* __restrict__ Wattn,
                                 const float* __restrict__ root_repr,
                                 const float* __restrict__ W_root,
                                 const float* __restrict__ b_root) {
    int tid = threadIdx.x;
    if (blockIdx.x < PREP_IMG_B) {
        int idx = blockIdx.x * 256 + tid;
        int img = idx >> 14, r = idx & 16383, n = r >> 7, k = r & 127;
        float w = 0.f;
        if (img == 0)      { w = (k < FEAT) ? W_in[k * H + n] : 0.f; }
        else if (img == 1) w = Wg1[k * H + n];
        else if (img == 2) w = Wg2[k * H + n];
        else if (img == 3) w = Wm1[k * H + n] + Wm1[(H + k) * H + n];
        else if (img == 4) w = Wm1[(2 * H + k) * H + n] - Wm1[(H + k) * H + n];
        else if (img == 5) w = Wm2[k * H + n];
        else               w = (n < 13) ? Wout[k * 13 + n] : ((n < 26) ? Wattn[k * 13 + (n - 13)] : 0.f);
        int off = n * 128 + (((k >> 3) ^ (n & 7)) << 3) + (k & 7);
        g_imgs[img * 16384 + off] = __half_as_ushort(__float2half_rn(w));
    } else if (blockIdx.x < PREP_IMG_B + PREP_ROOT_B) {
        __shared__ float sX[2][FEAT];
        int half = tid >> 7, n = tid & 127;
        int r = (blockIdx.x - PREP_IMG_B) * 2 + half;
        for (int k = n; k < FEAT; k += 128) sX[half][k] = root_repr[r * FEAT + k];
        __syncthreads();
        float s = b_root[n];
#pragma unroll 2
        for (int k = 0; k < FEAT; k++) s += sX[half][k] * W_root[k * H + n];
        g_root_emb[r * H + n] = fmaxf(s, 0.f);
    } else {
        int zb = blockIdx.x - PREP_IMG_B - PREP_ROOT_B;
        if (zb == 0 && tid < 2) g_ctr[tid] = 0;
        uint4 z = make_uint4(0, 0, 0, 0);
        uint4* fs = (uint4*)g_frag_sum;
        const int NFS = (int)(((size_t)NF * H) / 4);
        for (int i = zb * 256 + tid; i < NFS; i += PREP_ZERO_B * 256) fs[i] = z;
        uint4* ct = (uint4*)g_cnt;
        for (int i = zb * 256 + tid; i < NF / 4; i += PREP_ZERO_B * 256) ct[i] = z;
    }
}

// ---------------- node chain: persistent + work stealing ----------------
__global__ __launch_bounds__(256, 2) void node_chain_kernel(
    const float* __restrict__ node_h, const int* __restrict__ seg,
    const float* __restrict__ b_in, const float* __restrict__ b_g1,
    const float* __restrict__ b_g2) {
    extern __shared__ __align__(16) char Ab[];
    __shared__ float sB[3][128];
    __shared__ int sSeg[128];
    __shared__ int sTile;

    int tid = threadIdx.x, lane = tid & 31, w = tid >> 5;
    int mrow0 = (w >> 2) * 64, ncol0 = (w & 3) * 32;
    u32 smA = smem_u32(Ab);
    u32 S0 = smA + S0_OFF, S1 = smA + S1_OFF;

    load_img(S0, g_imgs, tid);           CPA_COMMIT();   // W0
    load_img(S1, g_imgs + 16384, tid);   CPA_COMMIT();   // W1 (resident forever)

    if (tid < 128) { sB[0][tid] = b_in[tid]; sB[1][tid] = b_g1[tid]; sB[2][tid] = b_g2[tid]; }
    if (tid == 0) sTile = (int)atomicAdd(&g_ctr[0], 1u);

    int rowA = mrow0 + (lane & 15);
    u32 aRow0 = smA + rowA * 256; int aXor = rowA & 7; int aSel = lane >> 4;
    int rowB = ncol0 + (lane & 7) + ((lane >> 4) << 3);
    u32 wOff = rowB * 256; int wXor = rowB & 7; int wSel = (lane >> 3) & 1;

    __syncthreads();
    int tile = sTile;

    while (tile < NTILE_NODE) {
        int tilebase = tile * 128;

        if (tid < 128) sSeg[tid] = seg[tilebase + tid];
        for (int i = tid; i < 128 * 5; i += 256) {
            int m = i / 5, k = 86 + (i - 5 * (i / 5)) * 2;
            *(u32*)(Ab + a_off(m, k)) = 0;
        }
        for (int idx = tid; idx < 128 * 43; idx += 256) {
            int m = idx / 43, k = (idx - m * 43) * 2;
            float2 v = *(const float2*)(node_h + (size_t)(tilebase + m) * FEAT + k);
            *(u32*)(Ab + a_off(m, k)) = pack_h2(v.x, v.y);
        }
        CPA_WAIT0(); __syncthreads();       // W0 ready (first tile also W1)

        float acc[4][4][4];

        // ---- L0 (K=96) ----
        acc_zero(acc);
        mma_pass<6>(acc, aRow0, aXor, aSel, S0 + wOff, wXor, wSel);
        __syncthreads();
        load_img(S0, g_imgs + 2 * 16384, tid); CPA_COMMIT();   // W2 -> S0
        epi16(Ab, acc, sB[0], (const float*)0, (const int*)0, false, mrow0, ncol0, lane);
        __syncthreads();

        // ---- L1 (W1 resident in S1) ----
        acc_zero(acc);
        mma_pass<8>(acc, aRow0, aXor, aSel, S1 + wOff, wXor, wSel);
        __syncthreads();
        epi16(Ab, acc, sB[1], (const float*)0, (const int*)0, true, mrow0, ncol0, lane);
        CPA_WAIT0(); __syncthreads();       // W2 ready

        // ---- L2 -> pool ----
        acc_zero(acc);
        mma_pass<8>(acc, aRow0, aXor, aSel, S0 + wOff, wXor, wSel);
        if (tid == 0) sTile = (int)atomicAdd(&g_ctr[0], 1u);   // early grab, hidden under MMA/epi
        __syncthreads();
        {
            int gr = lane >> 2, q2 = (lane & 3) * 2;
#pragma unroll
            for (int mt = 0; mt < 4; mt++) {
                int r0 = mrow0 + mt * 16 + gr, r1 = r0 + 8;
#pragma unroll
                for (int nt = 0; nt < 4; nt++) {
                    int c = ncol0 + nt * 8 + q2;
                    *(float2*)(Ab + p_off(r0, c)) =
                        make_float2(fmaxf(acc[mt][nt][0] + sB[2][c], 0.f),
                                    fmaxf(acc[mt][nt][1] + sB[2][c + 1], 0.f));
                    *(float2*)(Ab + p_off(r1, c)) =
                        make_float2(fmaxf(acc[mt][nt][2] + sB[2][c], 0.f),
                                    fmaxf(acc[mt][nt][3] + sB[2][c + 1], 0.f));
                }
            }
        }
        __syncthreads();

        // sorted-segment run-length pooling
        {
            int col = tid & 127, hh = tid >> 7;
            int r0 = hh * 64;
            float r = 0.f; int cur = sSeg[r0];
            for (int m = r0; m < r0 + 64; m++) {
                int s = sSeg[m];
                if (s != cur) { atomicAdd(&g_frag_sum[(size_t)cur * H + col], r); r = 0.f; cur = s; }
                r += *(const float*)(Ab + p_off(m, col));
            }
            atomicAdd(&g_frag_sum[(size_t)cur * H + col], r);
        }
        if (tid < 8) {
            int r0 = tid * 16;
            float c = 0.f; int cur = sSeg[r0];
            for (int m = r0; m < r0 + 16; m++) {
                int s = sSeg[m];
                if (s != cur) { atomicAdd(&g_cnt[cur], c); c = 0.f; cur = s; }
                c += 1.f;
            }
            atomicAdd(&g_cnt[cur], c);
        }
        __syncthreads();
        tile = sTile;
        if (tile < NTILE_NODE) { load_img(S0, g_imgs, tid); CPA_COMMIT(); }   // W0 reload
    }
}

// ---------------- fragment head: persistent + work stealing ----------------
__global__ __launch_bounds__(256, 2) void frag_mlp_kernel(
    const int* __restrict__ ind_maps, const int* __restrict__ broken,
    const float* __restrict__ W_m1, const float* __restrict__ b_m1,
    const float* __restrict__ b_m2, const float* __restrict__ b_out,
    const float* __restrict__ b_attn, float* __restrict__ out) {
    extern __shared__ __align__(16) char Ab[];
    __shared__ int sInd[128]; __shared__ float sInv[128]; __shared__ int sBk[128];
    __shared__ float sB1[128], sB2[128], sBo[26];
    __shared__ float sOne[13 * 132];
    __shared__ int sTile;

    int tid = threadIdx.x, lane = tid & 31, w = tid >> 5;
    int mrow0 = (w >> 2) * 64, ncol0 = (w & 3) * 32;
    u32 smA = smem_u32(Ab);
    u32 S0 = smA + S0_OFF, S1 = smA + S1_OFF;

    load_img(S0, g_imgs + 3 * 16384, tid); CPA_COMMIT();   // Wa
    load_img(S1, g_imgs + 4 * 16384, tid); CPA_COMMIT();   // Wb

    if (tid < 128) { sB1[tid] = b_m1[tid]; sB2[tid] = b_m2[tid]; }
    if (tid < 26) sBo[tid] = (tid < 13) ? b_out[tid] : b_attn[tid - 13];
    for (int i = tid; i < 13 * 128; i += 256) {
        int rr = i >> 7, c = i & 127;
        sOne[rr * 132 + c] = W_m1[(size_t)(384 + rr) * H + c];
    }
    if (tid == 0) sTile = (int)atomicAdd(&g_ctr[1], 1u);

    int rowA = mrow0 + (lane & 15);
    u32 aRow0 = smA + rowA * 256; int aXor = rowA & 7; int aSel = lane >> 4;
    int rowB = ncol0 + (lane & 7) + ((lane >> 4) << 3);
    u32 wOff = rowB * 256; int wXor = rowB & 7; int wSel = (lane >> 3) & 1;

    __syncthreads();
    int tile = sTile;

    while (tile < NTILE_FRAG) {
        int base = tile * 128;

        if (tid < 128) {
            int f = base + tid;
            sInd[tid] = (f < NF) ? ind_maps[f] : 0;
            sInv[tid] = (f < NF) ? 1.f / fmaxf(g_cnt[f], 1.f) : 0.f;
            int b = (f < NF) ? broken[f] : 0;
            sBk[tid] = min(max(b, 0), 12);
        }
        __syncthreads();

        // stage ext-root rows (float4)
        for (int idx = tid; idx < 128 * 32; idx += 256) {
            int m = idx >> 5, k = (idx & 31) * 4;
            float4 v = *(const float4*)(g_root_emb + (size_t)sInd[m] * H + k);
            *(uint2*)(Ab + a_off(m, k)) = make_uint2(pack_h2(v.x, v.y), pack_h2(v.z, v.w));
        }
        CPA_WAIT0(); __syncthreads();       // Wa, Wb ready

        float acc[4][4][4];
        acc_zero(acc);

        // ---- L1a: ext @ Wa ----
        mma_pass<8>(acc, aRow0, aXor, aSel, S0 + wOff, wXor, wSel);
        __syncthreads();
        load_img(S0, g_imgs + 5 * 16384, tid); CPA_COMMIT();   // Wm2 -> S0
        for (int idx = tid; idx < 128 * 32; idx += 256) {      // restage A = mean rows (float4)
            int m = idx >> 5, k = (idx & 31) * 4;
            int f = base + m;
            float4 v = make_float4(0.f, 0.f, 0.f, 0.f);
            float iv = sInv[m];
            if (f < NF) {
                v = *(const float4*)(g_frag_sum + (size_t)f * H + k);
                v.x *= iv; v.y *= iv; v.z *= iv; v.w *= iv;
            }
            *(uint2*)(Ab + a_off(m, k)) = make_uint2(pack_h2(v.x, v.y), pack_h2(v.z, v.w));
        }
        __syncthreads();

        // ---- L1b: += mean @ Wb ----
        mma_pass<8>(acc, aRow0, aXor, aSel, S1 + wOff, wXor, wSel);
        __syncthreads();
        load_img(S1, g_imgs + 6 * 16384, tid); CPA_COMMIT();   // Wout -> S1
        epi16(Ab, acc, sB1, sOne, sBk, true, mrow0, ncol0, lane);
        CPA_WAIT1(); __syncthreads();       // Wm2 ready (FIFO)

        // ---- L2 ----
        acc_zero(acc);
        mma_pass<8>(acc, aRow0, aXor, aSel, S0 + wOff, wXor, wSel);
        __syncthreads();
        epi16(Ab, acc, sB2, (const float*)0, (const int*)0, true, mrow0, ncol0, lane);
        CPA_WAIT0(); __syncthreads();       // Wout ready

        // ---- out layer: cols 0..25 ----
        if (tid == 0) sTile = (int)atomicAdd(&g_ctr[1], 1u);   // early grab
        if (ncol0 == 0) {
            acc_zero(acc);
            mma_pass<8>(acc, aRow0, aXor, aSel, S1 + wOff, wXor, wSel);
            int gr = lane >> 2, q2 = (lane & 3) * 2;
#pragma unroll
            for (int mt = 0; mt < 4; mt++) {
                int r0 = mrow0 + mt * 16 + gr, r1 = r0 + 8;
                int fA = base + r0, fB = base + r1;
#pragma unroll
                for (int nt = 0; nt < 4; nt++) {
#pragma unroll
                    for (int e = 0; e < 2; e++) {
                        int c = nt * 8 + q2 + e;
                        if (c >= 26) continue;
                        if (fA < NF) {
                            float v = acc[mt][nt][e] + sBo[c];
                            if (c < 13) out[(size_t)fA * 13 + c] = 1.f / (1.f + __expf(-v));
                            else        out[(size_t)NF * 13 + (size_t)fA * 13 + (c - 13)] = v;
                        }
                        if (fB < NF) {
                            float v = acc[mt][nt][2 + e] + sBo[c];
                            if (c < 13) out[(size_t)fB * 13 + c] = 1.f / (1.f + __expf(-v));
                            else        out[(size_t)NF * 13 + (size_t)fB * 13 + (c - 13)] = v;
                        }
                    }
                }
            }
        }
        __syncthreads();
        tile = sTile;
        if (tile < NTILE_FRAG) {
            load_img(S0, g_imgs + 3 * 16384, tid); CPA_COMMIT();   // Wa
            load_img(S1, g_imgs + 4 * 16384, tid); CPA_COMMIT();   // Wb
        }
    }
}

// ---------------- launcher ----------------
extern "C" void kernel_launch(void* const* d_in, const int* in_sizes, int n_in,
                              void* d_out, int out_size) {
    const float* node_h    = (const float*)d_in[0];
    const int*   seg       = (const int*)d_in[1];
    const float* root_repr = (const float*)d_in[2];
    const int*   ind_maps  = (const int*)d_in[3];
    const int*   broken    = (const int*)d_in[4];
    const float* W_root = (const float*)d_in[5];  const float* b_root = (const float*)d_in[6];
    const float* W_in   = (const float*)d_in[7];  const float* b_in   = (const float*)d_in[8];
    const float* W_g1   = (const float*)d_in[9];  const float* b_g1   = (const float*)d_in[10];
    const float* W_g2   = (const float*)d_in[11]; const float* b_g2   = (const float*)d_in[12];
    const float* W_m1   = (const float*)d_in[13]; const float* b_m1   = (const float*)d_in[14];
    const float* W_m2   = (const float*)d_in[15]; const float* b_m2   = (const float*)d_in[16];
    const float* W_out  = (const float*)d_in[17]; const float* b_out  = (const float*)d_in[18];
    const float* W_attn = (const float*)d_in[19]; const float* b_attn = (const float*)d_in[20];
    float* out = (float*)d_out;

    int nsm = 148;
    cudaDeviceGetAttribute(&nsm, cudaDevAttrMultiProcessorCount, 0);
    int grid = 2 * nsm;

    cudaFuncSetAttribute(node_chain_kernel, cudaFuncAttributeMaxDynamicSharedMemorySize, DYN);
    cudaFuncSetAttribute(frag_mlp_kernel,   cudaFuncAttributeMaxDynamicSharedMemorySize, DYN);

    prep_root_kernel<<<PREP_IMG_B + PREP_ROOT_B + PREP_ZERO_B, 256>>>(
        W_in, W_g1, W_g2, W_m1, W_m2, W_out, W_attn, root_repr, W_root, b_root);
    node_chain_kernel<<<grid, 256, DYN>>>(node_h, seg, b_in, b_g1, b_g2);
    frag_mlp_kernel<<<grid, 256, DYN>>>(ind_maps, broken, W_m1, b_m1,
                                        b_m2, b_out, b_attn, out);
}